// round 3
// baseline (speedup 1.0000x reference)
#include <cuda_runtime.h>

#define NB   131072
#define NDX  256
#define NDY  32
#define NK   4
#define NH   128
#define C_LR  0.1f
#define C_REG 0.01f
#define C_SW  1.0f

// ---------------- scratch (device globals: no allocation allowed) ----------------
__device__ float g_hxe[NB * NH];   // x @ e_w1[:DX] + e_b1
__device__ float g_hxs[NB * NH];   // x @ s_xw + s_xb
__device__ float g_c[NB * NH];     // static part of transition pre-activation
__device__ float g_cth[NK * NH];   // temb@tr1w[2H:3H] + th@tr1w[3H:4H] + tr1b, per class

// ---------------- kernel B: per-class constants (4 classes, trivial) ----------------
__global__ void cth_kernel(const float* __restrict__ s_temb,
                           const float* __restrict__ s_t1w,
                           const float* __restrict__ s_t1b,
                           const float* __restrict__ s_t2w,
                           const float* __restrict__ s_t2b,
                           const float* __restrict__ tr1w,
                           const float* __restrict__ tr1b) {
    int j = threadIdx.x;                 // 0..127
    __shared__ float v[NH], th[NH];
    for (int k = 0; k < NK; k++) {
        float tau = fmaxf((float)k / 1000.0f, 1e-6f);
        float z = tau * s_t1w[j] + s_t1b[j];
        float sg = 1.0f / (1.0f + expf(-z));
        v[j] = z * sg;
        __syncthreads();
        float acc = s_t2b[j];
        for (int q = 0; q < NH; q++) acc += v[q] * s_t2w[q * NH + j];
        th[j] = acc;
        __syncthreads();
        float c = tr1b[j];
        for (int q = 0; q < NH; q++) {
            c += s_temb[k * NH + q] * tr1w[(2 * NH + q) * NH + j];
            c += th[q] * tr1w[(3 * NH + q) * NH + j];
        }
        g_cth[k * NH + j] = c;
        __syncthreads();
    }
}

// ---------------- kernel A: tiled FP32 GEMM, N fixed at 128 ----------------
// out[m][n] = sum_k X[m*ldx + k] * Wm[k*128 + n]  (+bias[n]) (+g_cth-style table[t[m]][n])
__global__ __launch_bounds__(256)
void gemm128_kernel(const float* __restrict__ X, int ldx, int Kdim,
                    const float* __restrict__ Wm,
                    const float* __restrict__ bias,
                    const float* __restrict__ table,
                    const int* __restrict__ tt,
                    float* __restrict__ out) {
    __shared__ float Xs[64 * 33];
    __shared__ float Ws[32 * 128];
    int tid = threadIdx.x;
    int tcol = tid & 31;      // covers n = tcol + 32q
    int trow = tid >> 5;      // covers m = trow + 8p (same for whole warp -> broadcast LDS)
    int m0 = blockIdx.x * 64;

    float acc[8][4];
#pragma unroll
    for (int p = 0; p < 8; p++)
#pragma unroll
        for (int q = 0; q < 4; q++) acc[p][q] = 0.0f;

    for (int k0 = 0; k0 < Kdim; k0 += 32) {
#pragma unroll
        for (int i = 0; i < 8; i++) {
            int e = tid + 256 * i;
            int m = e >> 5, kk = e & 31;
            Xs[m * 33 + kk] = X[(m0 + m) * ldx + k0 + kk];
        }
#pragma unroll
        for (int i = 0; i < 16; i++) {
            int e = tid + 256 * i;
            int kk = e >> 7, n = e & 127;
            Ws[kk * 128 + n] = Wm[(k0 + kk) * NH + n];
        }
        __syncthreads();
#pragma unroll 8
        for (int kk = 0; kk < 32; kk++) {
            float xv[8], wv[4];
#pragma unroll
            for (int p = 0; p < 8; p++) xv[p] = Xs[(trow + 8 * p) * 33 + kk];
#pragma unroll
            for (int q = 0; q < 4; q++) wv[q] = Ws[kk * 128 + tcol + 32 * q];
#pragma unroll
            for (int p = 0; p < 8; p++)
#pragma unroll
                for (int q = 0; q < 4; q++) acc[p][q] += xv[p] * wv[q];
        }
        __syncthreads();
    }
#pragma unroll
    for (int p = 0; p < 8; p++) {
        int m = m0 + trow + 8 * p;
        int tc = 0;
        if (table) { int tv = tt[m]; tc = tv > 0 ? tv : 0; }
#pragma unroll
        for (int q = 0; q < 4; q++) {
            int n = tcol + 32 * q;
            float vv = acc[p][q];
            if (bias)  vv += bias[n];
            if (table) vv += table[tc * NH + n];
            out[m * NH + n] = vv;
        }
    }
}

// ---------------- main kernel: 20 gradient-descent steps, warp-per-2-rows ----------------
// SMEM layout (floats):
//  sE1y 4096 | sSyw 4096 | sW2 16384 | sT1y 16384 | sE3 512 | sT2 512 | sb2 128 | syb 128 | st2b 8 | scratch 16*256
#define SMEM_FLOATS (4096 + 4096 + 16384 + 16384 + 512 + 512 + 128 + 128 + 8 + 16 * 256)
#define SMEM_BYTES  (SMEM_FLOATS * 4)

__global__ __launch_bounds__(512, 1)
void edi_main_kernel(const int* __restrict__ t,
                     const float* __restrict__ e_w1,
                     const float* __restrict__ e_w2,
                     const float* __restrict__ e_b2,
                     const float* __restrict__ e_w3,
                     const float* __restrict__ s_yw,
                     const float* __restrict__ s_yb,
                     const float* __restrict__ tr1w,
                     const float* __restrict__ tr2w,
                     const float* __restrict__ tr2b,
                     const int* __restrict__ steps_p,
                     float* __restrict__ out) {
    extern __shared__ float sm[];
    float* sE1y = sm;
    float* sSyw = sE1y + 4096;
    float* sW2  = sSyw + 4096;
    float* sT1y = sW2 + 16384;
    float* sE3  = sT1y + 16384;
    float* sT2  = sE3 + 512;
    float* sb2  = sT2 + 512;
    float* syb  = sb2 + 128;
    float* st2b = syb + 128;
    float* sscr = st2b + 8;

    int tid = threadIdx.x;
    // ---- load weights, XOR-swizzled so both row- and col-access are conflict-free ----
    for (int idx = tid; idx < 32 * 128; idx += 512) {
        int d = idx >> 7, k = idx & 127;
        int swi = d * 128 + (k & 96) + ((k & 31) ^ d);
        sE1y[swi] = e_w1[(NDX + d) * NH + k];   // e_w1[DX:] (32 x 128)
        sSyw[swi] = s_yw[idx];                  // (32 x 128)
    }
    for (int idx = tid; idx < 128 * 128; idx += 512) {
        int j = idx >> 7, k = idx & 127;
        int swi = j * 128 + (k & 96) + ((k & 31) ^ (j & 31));
        sW2[swi]  = e_w2[idx];
        sT1y[swi] = tr1w[(NH + j) * NH + k];    // tr1w rows [H, 2H)
    }
    for (int idx = tid; idx < 512; idx += 512) { sE3[idx] = e_w3[idx]; sT2[idx] = tr2w[idx]; }
    if (tid < 128) { sb2[tid] = e_b2[tid]; syb[tid] = s_yb[tid]; }
    if (tid < 4)   st2b[tid] = tr2b[tid];
    __syncthreads();

    const int lane = tid & 31;
    const int warp = tid >> 5;
    float* scr = sscr + warp * 256;            // [j*2 + rowpair], per-warp activation scratch
    const float2* scr2 = (const float2*)scr;
    float2* scrw = (float2*)scr;

    const int r0 = (blockIdx.x * 16 + warp) * 2;
    const int nsteps = *steps_p;

    int tci0, tci1; float val0, val1;
    { int tv = t[r0];     tci0 = tv > 0 ? tv : 0; val0 = tv >= 0 ? 1.0f : 0.0f; }
    { int tv = t[r0 + 1]; tci1 = tv > 0 ? tv : 0; val1 = tv >= 0 ? 1.0f : 0.0f; }

    float y0 = 0.0f, y1 = 0.0f;                // lane d owns y[d]
    float hxe0[4], hxe1[4], cc0[4], cc1[4];
#pragma unroll
    for (int m = 0; m < 4; m++) {
        hxe0[m] = g_hxe[r0 * NH + 32 * m + lane];
        hxe1[m] = g_hxe[(r0 + 1) * NH + 32 * m + lane];
        cc0[m]  = g_c[r0 * NH + 32 * m + lane];
        cc1[m]  = g_c[(r0 + 1) * NH + 32 * m + lane];
    }

    for (int s = 0; s < nsteps; s++) {
        // ======== forward: energy h1 = relu(hx_e + y @ E1y) ========
        float h10[4], h11[4];
#pragma unroll
        for (int m = 0; m < 4; m++) { h10[m] = hxe0[m]; h11[m] = hxe1[m]; }
#pragma unroll 4
        for (int d = 0; d < 32; d++) {
            float b0 = __shfl_sync(0xffffffffu, y0, d);
            float b1 = __shfl_sync(0xffffffffu, y1, d);
            int base = d * 128 + (lane ^ d);
#pragma unroll
            for (int m = 0; m < 4; m++) {
                float w = sE1y[base + 32 * m];
                h10[m] += b0 * w; h11[m] += b1 * w;
            }
        }
#pragma unroll
        for (int m = 0; m < 4; m++) { h10[m] = fmaxf(h10[m], 0.f); h11[m] = fmaxf(h11[m], 0.f); }
#pragma unroll
        for (int m = 0; m < 4; m++) scrw[lane + 32 * m] = make_float2(h10[m], h11[m]);
        __syncwarp();

        // h2 = relu(h1 @ W2 + b2)
        float h20[4], h21[4];
#pragma unroll
        for (int m = 0; m < 4; m++) { float b = sb2[lane + 32 * m]; h20[m] = b; h21[m] = b; }
#pragma unroll 2
        for (int j = 0; j < 128; j++) {
            float2 hj = scr2[j];
            int base = j * 128 + (lane ^ (j & 31));
#pragma unroll
            for (int m = 0; m < 4; m++) {
                float w = sW2[base + 32 * m];
                h20[m] += hj.x * w; h21[m] += hj.y * w;
            }
        }
#pragma unroll
        for (int m = 0; m < 4; m++) { h20[m] = fmaxf(h20[m], 0.f); h21[m] = fmaxf(h21[m], 0.f); }
        __syncwarp();

        // ======== forward: transition. hy = y @ Syw + s_yb ========
        float hy0[4], hy1[4];
#pragma unroll
        for (int m = 0; m < 4; m++) { float b = syb[lane + 32 * m]; hy0[m] = b; hy1[m] = b; }
#pragma unroll 4
        for (int d = 0; d < 32; d++) {
            float b0 = __shfl_sync(0xffffffffu, y0, d);
            float b1 = __shfl_sync(0xffffffffu, y1, d);
            int base = d * 128 + (lane ^ d);
#pragma unroll
            for (int m = 0; m < 4; m++) {
                float w = sSyw[base + 32 * m];
                hy0[m] += b0 * w; hy1[m] += b1 * w;
            }
        }
#pragma unroll
        for (int m = 0; m < 4; m++) scrw[lane + 32 * m] = make_float2(hy0[m], hy1[m]);
        __syncwarp();

        // u = c + hy @ T1y
        float u0[4], u1[4];
#pragma unroll
        for (int m = 0; m < 4; m++) { u0[m] = cc0[m]; u1[m] = cc1[m]; }
#pragma unroll 2
        for (int j = 0; j < 128; j++) {
            float2 hj = scr2[j];
            int base = j * 128 + (lane ^ (j & 31));
#pragma unroll
            for (int m = 0; m < 4; m++) {
                float w = sT1y[base + 32 * m];
                u0[m] += hj.x * w; u1[m] += hj.y * w;
            }
        }
        __syncwarp();

        // silu + logits partials
        float sg0[4], sg1[4];
        float lg0[4] = {0, 0, 0, 0}, lg1[4] = {0, 0, 0, 0};
#pragma unroll
        for (int m = 0; m < 4; m++) {
            int j = lane + 32 * m;
            float4 t2 = *(const float4*)&sT2[j * 4];
            float s0 = 1.0f / (1.0f + expf(-u0[m])); sg0[m] = s0;
            float a0 = u0[m] * s0;
            lg0[0] += a0 * t2.x; lg0[1] += a0 * t2.y; lg0[2] += a0 * t2.z; lg0[3] += a0 * t2.w;
            float s1 = 1.0f / (1.0f + expf(-u1[m])); sg1[m] = s1;
            float a1 = u1[m] * s1;
            lg1[0] += a1 * t2.x; lg1[1] += a1 * t2.y; lg1[2] += a1 * t2.z; lg1[3] += a1 * t2.w;
        }
#pragma unroll
        for (int off = 16; off > 0; off >>= 1) {
#pragma unroll
            for (int k = 0; k < 4; k++) {
                lg0[k] += __shfl_xor_sync(0xffffffffu, lg0[k], off);
                lg1[k] += __shfl_xor_sync(0xffffffffu, lg1[k], off);
            }
        }
        // dlogits = SW*valid*(softmax(logits) - onehot(tci))
        float dl0[4], dl1[4];
        {
            float l[4];
#pragma unroll
            for (int k = 0; k < 4; k++) l[k] = lg0[k] + st2b[k];
            float mx = fmaxf(fmaxf(l[0], l[1]), fmaxf(l[2], l[3]));
            float ek[4], den = 0.f;
#pragma unroll
            for (int k = 0; k < 4; k++) { ek[k] = expf(l[k] - mx); den += ek[k]; }
            float inv = C_SW * val0 / den;
#pragma unroll
            for (int k = 0; k < 4; k++)
                dl0[k] = ek[k] * inv - (k == tci0 ? C_SW * val0 : 0.0f);
        }
        {
            float l[4];
#pragma unroll
            for (int k = 0; k < 4; k++) l[k] = lg1[k] + st2b[k];
            float mx = fmaxf(fmaxf(l[0], l[1]), fmaxf(l[2], l[3]));
            float ek[4], den = 0.f;
#pragma unroll
            for (int k = 0; k < 4; k++) { ek[k] = expf(l[k] - mx); den += ek[k]; }
            float inv = C_SW * val1 / den;
#pragma unroll
            for (int k = 0; k < 4; k++)
                dl1[k] = ek[k] * inv - (k == tci1 ? C_SW * val1 : 0.0f);
        }

        // ======== backward: transition ========
        // du = (tr2w @ dlogits) * silu'(u)
#pragma unroll
        for (int m = 0; m < 4; m++) {
            int j = lane + 32 * m;
            float4 t2 = *(const float4*)&sT2[j * 4];
            float da0 = t2.x * dl0[0] + t2.y * dl0[1] + t2.z * dl0[2] + t2.w * dl0[3];
            float da1 = t2.x * dl1[0] + t2.y * dl1[1] + t2.z * dl1[2] + t2.w * dl1[3];
            float du0 = da0 * sg0[m] * (1.0f + u0[m] * (1.0f - sg0[m]));
            float du1 = da1 * sg1[m] * (1.0f + u1[m] * (1.0f - sg1[m]));
            scrw[j] = make_float2(du0, du1);
        }
        __syncwarp();
        // dhy_j = sum_k T1y[j,k] * du_k
        float dhy0[4] = {0, 0, 0, 0}, dhy1[4] = {0, 0, 0, 0};
#pragma unroll 2
        for (int k = 0; k < 128; k++) {
            float2 dk = scr2[k];
            int off = (k & 96) + ((k & 31) ^ lane);
#pragma unroll
            for (int m = 0; m < 4; m++) {
                float w = sT1y[(lane + 32 * m) * 128 + off];
                dhy0[m] += dk.x * w; dhy1[m] += dk.y * w;
            }
        }
        __syncwarp();
#pragma unroll
        for (int m = 0; m < 4; m++) scrw[lane + 32 * m] = make_float2(dhy0[m], dhy1[m]);
        __syncwarp();
        // gy += Syw[d,:] . dhy   (d = lane)
        float gy0 = 2.0f * C_REG * y0, gy1 = 2.0f * C_REG * y1;
#pragma unroll 2
        for (int j = 0; j < 128; j++) {
            float2 dj = scr2[j];
            float w = sSyw[lane * 128 + (j & 96) + ((j & 31) ^ lane)];
            gy0 += dj.x * w; gy1 += dj.y * w;
        }
        __syncwarp();

        // ======== backward: energy ========
        // dh2pre = (h2 > 0) * e_w3[:, tci]
#pragma unroll
        for (int m = 0; m < 4; m++) {
            int j = lane + 32 * m;
            float d20 = (h20[m] > 0.f) ? sE3[j * 4 + tci0] : 0.f;
            float d21 = (h21[m] > 0.f) ? sE3[j * 4 + tci1] : 0.f;
            scrw[j] = make_float2(d20, d21);
        }
        __syncwarp();
        // dh1_j = (h1_j>0) * sum_k W2[j,k] dh2pre_k
        float dh10[4] = {0, 0, 0, 0}, dh11[4] = {0, 0, 0, 0};
#pragma unroll 2
        for (int k = 0; k < 128; k++) {
            float2 dk = scr2[k];
            int off = (k & 96) + ((k & 31) ^ lane);
#pragma unroll
            for (int m = 0; m < 4; m++) {
                float w = sW2[(lane + 32 * m) * 128 + off];
                dh10[m] += dk.x * w; dh11[m] += dk.y * w;
            }
        }
#pragma unroll
        for (int m = 0; m < 4; m++) {
            dh10[m] = (h10[m] > 0.f) ? dh10[m] : 0.f;
            dh11[m] = (h11[m] > 0.f) ? dh11[m] : 0.f;
        }
        __syncwarp();
#pragma unroll
        for (int m = 0; m < 4; m++) scrw[lane + 32 * m] = make_float2(dh10[m], dh11[m]);
        __syncwarp();
        // gy += E1y[d,:] . dh1pre
#pragma unroll 2
        for (int j = 0; j < 128; j++) {
            float2 dj = scr2[j];
            float w = sE1y[lane * 128 + (j & 96) + ((j & 31) ^ lane)];
            gy0 += dj.x * w; gy1 += dj.y * w;
        }
        __syncwarp();

        // SGD update
        y0 -= C_LR * gy0;
        y1 -= C_LR * gy1;
    }

    out[r0 * NDY + lane] = y0;
    out[(r0 + 1) * NDY + lane] = y1;
}

// ---------------- launcher ----------------
extern "C" void kernel_launch(void* const* d_in, const int* in_sizes, int n_in,
                              void* d_out, int out_size) {
    const float* x      = (const float*)d_in[0];
    const int*   t      = (const int*)d_in[1];
    const float* e_w1   = (const float*)d_in[2];
    const float* e_b1   = (const float*)d_in[3];
    const float* e_w2   = (const float*)d_in[4];
    const float* e_b2   = (const float*)d_in[5];
    const float* e_w3   = (const float*)d_in[6];
    /* d_in[7] = e_b3: not needed for grad wrt y */
    const float* s_xw   = (const float*)d_in[8];
    const float* s_xb   = (const float*)d_in[9];
    const float* s_yw   = (const float*)d_in[10];
    const float* s_yb   = (const float*)d_in[11];
    const float* s_temb = (const float*)d_in[12];
    const float* s_t1w  = (const float*)d_in[13];
    const float* s_t1b  = (const float*)d_in[14];
    const float* s_t2w  = (const float*)d_in[15];
    const float* s_t2b  = (const float*)d_in[16];
    const float* tr1w   = (const float*)d_in[17];
    const float* tr1b   = (const float*)d_in[18];
    const float* tr2w   = (const float*)d_in[19];
    const float* tr2b   = (const float*)d_in[20];
    const int*   steps  = (const int*)d_in[21];
    float* out = (float*)d_out;

    float *p_hxe, *p_hxs, *p_c, *p_cth;
    cudaGetSymbolAddress((void**)&p_hxe, g_hxe);
    cudaGetSymbolAddress((void**)&p_hxs, g_hxs);
    cudaGetSymbolAddress((void**)&p_c,   g_c);
    cudaGetSymbolAddress((void**)&p_cth, g_cth);

    // 1) per-class constants
    cth_kernel<<<1, NH>>>(s_temb, s_t1w, s_t1b, s_t2w, s_t2b, tr1w, tr1b);

    // 2) per-row constants: hx_e, hx_s, then c = hx_s @ tr1w[:H] + cth[t]
    gemm128_kernel<<<NB / 64, 256>>>(x, NDX, NDX, e_w1, e_b1, nullptr, nullptr, p_hxe);
    gemm128_kernel<<<NB / 64, 256>>>(x, NDX, NDX, s_xw, s_xb, nullptr, nullptr, p_hxs);
    gemm128_kernel<<<NB / 64, 256>>>(p_hxs, NH, NH, tr1w, nullptr, p_cth, t, p_c);

    // 3) 20 SGD steps, warp-per-2-rows, weights resident in swizzled SMEM
    cudaFuncSetAttribute(edi_main_kernel, cudaFuncAttributeMaxDynamicSharedMemorySize, SMEM_BYTES);
    edi_main_kernel<<<NB / 32, 512, SMEM_BYTES>>>(t, e_w1, e_w2, e_b2, e_w3,
                                                  s_yw, s_yb, tr1w, tr2w, tr2b,
                                                  steps, out);
}

// round 5
// speedup vs baseline: 1.6996x; 1.6996x over previous
#include <cuda_runtime.h>

typedef unsigned long long u64;

#define NB   131072
#define NDX  256
#define NDY  32
#define NK   4
#define NH   128
#define C_LR  0.1f
#define C_REG 0.01f
#define C_SW  1.0f

// ---------------- scratch (device globals: no allocation allowed) ----------------
__device__ float g_hxe[NB * NH];   // x @ e_w1[:DX] + e_b1
__device__ float g_hxs[NB * NH];   // x @ s_xw + s_xb
__device__ float g_c[NB * NH];     // static part of transition pre-activation
__device__ float g_cth[NK * NH];   // temb@tr1w[2H:3H] + th@tr1w[3H:4H] + tr1b, per class

// ---------------- packed f32x2 helpers ----------------
__device__ __forceinline__ u64 pk2(float x, float y) {
    u64 r; asm("mov.b64 %0, {%1,%2};" : "=l"(r) : "f"(x), "f"(y)); return r;
}
__device__ __forceinline__ u64 pks(float x) {
    u64 r; asm("mov.b64 %0, {%1,%1};" : "=l"(r) : "f"(x)); return r;
}
__device__ __forceinline__ void up2(u64 v, float& x, float& y) {
    asm("mov.b64 {%0,%1}, %2;" : "=f"(x), "=f"(y) : "l"(v));
}
__device__ __forceinline__ u64 ffma2(u64 a, u64 b, u64 c) {
    u64 d; asm("fma.rn.f32x2 %0, %1, %2, %3;" : "=l"(d) : "l"(a), "l"(b), "l"(c)); return d;
}
__device__ __forceinline__ u64 fmul2(u64 a, u64 b) {
    u64 d; asm("mul.rn.f32x2 %0, %1, %2;" : "=l"(d) : "l"(a), "l"(b)); return d;
}
__device__ __forceinline__ u64 fadd2(u64 a, u64 b) {
    u64 d; asm("add.rn.f32x2 %0, %1, %2;" : "=l"(d) : "l"(a), "l"(b)); return d;
}

// Per-warp activation scratch: two regions of 512 floats (float4 per j).
// Region0 holds rows 0-3 (pairs 0,1), region1 rows 4-7 (pairs 2,3).
// Store addresses stride 4 words => 16B granule index = j (mod 8 distinct per
// 8-lane phase) => conflict-free STS.128 with no swizzle. Reads are broadcast.
__device__ __forceinline__ void st8(float* scr, int j, u64 v0, u64 v1, u64 v2, u64 v3) {
    *reinterpret_cast<ulonglong2*>(scr + j * 4)       = make_ulonglong2(v0, v1);
    *reinterpret_cast<ulonglong2*>(scr + 512 + j * 4) = make_ulonglong2(v2, v3);
}
__device__ __forceinline__ void ld8(const float* scr, int j, u64& v0, u64& v1, u64& v2, u64& v3) {
    ulonglong2 a = *reinterpret_cast<const ulonglong2*>(scr + j * 4);
    ulonglong2 b = *reinterpret_cast<const ulonglong2*>(scr + 512 + j * 4);
    v0 = a.x; v1 = a.y; v2 = b.x; v3 = b.y;
}

// ---------------- kernel B: per-class constants (4 classes, trivial) ----------------
__global__ void cth_kernel(const float* __restrict__ s_temb,
                           const float* __restrict__ s_t1w,
                           const float* __restrict__ s_t1b,
                           const float* __restrict__ s_t2w,
                           const float* __restrict__ s_t2b,
                           const float* __restrict__ tr1w,
                           const float* __restrict__ tr1b) {
    int j = threadIdx.x;                 // 0..127
    __shared__ float v[NH], th[NH];
    for (int k = 0; k < NK; k++) {
        float tau = fmaxf((float)k / 1000.0f, 1e-6f);
        float z = tau * s_t1w[j] + s_t1b[j];
        float sg = 1.0f / (1.0f + expf(-z));
        v[j] = z * sg;
        __syncthreads();
        float acc = s_t2b[j];
        for (int q = 0; q < NH; q++) acc += v[q] * s_t2w[q * NH + j];
        th[j] = acc;
        __syncthreads();
        float c = tr1b[j];
        for (int q = 0; q < NH; q++) {
            c += s_temb[k * NH + q] * tr1w[(2 * NH + q) * NH + j];
            c += th[q] * tr1w[(3 * NH + q) * NH + j];
        }
        g_cth[k * NH + j] = c;
        __syncthreads();
    }
}

// ---------------- kernel A: tiled FP32 GEMM, N fixed at 128 ----------------
__global__ __launch_bounds__(256)
void gemm128_kernel(const float* __restrict__ X, int ldx, int Kdim,
                    const float* __restrict__ Wm,
                    const float* __restrict__ bias,
                    const float* __restrict__ table,
                    const int* __restrict__ tt,
                    float* __restrict__ out) {
    __shared__ float Xs[64 * 33];
    __shared__ float Ws[32 * 128];
    int tid = threadIdx.x;
    int tcol = tid & 31;
    int trow = tid >> 5;
    int m0 = blockIdx.x * 64;

    float acc[8][4];
#pragma unroll
    for (int p = 0; p < 8; p++)
#pragma unroll
        for (int q = 0; q < 4; q++) acc[p][q] = 0.0f;

    for (int k0 = 0; k0 < Kdim; k0 += 32) {
#pragma unroll
        for (int i = 0; i < 8; i++) {
            int e = tid + 256 * i;
            int m = e >> 5, kk = e & 31;
            Xs[m * 33 + kk] = X[(m0 + m) * ldx + k0 + kk];
        }
#pragma unroll
        for (int i = 0; i < 16; i++) {
            int e = tid + 256 * i;
            int kk = e >> 7, n = e & 127;
            Ws[kk * 128 + n] = Wm[(k0 + kk) * NH + n];
        }
        __syncthreads();
#pragma unroll 8
        for (int kk = 0; kk < 32; kk++) {
            float xv[8], wv[4];
#pragma unroll
            for (int p = 0; p < 8; p++) xv[p] = Xs[(trow + 8 * p) * 33 + kk];
#pragma unroll
            for (int q = 0; q < 4; q++) wv[q] = Ws[kk * 128 + tcol + 32 * q];
#pragma unroll
            for (int p = 0; p < 8; p++)
#pragma unroll
                for (int q = 0; q < 4; q++) acc[p][q] += xv[p] * wv[q];
        }
        __syncthreads();
    }
#pragma unroll
    for (int p = 0; p < 8; p++) {
        int m = m0 + trow + 8 * p;
        int tc = 0;
        if (table) { int tv = tt[m]; tc = tv > 0 ? tv : 0; }
#pragma unroll
        for (int q = 0; q < 4; q++) {
            int n = tcol + 32 * q;
            float vv = acc[p][q];
            if (bias)  vv += bias[n];
            if (table) vv += table[tc * NH + n];
            out[m * NH + n] = vv;
        }
    }
}

// ---------------- main kernel: 20 SGD steps, warp-per-8-rows, packed f32x2 ----------------
// SMEM floats: sE1y 4096 | sSyw 4096 | sW2 16384 | sT1y 16384 | sE3T 512 | sT2 512
//            | sb2 128 | syb 128 | st2b 8 | scratch 8*1024
#define SMEM_FLOATS (4096 + 4096 + 16384 + 16384 + 512 + 512 + 128 + 128 + 8 + 8 * 1024)
#define SMEM_BYTES  (SMEM_FLOATS * 4)

__global__ __launch_bounds__(256, 1)
void edi_main_kernel(const int* __restrict__ t,
                     const float* __restrict__ e_w1,
                     const float* __restrict__ e_w2,
                     const float* __restrict__ e_b2,
                     const float* __restrict__ e_w3,
                     const float* __restrict__ s_yw,
                     const float* __restrict__ s_yb,
                     const float* __restrict__ tr1w,
                     const float* __restrict__ tr2w,
                     const float* __restrict__ tr2b,
                     const int* __restrict__ steps_p,
                     float* __restrict__ out) {
    extern __shared__ float sm[];
    float* sE1y = sm;
    float* sSyw = sE1y + 4096;
    float* sW2  = sSyw + 4096;
    float* sT1y = sW2 + 16384;
    float* sE3T = sT1y + 16384;   // transposed: [k][j]
    float* sT2  = sE3T + 512;
    float* sb2  = sT2 + 512;
    float* syb  = sb2 + 128;
    float* st2b = syb + 128;
    float* sscr = st2b + 8;

    int tid = threadIdx.x;
    // XOR-swizzled weight layouts: row-read and col-read both conflict-free.
    for (int idx = tid; idx < 32 * 128; idx += 256) {
        int d = idx >> 7, k = idx & 127;
        int swi = d * 128 + (k & 96) + ((k & 31) ^ d);
        sE1y[swi] = e_w1[(NDX + d) * NH + k];
        sSyw[swi] = s_yw[idx];
    }
    for (int idx = tid; idx < 128 * 128; idx += 256) {
        int j = idx >> 7, k = idx & 127;
        int swi = j * 128 + (k & 96) + ((k & 31) ^ (j & 31));
        sW2[swi]  = e_w2[idx];
        sT1y[swi] = tr1w[(NH + j) * NH + k];
    }
    for (int idx = tid; idx < 512; idx += 256) {
        sE3T[(idx & 3) * 128 + (idx >> 2)] = e_w3[idx];
        sT2[idx] = tr2w[idx];
    }
    if (tid < 128) { sb2[tid] = e_b2[tid]; syb[tid] = s_yb[tid]; }
    if (tid < 4)   st2b[tid] = tr2b[tid];
    __syncthreads();

    const int lane = tid & 31;
    const int warp = tid >> 5;
    float* scr = sscr + warp * 1024;
    const int r0 = (blockIdx.x * 8 + warp) * 8;    // 8 rows per warp
    const int nsteps = *steps_p;

    int tci[8]; float svf[8];
#pragma unroll
    for (int r = 0; r < 8; r++) {
        int tv = t[r0 + r];
        tci[r] = tv > 0 ? tv : 0;
        svf[r] = tv >= 0 ? C_SW : 0.0f;
    }

    u64 y[4] = {0ull, 0ull, 0ull, 0ull};           // pairs (rows 2p, 2p+1); lane d owns y[d]
    u64 hxe[4][4], cc[4][4];                       // [m][pair]
#pragma unroll
    for (int m = 0; m < 4; m++)
#pragma unroll
        for (int p = 0; p < 4; p++) {
            int col = 32 * m + lane;
            hxe[m][p] = pk2(g_hxe[(r0 + 2 * p) * NH + col], g_hxe[(r0 + 2 * p + 1) * NH + col]);
            cc[m][p]  = pk2(g_c[(r0 + 2 * p) * NH + col],   g_c[(r0 + 2 * p + 1) * NH + col]);
        }

    for (int s = 0; s < nsteps; s++) {
        __syncwarp();
        st8(scr, lane, y[0], y[1], y[2], y[3]);    // y[d] broadcast table, d = lane
        __syncwarp();

        // ---- E1y fwd (h1) + Syw fwd (hy) share y broadcasts ----
        u64 A[4][4], Hy[4][4];
#pragma unroll
        for (int m = 0; m < 4; m++) {
            float bb = syb[32 * m + lane];
#pragma unroll
            for (int p = 0; p < 4; p++) { A[m][p] = hxe[m][p]; Hy[m][p] = pks(bb); }
        }
#pragma unroll 4
        for (int d = 0; d < 32; d++) {
            u64 b0, b1, b2, b3; ld8(scr, d, b0, b1, b2, b3);
            int base = d * 128 + (lane ^ d);
#pragma unroll
            for (int m = 0; m < 4; m++) {
                u64 w = pks(sE1y[base + 32 * m]);
                A[m][0] = ffma2(b0, w, A[m][0]); A[m][1] = ffma2(b1, w, A[m][1]);
                A[m][2] = ffma2(b2, w, A[m][2]); A[m][3] = ffma2(b3, w, A[m][3]);
                u64 v = pks(sSyw[base + 32 * m]);
                Hy[m][0] = ffma2(b0, v, Hy[m][0]); Hy[m][1] = ffma2(b1, v, Hy[m][1]);
                Hy[m][2] = ffma2(b2, v, Hy[m][2]); Hy[m][3] = ffma2(b3, v, Hy[m][3]);
            }
        }
        // relu(h1) + sign mask
        unsigned m1 = 0;
#pragma unroll
        for (int m = 0; m < 4; m++)
#pragma unroll
            for (int p = 0; p < 4; p++) {
                float x, z; up2(A[m][p], x, z);
                m1 |= (x > 0.f ? 1u : 0u) << (m * 8 + 2 * p);
                m1 |= (z > 0.f ? 1u : 0u) << (m * 8 + 2 * p + 1);
                A[m][p] = pk2(fmaxf(x, 0.f), fmaxf(z, 0.f));
            }
        __syncwarp();
#pragma unroll
        for (int m = 0; m < 4; m++) st8(scr, lane + 32 * m, A[m][0], A[m][1], A[m][2], A[m][3]);
        __syncwarp();

        // ---- W2 fwd: only the relu mask of h2 is needed ----
        unsigned m2 = 0;
        {
            u64 B[4][4];
#pragma unroll
            for (int m = 0; m < 4; m++) {
                float bb = sb2[32 * m + lane];
#pragma unroll
                for (int p = 0; p < 4; p++) B[m][p] = pks(bb);
            }
#pragma unroll 4
            for (int j = 0; j < 128; j++) {
                u64 b0, b1, b2, b3; ld8(scr, j, b0, b1, b2, b3);
                int base = j * 128 + (lane ^ (j & 31));
#pragma unroll
                for (int m = 0; m < 4; m++) {
                    u64 w = pks(sW2[base + 32 * m]);
                    B[m][0] = ffma2(b0, w, B[m][0]); B[m][1] = ffma2(b1, w, B[m][1]);
                    B[m][2] = ffma2(b2, w, B[m][2]); B[m][3] = ffma2(b3, w, B[m][3]);
                }
            }
#pragma unroll
            for (int m = 0; m < 4; m++)
#pragma unroll
                for (int p = 0; p < 4; p++) {
                    float x, z; up2(B[m][p], x, z);
                    m2 |= (x > 0.f ? 1u : 0u) << (m * 8 + 2 * p);
                    m2 |= (z > 0.f ? 1u : 0u) << (m * 8 + 2 * p + 1);
                }
        }
        __syncwarp();
#pragma unroll
        for (int m = 0; m < 4; m++) st8(scr, lane + 32 * m, Hy[m][0], Hy[m][1], Hy[m][2], Hy[m][3]);
        __syncwarp();

        // ---- T1y fwd: u = c + hy @ T1y (u persists into backward) ----
        u64 U[4][4];
#pragma unroll
        for (int m = 0; m < 4; m++)
#pragma unroll
            for (int p = 0; p < 4; p++) U[m][p] = cc[m][p];
#pragma unroll 4
        for (int j = 0; j < 128; j++) {
            u64 b0, b1, b2, b3; ld8(scr, j, b0, b1, b2, b3);
            int base = j * 128 + (lane ^ (j & 31));
#pragma unroll
            for (int m = 0; m < 4; m++) {
                u64 w = pks(sT1y[base + 32 * m]);
                U[m][0] = ffma2(b0, w, U[m][0]); U[m][1] = ffma2(b1, w, U[m][1]);
                U[m][2] = ffma2(b2, w, U[m][2]); U[m][3] = ffma2(b3, w, U[m][3]);
            }
        }

        // ---- logits partials, warp reduction, softmax -> dlogits ----
        u64 lg[4][4];
#pragma unroll
        for (int k = 0; k < 4; k++)
#pragma unroll
            for (int p = 0; p < 4; p++) lg[k][p] = 0ull;
#pragma unroll
        for (int m = 0; m < 4; m++) {
            float4 t2 = *reinterpret_cast<const float4*>(&sT2[(lane + 32 * m) * 4]);
#pragma unroll
            for (int p = 0; p < 4; p++) {
                float ux, uz; up2(U[m][p], ux, uz);
                float ax = ux * __fdividef(1.f, 1.f + __expf(-ux));
                float az = uz * __fdividef(1.f, 1.f + __expf(-uz));
                u64 a2 = pk2(ax, az);
                lg[0][p] = ffma2(a2, pks(t2.x), lg[0][p]);
                lg[1][p] = ffma2(a2, pks(t2.y), lg[1][p]);
                lg[2][p] = ffma2(a2, pks(t2.z), lg[2][p]);
                lg[3][p] = ffma2(a2, pks(t2.w), lg[3][p]);
            }
        }
#pragma unroll
        for (int off = 16; off > 0; off >>= 1)
#pragma unroll
            for (int k = 0; k < 4; k++)
#pragma unroll
                for (int p = 0; p < 4; p++)
                    lg[k][p] = fadd2(lg[k][p], __shfl_xor_sync(0xffffffffu, lg[k][p], off));

        u64 dl[4][4];
#pragma unroll
        for (int p = 0; p < 4; p++) {
            float l0[4], l1[4];
#pragma unroll
            for (int k = 0; k < 4; k++) {
                float x, z; up2(lg[k][p], x, z);
                l0[k] = x + st2b[k]; l1[k] = z + st2b[k];
            }
            float dlo[4], dhi[4];
            {
                float mx = fmaxf(fmaxf(l0[0], l0[1]), fmaxf(l0[2], l0[3]));
                float e0 = __expf(l0[0] - mx), e1 = __expf(l0[1] - mx);
                float e2 = __expf(l0[2] - mx), e3 = __expf(l0[3] - mx);
                float sw = svf[2 * p]; int tc = tci[2 * p];
                float inv = sw * __fdividef(1.f, e0 + e1 + e2 + e3);
                dlo[0] = e0 * inv - (tc == 0 ? sw : 0.f);
                dlo[1] = e1 * inv - (tc == 1 ? sw : 0.f);
                dlo[2] = e2 * inv - (tc == 2 ? sw : 0.f);
                dlo[3] = e3 * inv - (tc == 3 ? sw : 0.f);
            }
            {
                float mx = fmaxf(fmaxf(l1[0], l1[1]), fmaxf(l1[2], l1[3]));
                float e0 = __expf(l1[0] - mx), e1 = __expf(l1[1] - mx);
                float e2 = __expf(l1[2] - mx), e3 = __expf(l1[3] - mx);
                float sw = svf[2 * p + 1]; int tc = tci[2 * p + 1];
                float inv = sw * __fdividef(1.f, e0 + e1 + e2 + e3);
                dhi[0] = e0 * inv - (tc == 0 ? sw : 0.f);
                dhi[1] = e1 * inv - (tc == 1 ? sw : 0.f);
                dhi[2] = e2 * inv - (tc == 2 ? sw : 0.f);
                dhi[3] = e3 * inv - (tc == 3 ? sw : 0.f);
            }
#pragma unroll
            for (int k = 0; k < 4; k++) dl[k][p] = pk2(dlo[k], dhi[k]);
        }

        // ---- du = (tr2w @ dl) * silu'(u), store ----
        __syncwarp();
#pragma unroll
        for (int m = 0; m < 4; m++) {
            int jj = lane + 32 * m;
            float4 t2 = *reinterpret_cast<const float4*>(&sT2[jj * 4]);
            u64 dv[4];
#pragma unroll
            for (int p = 0; p < 4; p++) {
                u64 da = fmul2(dl[0][p], pks(t2.x));
                da = ffma2(dl[1][p], pks(t2.y), da);
                da = ffma2(dl[2][p], pks(t2.z), da);
                da = ffma2(dl[3][p], pks(t2.w), da);
                float ux, uz; up2(U[m][p], ux, uz);
                float sgx = __fdividef(1.f, 1.f + __expf(-ux));
                float sgz = __fdividef(1.f, 1.f + __expf(-uz));
                float dsx = sgx * (1.f + ux * (1.f - sgx));
                float dsz = sgz * (1.f + uz * (1.f - sgz));
                dv[p] = fmul2(da, pk2(dsx, dsz));
            }
            st8(scr, jj, dv[0], dv[1], dv[2], dv[3]);
        }
        __syncwarp();

        // ---- T1y bwd: dhy ----
        u64 D[4][4];
#pragma unroll
        for (int m = 0; m < 4; m++)
#pragma unroll
            for (int p = 0; p < 4; p++) D[m][p] = 0ull;
#pragma unroll 4
        for (int k = 0; k < 128; k++) {
            u64 b0, b1, b2, b3; ld8(scr, k, b0, b1, b2, b3);
            int off = (k & 96) + ((k & 31) ^ lane);
#pragma unroll
            for (int m = 0; m < 4; m++) {
                u64 w = pks(sT1y[(lane + 32 * m) * 128 + off]);
                D[m][0] = ffma2(b0, w, D[m][0]); D[m][1] = ffma2(b1, w, D[m][1]);
                D[m][2] = ffma2(b2, w, D[m][2]); D[m][3] = ffma2(b3, w, D[m][3]);
            }
        }
        __syncwarp();
#pragma unroll
        for (int m = 0; m < 4; m++) st8(scr, lane + 32 * m, D[m][0], D[m][1], D[m][2], D[m][3]);
        __syncwarp();

        // ---- gy = 2*REG*y + Syw[lane,:] . dhy ----
        u64 gy[4];
#pragma unroll
        for (int p = 0; p < 4; p++) gy[p] = fmul2(pks(2.f * C_REG), y[p]);
#pragma unroll 4
        for (int j = 0; j < 128; j++) {
            u64 b0, b1, b2, b3; ld8(scr, j, b0, b1, b2, b3);
            u64 w = pks(sSyw[lane * 128 + (j & 96) + ((j & 31) ^ lane)]);
            gy[0] = ffma2(b0, w, gy[0]); gy[1] = ffma2(b1, w, gy[1]);
            gy[2] = ffma2(b2, w, gy[2]); gy[3] = ffma2(b3, w, gy[3]);
        }

        // ---- energy bwd: dh2pre = (h2>0) * e_w3[:, tci] ----
        __syncwarp();
#pragma unroll
        for (int m = 0; m < 4; m++) {
            int jj = lane + 32 * m;
            u64 dv[4];
#pragma unroll
            for (int p = 0; p < 4; p++) {
                float e0 = ((m2 >> (m * 8 + 2 * p)) & 1)     ? sE3T[tci[2 * p] * 128 + jj]     : 0.f;
                float e1 = ((m2 >> (m * 8 + 2 * p + 1)) & 1) ? sE3T[tci[2 * p + 1] * 128 + jj] : 0.f;
                dv[p] = pk2(e0, e1);
            }
            st8(scr, jj, dv[0], dv[1], dv[2], dv[3]);
        }
        __syncwarp();

        // ---- W2 bwd: dh1 (masked by h1>0) ----
#pragma unroll
        for (int m = 0; m < 4; m++)
#pragma unroll
            for (int p = 0; p < 4; p++) D[m][p] = 0ull;
#pragma unroll 4
        for (int k = 0; k < 128; k++) {
            u64 b0, b1, b2, b3; ld8(scr, k, b0, b1, b2, b3);
            int off = (k & 96) + ((k & 31) ^ lane);
#pragma unroll
            for (int m = 0; m < 4; m++) {
                u64 w = pks(sW2[(lane + 32 * m) * 128 + off]);
                D[m][0] = ffma2(b0, w, D[m][0]); D[m][1] = ffma2(b1, w, D[m][1]);
                D[m][2] = ffma2(b2, w, D[m][2]); D[m][3] = ffma2(b3, w, D[m][3]);
            }
        }
#pragma unroll
        for (int m = 0; m < 4; m++)
#pragma unroll
            for (int p = 0; p < 4; p++) {
                float x, z; up2(D[m][p], x, z);
                x = ((m1 >> (m * 8 + 2 * p)) & 1)     ? x : 0.f;
                z = ((m1 >> (m * 8 + 2 * p + 1)) & 1) ? z : 0.f;
                D[m][p] = pk2(x, z);
            }
        __syncwarp();
#pragma unroll
        for (int m = 0; m < 4; m++) st8(scr, lane + 32 * m, D[m][0], D[m][1], D[m][2], D[m][3]);
        __syncwarp();

        // ---- gy += E1y[lane,:] . dh1pre ----
#pragma unroll 4
        for (int j = 0; j < 128; j++) {
            u64 b0, b1, b2, b3; ld8(scr, j, b0, b1, b2, b3);
            u64 w = pks(sE1y[lane * 128 + (j & 96) + ((j & 31) ^ lane)]);
            gy[0] = ffma2(b0, w, gy[0]); gy[1] = ffma2(b1, w, gy[1]);
            gy[2] = ffma2(b2, w, gy[2]); gy[3] = ffma2(b3, w, gy[3]);
        }

        // ---- SGD update ----
#pragma unroll
        for (int p = 0; p < 4; p++) y[p] = ffma2(gy[p], pks(-C_LR), y[p]);
    }

#pragma unroll
    for (int p = 0; p < 4; p++) {
        float a, b; up2(y[p], a, b);
        out[(r0 + 2 * p) * NDY + lane] = a;
        out[(r0 + 2 * p + 1) * NDY + lane] = b;
    }
}

// ---------------- launcher ----------------
extern "C" void kernel_launch(void* const* d_in, const int* in_sizes, int n_in,
                              void* d_out, int out_size) {
    const float* x      = (const float*)d_in[0];
    const int*   t      = (const int*)d_in[1];
    const float* e_w1   = (const float*)d_in[2];
    const float* e_b1   = (const float*)d_in[3];
    const float* e_w2   = (const float*)d_in[4];
    const float* e_b2   = (const float*)d_in[5];
    const float* e_w3   = (const float*)d_in[6];
    const float* s_xw   = (const float*)d_in[8];
    const float* s_xb   = (const float*)d_in[9];
    const float* s_yw   = (const float*)d_in[10];
    const float* s_yb   = (const float*)d_in[11];
    const float* s_temb = (const float*)d_in[12];
    const float* s_t1w  = (const float*)d_in[13];
    const float* s_t1b  = (const float*)d_in[14];
    const float* s_t2w  = (const float*)d_in[15];
    const float* s_t2b  = (const float*)d_in[16];
    const float* tr1w   = (const float*)d_in[17];
    const float* tr1b   = (const float*)d_in[18];
    const float* tr2w   = (const float*)d_in[19];
    const float* tr2b   = (const float*)d_in[20];
    const int*   steps  = (const int*)d_in[21];
    float* out = (float*)d_out;

    float *p_hxe, *p_hxs, *p_c, *p_cth;
    cudaGetSymbolAddress((void**)&p_hxe, g_hxe);
    cudaGetSymbolAddress((void**)&p_hxs, g_hxs);
    cudaGetSymbolAddress((void**)&p_c,   g_c);
    cudaGetSymbolAddress((void**)&p_cth, g_cth);

    // 1) per-class constants
    cth_kernel<<<1, NH>>>(s_temb, s_t1w, s_t1b, s_t2w, s_t2b, tr1w, tr1b);

    // 2) per-row constants: hx_e, hx_s, then c = hx_s @ tr1w[:H] + cth[t]
    gemm128_kernel<<<NB / 64, 256>>>(x, NDX, NDX, e_w1, e_b1, nullptr, nullptr, p_hxe);
    gemm128_kernel<<<NB / 64, 256>>>(x, NDX, NDX, s_xw, s_xb, nullptr, nullptr, p_hxs);
    gemm128_kernel<<<NB / 64, 256>>>(p_hxs, NH, NH, tr1w, nullptr, p_cth, t, p_c);

    // 3) 20 SGD steps, warp-per-8-rows, packed f32x2, weights in swizzled SMEM
    cudaFuncSetAttribute(edi_main_kernel, cudaFuncAttributeMaxDynamicSharedMemorySize, SMEM_BYTES);
    edi_main_kernel<<<NB / 64, 256, SMEM_BYTES>>>(t, e_w1, e_w2, e_b2, e_w3,
                                                  s_yw, s_yb, tr1w, tr2w, tr2b,
                                                  steps, out);
}

// round 6
// speedup vs baseline: 2.4578x; 1.4461x over previous
#include <cuda_runtime.h>

typedef unsigned long long u64;

#define NB   131072
#define NDX  256
#define NDY  32
#define NK   4
#define NH   128
#define C_LR  0.1f
#define C_REG 0.01f
#define C_SW  1.0f

// ---------------- scratch (device globals: no allocation allowed) ----------------
__device__ float g_hxe[NB * NH];   // x @ e_w1[:DX] + e_b1
__device__ float g_hxs[NB * NH];   // x @ s_xw + s_xb
__device__ float g_c[NB * NH];     // static part of transition pre-activation
__device__ float g_cth[NK * NH];   // temb@tr1w[2H:3H] + th@tr1w[3H:4H] + tr1b (+ s_yb@T1y), per class
__device__ float g_P[NDY * NH];    // Syw @ T1y  (32 x 128) -- folded transition matrix

// ---------------- packed f32x2 helpers ----------------
__device__ __forceinline__ u64 pk2(float x, float y) {
    u64 r; asm("mov.b64 %0, {%1,%2};" : "=l"(r) : "f"(x), "f"(y)); return r;
}
__device__ __forceinline__ u64 pks(float x) {
    u64 r; asm("mov.b64 %0, {%1,%1};" : "=l"(r) : "f"(x)); return r;
}
__device__ __forceinline__ void up2(u64 v, float& x, float& y) {
    asm("mov.b64 {%0,%1}, %2;" : "=f"(x), "=f"(y) : "l"(v));
}
__device__ __forceinline__ u64 ffma2(u64 a, u64 b, u64 c) {
    u64 d; asm("fma.rn.f32x2 %0, %1, %2, %3;" : "=l"(d) : "l"(a), "l"(b), "l"(c)); return d;
}
__device__ __forceinline__ u64 fmul2(u64 a, u64 b) {
    u64 d; asm("mul.rn.f32x2 %0, %1, %2;" : "=l"(d) : "l"(a), "l"(b)); return d;
}
__device__ __forceinline__ u64 fadd2(u64 a, u64 b) {
    u64 d; asm("add.rn.f32x2 %0, %1, %2;" : "=l"(d) : "l"(a), "l"(b)); return d;
}

// Per-warp activation scratch: two regions of 512 floats (float4 per j).
__device__ __forceinline__ void st8(float* scr, int j, u64 v0, u64 v1, u64 v2, u64 v3) {
    *reinterpret_cast<ulonglong2*>(scr + j * 4)       = make_ulonglong2(v0, v1);
    *reinterpret_cast<ulonglong2*>(scr + 512 + j * 4) = make_ulonglong2(v2, v3);
}
__device__ __forceinline__ void ld8(const float* scr, int j, u64& v0, u64& v1, u64& v2, u64& v3) {
    ulonglong2 a = *reinterpret_cast<const ulonglong2*>(scr + j * 4);
    ulonglong2 b = *reinterpret_cast<const ulonglong2*>(scr + 512 + j * 4);
    v0 = a.x; v1 = a.y; v2 = b.x; v3 = b.y;
}

// ---------------- kernel B: per-class constants ----------------
__global__ void cth_kernel(const float* __restrict__ s_temb,
                           const float* __restrict__ s_t1w,
                           const float* __restrict__ s_t1b,
                           const float* __restrict__ s_t2w,
                           const float* __restrict__ s_t2b,
                           const float* __restrict__ tr1w,
                           const float* __restrict__ tr1b) {
    int j = threadIdx.x;                 // 0..127
    __shared__ float v[NH], th[NH];
    for (int k = 0; k < NK; k++) {
        float tau = fmaxf((float)k / 1000.0f, 1e-6f);
        float z = tau * s_t1w[j] + s_t1b[j];
        float sg = 1.0f / (1.0f + expf(-z));
        v[j] = z * sg;
        __syncthreads();
        float acc = s_t2b[j];
        for (int q = 0; q < NH; q++) acc += v[q] * s_t2w[q * NH + j];
        th[j] = acc;
        __syncthreads();
        float c = tr1b[j];
        for (int q = 0; q < NH; q++) {
            c += s_temb[k * NH + q] * tr1w[(2 * NH + q) * NH + j];
            c += th[q] * tr1w[(3 * NH + q) * NH + j];
        }
        g_cth[k * NH + j] = c;
        __syncthreads();
    }
}

// ---------------- kernel P: fold Syw@T1y and s_yb@T1y ----------------
// grid = 32 blocks of 128 threads; block d computes P[d,:]; block 0 also folds
// bp[k] = sum_j s_yb[j]*T1y[j,k] into all 4 class rows of g_cth.
__global__ void p_kernel(const float* __restrict__ s_yw,
                         const float* __restrict__ s_yb,
                         const float* __restrict__ tr1w) {
    int k = threadIdx.x;
    int d = blockIdx.x;
    float acc = 0.0f;
    for (int j = 0; j < NH; j++)
        acc += s_yw[d * NH + j] * tr1w[(NH + j) * NH + k];
    g_P[d * NH + k] = acc;
    if (d == 0) {
        float bp = 0.0f;
        for (int j = 0; j < NH; j++)
            bp += s_yb[j] * tr1w[(NH + j) * NH + k];
        for (int c = 0; c < NK; c++) g_cth[c * NH + k] += bp;
    }
}

// ---------------- kernel A: tiled FP32 GEMM, N fixed at 128 ----------------
__global__ __launch_bounds__(256)
void gemm128_kernel(const float* __restrict__ X, int ldx, int Kdim,
                    const float* __restrict__ Wm,
                    const float* __restrict__ bias,
                    const float* __restrict__ table,
                    const int* __restrict__ tt,
                    float* __restrict__ out) {
    __shared__ float Xs[64 * 33];
    __shared__ float Ws[32 * 128];
    int tid = threadIdx.x;
    int tcol = tid & 31;
    int trow = tid >> 5;
    int m0 = blockIdx.x * 64;

    float acc[8][4];
#pragma unroll
    for (int p = 0; p < 8; p++)
#pragma unroll
        for (int q = 0; q < 4; q++) acc[p][q] = 0.0f;

    for (int k0 = 0; k0 < Kdim; k0 += 32) {
#pragma unroll
        for (int i = 0; i < 8; i++) {
            int e = tid + 256 * i;
            int m = e >> 5, kk = e & 31;
            Xs[m * 33 + kk] = X[(m0 + m) * ldx + k0 + kk];
        }
#pragma unroll
        for (int i = 0; i < 16; i++) {
            int e = tid + 256 * i;
            int kk = e >> 7, n = e & 127;
            Ws[kk * 128 + n] = Wm[(k0 + kk) * NH + n];
        }
        __syncthreads();
#pragma unroll 8
        for (int kk = 0; kk < 32; kk++) {
            float xv[8], wv[4];
#pragma unroll
            for (int p = 0; p < 8; p++) xv[p] = Xs[(trow + 8 * p) * 33 + kk];
#pragma unroll
            for (int q = 0; q < 4; q++) wv[q] = Ws[kk * 128 + tcol + 32 * q];
#pragma unroll
            for (int p = 0; p < 8; p++)
#pragma unroll
                for (int q = 0; q < 4; q++) acc[p][q] += xv[p] * wv[q];
        }
        __syncthreads();
    }
#pragma unroll
    for (int p = 0; p < 8; p++) {
        int m = m0 + trow + 8 * p;
        int tc = 0;
        if (table) { int tv = tt[m]; tc = tv > 0 ? tv : 0; }
#pragma unroll
        for (int q = 0; q < 4; q++) {
            int n = tcol + 32 * q;
            float vv = acc[p][q];
            if (bias)  vv += bias[n];
            if (table) vv += table[tc * NH + n];
            out[m * NH + n] = vv;
        }
    }
}

// ---------------- main kernel: 20 SGD steps, warp-per-8-rows, folded transition ----------------
// SMEM floats: sE1y 4096 | sW2 16384 | sP 4096 | sE3T 512 | sT2 512 | sb2 128 | st2b 8 | scr 8*1024
#define SMEM_FLOATS (4096 + 16384 + 4096 + 512 + 512 + 128 + 8 + 8 * 1024)
#define SMEM_BYTES  (SMEM_FLOATS * 4)

__global__ __launch_bounds__(256, 1)
void edi_main_kernel(const int* __restrict__ t,
                     const float* __restrict__ e_w1,
                     const float* __restrict__ e_w2,
                     const float* __restrict__ e_b2,
                     const float* __restrict__ e_w3,
                     const float* __restrict__ tr2w,
                     const float* __restrict__ tr2b,
                     const int* __restrict__ steps_p,
                     float* __restrict__ out) {
    extern __shared__ float sm[];
    float* sE1y = sm;
    float* sW2  = sE1y + 4096;
    float* sP   = sW2 + 16384;
    float* sE3T = sP + 4096;      // transposed: [k][j]
    float* sT2  = sE3T + 512;
    float* sb2  = sT2 + 512;
    float* st2b = sb2 + 128;
    float* sscr = st2b + 8;

    int tid = threadIdx.x;
    // XOR-swizzled weight layouts: row-read and col-read both conflict-free.
    for (int idx = tid; idx < 32 * 128; idx += 256) {
        int d = idx >> 7, k = idx & 127;
        int swi = d * 128 + (k & 96) + ((k & 31) ^ d);
        sE1y[swi] = e_w1[(NDX + d) * NH + k];
        sP[swi]   = g_P[idx];
    }
    for (int idx = tid; idx < 128 * 128; idx += 256) {
        int j = idx >> 7, k = idx & 127;
        int swi = j * 128 + (k & 96) + ((k & 31) ^ (j & 31));
        sW2[swi]  = e_w2[idx];
    }
    for (int idx = tid; idx < 512; idx += 256) {
        sE3T[(idx & 3) * 128 + (idx >> 2)] = e_w3[idx];
        sT2[idx] = tr2w[idx];
    }
    if (tid < 128) sb2[tid] = e_b2[tid];
    if (tid < 4)   st2b[tid] = tr2b[tid];
    __syncthreads();

    const int lane = tid & 31;
    const int warp = tid >> 5;
    float* scr = sscr + warp * 1024;
    const int r0 = (blockIdx.x * 8 + warp) * 8;    // 8 rows per warp
    const int nsteps = *steps_p;

    int tci[8]; float svf[8];
#pragma unroll
    for (int r = 0; r < 8; r++) {
        int tv = t[r0 + r];
        tci[r] = tv > 0 ? tv : 0;
        svf[r] = tv >= 0 ? C_SW : 0.0f;
    }

    u64 y[4] = {0ull, 0ull, 0ull, 0ull};           // pairs (rows 2p, 2p+1); lane d owns y[d]
    u64 hxe[4][4], cc[4][4];                       // [m][pair]
#pragma unroll
    for (int m = 0; m < 4; m++)
#pragma unroll
        for (int p = 0; p < 4; p++) {
            int col = 32 * m + lane;
            hxe[m][p] = pk2(g_hxe[(r0 + 2 * p) * NH + col], g_hxe[(r0 + 2 * p + 1) * NH + col]);
            cc[m][p]  = pk2(g_c[(r0 + 2 * p) * NH + col],   g_c[(r0 + 2 * p + 1) * NH + col]);
        }

    for (int s = 0; s < nsteps; s++) {
        __syncwarp();
        st8(scr, lane, y[0], y[1], y[2], y[3]);    // y[d] broadcast table, d = lane
        __syncwarp();

        // ---- fused fwd: h1pre = hxe + y@E1y ; u = cc + y@P ----
        u64 A[4][4], U[4][4];
#pragma unroll
        for (int m = 0; m < 4; m++)
#pragma unroll
            for (int p = 0; p < 4; p++) { A[m][p] = hxe[m][p]; U[m][p] = cc[m][p]; }
#pragma unroll 4
        for (int d = 0; d < 32; d++) {
            u64 b0, b1, b2, b3; ld8(scr, d, b0, b1, b2, b3);
            int base = d * 128 + (lane ^ d);
#pragma unroll
            for (int m = 0; m < 4; m++) {
                u64 w = pks(sE1y[base + 32 * m]);
                A[m][0] = ffma2(b0, w, A[m][0]); A[m][1] = ffma2(b1, w, A[m][1]);
                A[m][2] = ffma2(b2, w, A[m][2]); A[m][3] = ffma2(b3, w, A[m][3]);
                u64 v = pks(sP[base + 32 * m]);
                U[m][0] = ffma2(b0, v, U[m][0]); U[m][1] = ffma2(b1, v, U[m][1]);
                U[m][2] = ffma2(b2, v, U[m][2]); U[m][3] = ffma2(b3, v, U[m][3]);
            }
        }
        // relu(h1) + sign mask
        unsigned m1 = 0;
#pragma unroll
        for (int m = 0; m < 4; m++)
#pragma unroll
            for (int p = 0; p < 4; p++) {
                float x, z; up2(A[m][p], x, z);
                m1 |= (x > 0.f ? 1u : 0u) << (m * 8 + 2 * p);
                m1 |= (z > 0.f ? 1u : 0u) << (m * 8 + 2 * p + 1);
                A[m][p] = pk2(fmaxf(x, 0.f), fmaxf(z, 0.f));
            }
        __syncwarp();
#pragma unroll
        for (int m = 0; m < 4; m++) st8(scr, lane + 32 * m, A[m][0], A[m][1], A[m][2], A[m][3]);
        __syncwarp();

        // ---- W2 fwd: only the relu mask of h2 is needed ----
        unsigned m2 = 0;
        {
            u64 B[4][4];
#pragma unroll
            for (int m = 0; m < 4; m++) {
                float bb = sb2[32 * m + lane];
#pragma unroll
                for (int p = 0; p < 4; p++) B[m][p] = pks(bb);
            }
#pragma unroll 4
            for (int j = 0; j < 128; j++) {
                u64 b0, b1, b2, b3; ld8(scr, j, b0, b1, b2, b3);
                int base = j * 128 + (lane ^ (j & 31));
#pragma unroll
                for (int m = 0; m < 4; m++) {
                    u64 w = pks(sW2[base + 32 * m]);
                    B[m][0] = ffma2(b0, w, B[m][0]); B[m][1] = ffma2(b1, w, B[m][1]);
                    B[m][2] = ffma2(b2, w, B[m][2]); B[m][3] = ffma2(b3, w, B[m][3]);
                }
            }
#pragma unroll
            for (int m = 0; m < 4; m++)
#pragma unroll
                for (int p = 0; p < 4; p++) {
                    float x, z; up2(B[m][p], x, z);
                    m2 |= (x > 0.f ? 1u : 0u) << (m * 8 + 2 * p);
                    m2 |= (z > 0.f ? 1u : 0u) << (m * 8 + 2 * p + 1);
                }
        }

        // ---- logits partials, warp reduction, softmax -> dlogits ----
        u64 lg[4][4];
#pragma unroll
        for (int k = 0; k < 4; k++)
#pragma unroll
            for (int p = 0; p < 4; p++) lg[k][p] = 0ull;
#pragma unroll
        for (int m = 0; m < 4; m++) {
            float4 t2 = *reinterpret_cast<const float4*>(&sT2[(lane + 32 * m) * 4]);
#pragma unroll
            for (int p = 0; p < 4; p++) {
                float ux, uz; up2(U[m][p], ux, uz);
                float ax = ux * __fdividef(1.f, 1.f + __expf(-ux));
                float az = uz * __fdividef(1.f, 1.f + __expf(-uz));
                u64 a2 = pk2(ax, az);
                lg[0][p] = ffma2(a2, pks(t2.x), lg[0][p]);
                lg[1][p] = ffma2(a2, pks(t2.y), lg[1][p]);
                lg[2][p] = ffma2(a2, pks(t2.z), lg[2][p]);
                lg[3][p] = ffma2(a2, pks(t2.w), lg[3][p]);
            }
        }
#pragma unroll
        for (int off = 16; off > 0; off >>= 1)
#pragma unroll
            for (int k = 0; k < 4; k++)
#pragma unroll
                for (int p = 0; p < 4; p++)
                    lg[k][p] = fadd2(lg[k][p], __shfl_xor_sync(0xffffffffu, lg[k][p], off));

        u64 dl[4][4];
#pragma unroll
        for (int p = 0; p < 4; p++) {
            float l0[4], l1[4];
#pragma unroll
            for (int k = 0; k < 4; k++) {
                float x, z; up2(lg[k][p], x, z);
                l0[k] = x + st2b[k]; l1[k] = z + st2b[k];
            }
            float dlo[4], dhi[4];
            {
                float mx = fmaxf(fmaxf(l0[0], l0[1]), fmaxf(l0[2], l0[3]));
                float e0 = __expf(l0[0] - mx), e1 = __expf(l0[1] - mx);
                float e2 = __expf(l0[2] - mx), e3 = __expf(l0[3] - mx);
                float sw = svf[2 * p]; int tc = tci[2 * p];
                float inv = sw * __fdividef(1.f, e0 + e1 + e2 + e3);
                dlo[0] = e0 * inv - (tc == 0 ? sw : 0.f);
                dlo[1] = e1 * inv - (tc == 1 ? sw : 0.f);
                dlo[2] = e2 * inv - (tc == 2 ? sw : 0.f);
                dlo[3] = e3 * inv - (tc == 3 ? sw : 0.f);
            }
            {
                float mx = fmaxf(fmaxf(l1[0], l1[1]), fmaxf(l1[2], l1[3]));
                float e0 = __expf(l1[0] - mx), e1 = __expf(l1[1] - mx);
                float e2 = __expf(l1[2] - mx), e3 = __expf(l1[3] - mx);
                float sw = svf[2 * p + 1]; int tc = tci[2 * p + 1];
                float inv = sw * __fdividef(1.f, e0 + e1 + e2 + e3);
                dhi[0] = e0 * inv - (tc == 0 ? sw : 0.f);
                dhi[1] = e1 * inv - (tc == 1 ? sw : 0.f);
                dhi[2] = e2 * inv - (tc == 2 ? sw : 0.f);
                dhi[3] = e3 * inv - (tc == 3 ? sw : 0.f);
            }
#pragma unroll
            for (int k = 0; k < 4; k++) dl[k][p] = pk2(dlo[k], dhi[k]);
        }

        // ---- du = (tr2w @ dl) * silu'(u), store ----
        __syncwarp();
#pragma unroll
        for (int m = 0; m < 4; m++) {
            int jj = lane + 32 * m;
            float4 t2 = *reinterpret_cast<const float4*>(&sT2[jj * 4]);
            u64 dv[4];
#pragma unroll
            for (int p = 0; p < 4; p++) {
                u64 da = fmul2(dl[0][p], pks(t2.x));
                da = ffma2(dl[1][p], pks(t2.y), da);
                da = ffma2(dl[2][p], pks(t2.z), da);
                da = ffma2(dl[3][p], pks(t2.w), da);
                float ux, uz; up2(U[m][p], ux, uz);
                float sgx = __fdividef(1.f, 1.f + __expf(-ux));
                float sgz = __fdividef(1.f, 1.f + __expf(-uz));
                float dsx = sgx * (1.f + ux * (1.f - sgx));
                float dsz = sgz * (1.f + uz * (1.f - sgz));
                dv[p] = fmul2(da, pk2(dsx, dsz));
            }
            st8(scr, jj, dv[0], dv[1], dv[2], dv[3]);
        }
        __syncwarp();

        // ---- folded transition bwd: gy = 2*REG*y + P[lane,:] . du ----
        u64 gy[4];
#pragma unroll
        for (int p = 0; p < 4; p++) gy[p] = fmul2(pks(2.f * C_REG), y[p]);
#pragma unroll 4
        for (int k = 0; k < 128; k++) {
            u64 b0, b1, b2, b3; ld8(scr, k, b0, b1, b2, b3);
            u64 w = pks(sP[lane * 128 + (k & 96) + ((k & 31) ^ lane)]);
            gy[0] = ffma2(b0, w, gy[0]); gy[1] = ffma2(b1, w, gy[1]);
            gy[2] = ffma2(b2, w, gy[2]); gy[3] = ffma2(b3, w, gy[3]);
        }

        // ---- energy bwd: dh2pre = (h2>0) * e_w3[:, tci] ----
        __syncwarp();
#pragma unroll
        for (int m = 0; m < 4; m++) {
            int jj = lane + 32 * m;
            u64 dv[4];
#pragma unroll
            for (int p = 0; p < 4; p++) {
                float e0 = ((m2 >> (m * 8 + 2 * p)) & 1)     ? sE3T[tci[2 * p] * 128 + jj]     : 0.f;
                float e1 = ((m2 >> (m * 8 + 2 * p + 1)) & 1) ? sE3T[tci[2 * p + 1] * 128 + jj] : 0.f;
                dv[p] = pk2(e0, e1);
            }
            st8(scr, jj, dv[0], dv[1], dv[2], dv[3]);
        }
        __syncwarp();

        // ---- W2 bwd: dh1 (masked by h1>0) ----
        u64 D[4][4];
#pragma unroll
        for (int m = 0; m < 4; m++)
#pragma unroll
            for (int p = 0; p < 4; p++) D[m][p] = 0ull;
#pragma unroll 4
        for (int k = 0; k < 128; k++) {
            u64 b0, b1, b2, b3; ld8(scr, k, b0, b1, b2, b3);
            int off = (k & 96) + ((k & 31) ^ lane);
#pragma unroll
            for (int m = 0; m < 4; m++) {
                u64 w = pks(sW2[(lane + 32 * m) * 128 + off]);
                D[m][0] = ffma2(b0, w, D[m][0]); D[m][1] = ffma2(b1, w, D[m][1]);
                D[m][2] = ffma2(b2, w, D[m][2]); D[m][3] = ffma2(b3, w, D[m][3]);
            }
        }
#pragma unroll
        for (int m = 0; m < 4; m++)
#pragma unroll
            for (int p = 0; p < 4; p++) {
                float x, z; up2(D[m][p], x, z);
                x = ((m1 >> (m * 8 + 2 * p)) & 1)     ? x : 0.f;
                z = ((m1 >> (m * 8 + 2 * p + 1)) & 1) ? z : 0.f;
                D[m][p] = pk2(x, z);
            }
        __syncwarp();
#pragma unroll
        for (int m = 0; m < 4; m++) st8(scr, lane + 32 * m, D[m][0], D[m][1], D[m][2], D[m][3]);
        __syncwarp();

        // ---- gy += E1y[lane,:] . dh1pre ----
#pragma unroll 4
        for (int j = 0; j < 128; j++) {
            u64 b0, b1, b2, b3; ld8(scr, j, b0, b1, b2, b3);
            u64 w = pks(sE1y[lane * 128 + (j & 96) + ((j & 31) ^ lane)]);
            gy[0] = ffma2(b0, w, gy[0]); gy[1] = ffma2(b1, w, gy[1]);
            gy[2] = ffma2(b2, w, gy[2]); gy[3] = ffma2(b3, w, gy[3]);
        }

        // ---- SGD update ----
#pragma unroll
        for (int p = 0; p < 4; p++) y[p] = ffma2(gy[p], pks(-C_LR), y[p]);
    }

#pragma unroll
    for (int p = 0; p < 4; p++) {
        float a, b; up2(y[p], a, b);
        out[(r0 + 2 * p) * NDY + lane] = a;
        out[(r0 + 2 * p + 1) * NDY + lane] = b;
    }
}

// ---------------- launcher ----------------
extern "C" void kernel_launch(void* const* d_in, const int* in_sizes, int n_in,
                              void* d_out, int out_size) {
    const float* x      = (const float*)d_in[0];
    const int*   t      = (const int*)d_in[1];
    const float* e_w1   = (const float*)d_in[2];
    const float* e_b1   = (const float*)d_in[3];
    const float* e_w2   = (const float*)d_in[4];
    const float* e_b2   = (const float*)d_in[5];
    const float* e_w3   = (const float*)d_in[6];
    const float* s_xw   = (const float*)d_in[8];
    const float* s_xb   = (const float*)d_in[9];
    const float* s_yw   = (const float*)d_in[10];
    const float* s_yb   = (const float*)d_in[11];
    const float* s_temb = (const float*)d_in[12];
    const float* s_t1w  = (const float*)d_in[13];
    const float* s_t1b  = (const float*)d_in[14];
    const float* s_t2w  = (const float*)d_in[15];
    const float* s_t2b  = (const float*)d_in[16];
    const float* tr1w   = (const float*)d_in[17];
    const float* tr1b   = (const float*)d_in[18];
    const float* tr2w   = (const float*)d_in[19];
    const float* tr2b   = (const float*)d_in[20];
    const int*   steps  = (const int*)d_in[21];
    float* out = (float*)d_out;

    float *p_hxe, *p_hxs, *p_c, *p_cth;
    cudaGetSymbolAddress((void**)&p_hxe, g_hxe);
    cudaGetSymbolAddress((void**)&p_hxs, g_hxs);
    cudaGetSymbolAddress((void**)&p_c,   g_c);
    cudaGetSymbolAddress((void**)&p_cth, g_cth);

    // 1) per-class constants, then fold Syw@T1y (and s_yb@T1y into cth)
    cth_kernel<<<1, NH>>>(s_temb, s_t1w, s_t1b, s_t2w, s_t2b, tr1w, tr1b);
    p_kernel<<<NDY, NH>>>(s_yw, s_yb, tr1w);

    // 2) per-row constants: hx_e, hx_s, then c = hx_s @ tr1w[:H] + cth[t]
    gemm128_kernel<<<NB / 64, 256>>>(x, NDX, NDX, e_w1, e_b1, nullptr, nullptr, p_hxe);
    gemm128_kernel<<<NB / 64, 256>>>(x, NDX, NDX, s_xw, s_xb, nullptr, nullptr, p_hxs);
    gemm128_kernel<<<NB / 64, 256>>>(p_hxs, NH, NH, tr1w, nullptr, p_cth, t, p_c);

    // 3) 20 SGD steps, warp-per-8-rows, folded transition, packed f32x2
    cudaFuncSetAttribute(edi_main_kernel, cudaFuncAttributeMaxDynamicSharedMemorySize, SMEM_BYTES);
    edi_main_kernel<<<NB / 64, 256, SMEM_BYTES>>>(t, e_w1, e_w2, e_b2, e_w3,
                                                  tr2w, tr2b, steps, out);
}

// round 10
// speedup vs baseline: 2.4873x; 1.0120x over previous
#include <cuda_runtime.h>

typedef unsigned long long u64;

#define NB   131072
#define NDX  256
#define NDY  32
#define NK   4
#define NH   128
#define C_LR  0.1f
#define C_REG 0.01f
#define C_SW  1.0f

// ---------------- scratch (device globals: no allocation allowed) ----------------
__device__ float g_hxe[NB * NH];   // x @ e_w1[:DX] + e_b1
__device__ float g_hxs[NB * NH];   // x @ s_xw + s_xb
__device__ float g_c[NB * NH];     // static part of transition pre-activation
__device__ float g_cth[NK * NH];   // per-class constant (incl. s_yb@T1y fold)
__device__ float g_P[NDY * NH];    // Syw @ T1y  (32 x 128) -- folded transition matrix

// ---------------- packed f32x2 helpers ----------------
__device__ __forceinline__ u64 pk2(float x, float y) {
    u64 r; asm("mov.b64 %0, {%1,%2};" : "=l"(r) : "f"(x), "f"(y)); return r;
}
__device__ __forceinline__ u64 pks(float x) {
    u64 r; asm("mov.b64 %0, {%1,%1};" : "=l"(r) : "f"(x)); return r;
}
__device__ __forceinline__ void up2(u64 v, float& x, float& y) {
    asm("mov.b64 {%0,%1}, %2;" : "=f"(x), "=f"(y) : "l"(v));
}
__device__ __forceinline__ u64 ffma2(u64 a, u64 b, u64 c) {
    u64 d; asm("fma.rn.f32x2 %0, %1, %2, %3;" : "=l"(d) : "l"(a), "l"(b), "l"(c)); return d;
}
__device__ __forceinline__ u64 fmul2(u64 a, u64 b) {
    u64 d; asm("mul.rn.f32x2 %0, %1, %2;" : "=l"(d) : "l"(a), "l"(b)); return d;
}
__device__ __forceinline__ u64 fadd2(u64 a, u64 b) {
    u64 d; asm("add.rn.f32x2 %0, %1, %2;" : "=l"(d) : "l"(a), "l"(b)); return d;
}

// Per-warp activation scratch: two regions of 512 floats (float4 per j).
__device__ __forceinline__ void st8(float* scr, int j, u64 v0, u64 v1, u64 v2, u64 v3) {
    *reinterpret_cast<ulonglong2*>(scr + j * 4)       = make_ulonglong2(v0, v1);
    *reinterpret_cast<ulonglong2*>(scr + 512 + j * 4) = make_ulonglong2(v2, v3);
}
__device__ __forceinline__ void ld8(const float* scr, int j, u64& v0, u64& v1, u64& v2, u64& v3) {
    ulonglong2 a = *reinterpret_cast<const ulonglong2*>(scr + j * 4);
    ulonglong2 b = *reinterpret_cast<const ulonglong2*>(scr + 512 + j * 4);
    v0 = a.x; v1 = a.y; v2 = b.x; v3 = b.y;
}

// ---------------- kernel B: per-class constants ----------------
__global__ void cth_kernel(const float* __restrict__ s_temb,
                           const float* __restrict__ s_t1w,
                           const float* __restrict__ s_t1b,
                           const float* __restrict__ s_t2w,
                           const float* __restrict__ s_t2b,
                           const float* __restrict__ tr1w,
                           const float* __restrict__ tr1b) {
    int j = threadIdx.x;                 // 0..127
    __shared__ float v[NH], th[NH];
    for (int k = 0; k < NK; k++) {
        float tau = fmaxf((float)k / 1000.0f, 1e-6f);
        float z = tau * s_t1w[j] + s_t1b[j];
        float sg = 1.0f / (1.0f + expf(-z));
        v[j] = z * sg;
        __syncthreads();
        float acc = s_t2b[j];
        for (int q = 0; q < NH; q++) acc += v[q] * s_t2w[q * NH + j];
        th[j] = acc;
        __syncthreads();
        float c = tr1b[j];
        for (int q = 0; q < NH; q++) {
            c += s_temb[k * NH + q] * tr1w[(2 * NH + q) * NH + j];
            c += th[q] * tr1w[(3 * NH + q) * NH + j];
        }
        g_cth[k * NH + j] = c;
        __syncthreads();
    }
}

// ---------------- kernel P: fold Syw@T1y and s_yb@T1y ----------------
__global__ void p_kernel(const float* __restrict__ s_yw,
                         const float* __restrict__ s_yb,
                         const float* __restrict__ tr1w) {
    int k = threadIdx.x;
    int d = blockIdx.x;
    float acc = 0.0f;
    for (int j = 0; j < NH; j++)
        acc += s_yw[d * NH + j] * tr1w[(NH + j) * NH + k];
    g_P[d * NH + k] = acc;
    if (d == 0) {
        float bp = 0.0f;
        for (int j = 0; j < NH; j++)
            bp += s_yb[j] * tr1w[(NH + j) * NH + k];
        for (int c = 0; c < NK; c++) g_cth[c * NH + k] += bp;
    }
}

// ---------------- kernel A: tiled FP32 GEMM, N fixed at 128 ----------------
__global__ __launch_bounds__(256)
void gemm128_kernel(const float* __restrict__ X, int ldx, int Kdim,
                    const float* __restrict__ Wm,
                    const float* __restrict__ bias,
                    const float* __restrict__ table,
                    const int* __restrict__ tt,
                    float* __restrict__ out) {
    __shared__ float Xs[64 * 33];
    __shared__ float Ws[32 * 128];
    int tid = threadIdx.x;
    int tcol = tid & 31;
    int trow = tid >> 5;
    int m0 = blockIdx.x * 64;

    float acc[8][4];
#pragma unroll
    for (int p = 0; p < 8; p++)
#pragma unroll
        for (int q = 0; q < 4; q++) acc[p][q] = 0.0f;

    for (int k0 = 0; k0 < Kdim; k0 += 32) {
#pragma unroll
        for (int i = 0; i < 8; i++) {
            int e = tid + 256 * i;
            int m = e >> 5, kk = e & 31;
            Xs[m * 33 + kk] = X[(m0 + m) * ldx + k0 + kk];
        }
#pragma unroll
        for (int i = 0; i < 16; i++) {
            int e = tid + 256 * i;
            int kk = e >> 7, n = e & 127;
            Ws[kk * 128 + n] = Wm[(k0 + kk) * NH + n];
        }
        __syncthreads();
#pragma unroll 8
        for (int kk = 0; kk < 32; kk++) {
            float xv[8], wv[4];
#pragma unroll
            for (int p = 0; p < 8; p++) xv[p] = Xs[(trow + 8 * p) * 33 + kk];
#pragma unroll
            for (int q = 0; q < 4; q++) wv[q] = Ws[kk * 128 + tcol + 32 * q];
#pragma unroll
            for (int p = 0; p < 8; p++)
#pragma unroll
                for (int q = 0; q < 4; q++) acc[p][q] += xv[p] * wv[q];
        }
        __syncthreads();
    }
#pragma unroll
    for (int p = 0; p < 8; p++) {
        int m = m0 + trow + 8 * p;
        int tc = 0;
        if (table) { int tv = tt[m]; tc = tv > 0 ? tv : 0; }
#pragma unroll
        for (int q = 0; q < 4; q++) {
            int n = tcol + 32 * q;
            float vv = acc[p][q];
            if (bias)  vv += bias[n];
            if (table) vv += table[tc * NH + n];
            out[m * NH + n] = vv;
        }
    }
}

// ---------------- kernel A2: dual-output GEMM (shares X tiles) ----------------
__global__ __launch_bounds__(256)
void gemm128_dual_kernel(const float* __restrict__ X, int ldx, int Kdim,
                         const float* __restrict__ W0, const float* __restrict__ b0v,
                         const float* __restrict__ W1, const float* __restrict__ b1v,
                         float* __restrict__ out0, float* __restrict__ out1) {
    __shared__ float Xs[64 * 33];
    __shared__ float Ws0[32 * 128];
    __shared__ float Ws1[32 * 128];
    int tid = threadIdx.x;
    int tcol = tid & 31;
    int trow = tid >> 5;
    int m0 = blockIdx.x * 64;

    float a0[8][4], a1[8][4];
#pragma unroll
    for (int p = 0; p < 8; p++)
#pragma unroll
        for (int q = 0; q < 4; q++) { a0[p][q] = 0.0f; a1[p][q] = 0.0f; }

    for (int k0 = 0; k0 < Kdim; k0 += 32) {
#pragma unroll
        for (int i = 0; i < 8; i++) {
            int e = tid + 256 * i;
            int m = e >> 5, kk = e & 31;
            Xs[m * 33 + kk] = X[(m0 + m) * ldx + k0 + kk];
        }
#pragma unroll
        for (int i = 0; i < 16; i++) {
            int e = tid + 256 * i;
            int kk = e >> 7, n = e & 127;
            Ws0[kk * 128 + n] = W0[(k0 + kk) * NH + n];
            Ws1[kk * 128 + n] = W1[(k0 + kk) * NH + n];
        }
        __syncthreads();
#pragma unroll 4
        for (int kk = 0; kk < 32; kk++) {
            float xv[8], w0[4], w1[4];
#pragma unroll
            for (int p = 0; p < 8; p++) xv[p] = Xs[(trow + 8 * p) * 33 + kk];
#pragma unroll
            for (int q = 0; q < 4; q++) { w0[q] = Ws0[kk * 128 + tcol + 32 * q]; w1[q] = Ws1[kk * 128 + tcol + 32 * q]; }
#pragma unroll
            for (int p = 0; p < 8; p++)
#pragma unroll
                for (int q = 0; q < 4; q++) { a0[p][q] += xv[p] * w0[q]; a1[p][q] += xv[p] * w1[q]; }
        }
        __syncthreads();
    }
#pragma unroll
    for (int p = 0; p < 8; p++) {
        int m = m0 + trow + 8 * p;
#pragma unroll
        for (int q = 0; q < 4; q++) {
            int n = tcol + 32 * q;
            out0[m * NH + n] = a0[p][q] + b0v[n];
            out1[m * NH + n] = a1[p][q] + b1v[n];
        }
    }
}

// ---------------- main kernel: 20 SGD steps, warp-per-8-rows, exact fp32 ----------------
// SMEM floats: sE1y 4096 | sW2 16384 | sP 4096 | sE3T 512 | sT2 512 | sb2 128 | st2b 8 | scr 8*1024
#define SMEM_FLOATS (4096 + 16384 + 4096 + 512 + 512 + 128 + 8 + 8 * 1024)
#define SMEM_BYTES  (SMEM_FLOATS * 4)

__global__ __launch_bounds__(256, 1)
void edi_main_kernel(const int* __restrict__ t,
                     const float* __restrict__ e_w1,
                     const float* __restrict__ e_w2,
                     const float* __restrict__ e_b2,
                     const float* __restrict__ e_w3,
                     const float* __restrict__ tr2w,
                     const float* __restrict__ tr2b,
                     const int* __restrict__ steps_p,
                     float* __restrict__ out) {
    extern __shared__ float sm[];
    float* sE1y = sm;
    float* sW2  = sE1y + 4096;
    float* sP   = sW2 + 16384;
    float* sE3T = sP + 4096;      // transposed: [k][j]
    float* sT2  = sE3T + 512;
    float* sb2  = sT2 + 512;
    float* st2b = sb2 + 128;
    float* sscr = st2b + 8;

    int tid = threadIdx.x;
    // XOR-swizzled weight layouts: row-read and col-read both conflict-free.
    for (int idx = tid; idx < 32 * 128; idx += 256) {
        int d = idx >> 7, k = idx & 127;
        int swi = d * 128 + (k & 96) + ((k & 31) ^ d);
        sE1y[swi] = e_w1[(NDX + d) * NH + k];
        sP[swi]   = g_P[idx];
    }
    for (int idx = tid; idx < 128 * 128; idx += 256) {
        int j = idx >> 7, k = idx & 127;
        int swi = j * 128 + (k & 96) + ((k & 31) ^ (j & 31));
        sW2[swi]  = e_w2[idx];
    }
    for (int idx = tid; idx < 512; idx += 256) {
        sE3T[(idx & 3) * 128 + (idx >> 2)] = e_w3[idx];
        sT2[idx] = tr2w[idx];
    }
    if (tid < 128) sb2[tid] = e_b2[tid];
    if (tid < 4)   st2b[tid] = tr2b[tid];
    __syncthreads();

    const int lane = tid & 31;
    const int warp = tid >> 5;
    float* scr = sscr + warp * 1024;
    const int r0 = (blockIdx.x * 8 + warp) * 8;    // 8 rows per warp
    const int nsteps = *steps_p;

    int tci[8]; float svf[8];
#pragma unroll
    for (int r = 0; r < 8; r++) {
        int tv = t[r0 + r];
        tci[r] = tv > 0 ? tv : 0;
        svf[r] = tv >= 0 ? C_SW : 0.0f;
    }

    u64 y[4] = {0ull, 0ull, 0ull, 0ull};           // pairs (rows 2p, 2p+1); lane d owns y[d]
    u64 hxe[4][4], cc[4][4];                       // [m][pair]
#pragma unroll
    for (int m = 0; m < 4; m++)
#pragma unroll
        for (int p = 0; p < 4; p++) {
            int col = 32 * m + lane;
            hxe[m][p] = pk2(g_hxe[(r0 + 2 * p) * NH + col], g_hxe[(r0 + 2 * p + 1) * NH + col]);
            cc[m][p]  = pk2(g_c[(r0 + 2 * p) * NH + col],   g_c[(r0 + 2 * p + 1) * NH + col]);
        }

    for (int s = 0; s < nsteps; s++) {
        __syncwarp();
        st8(scr, lane, y[0], y[1], y[2], y[3]);    // y[d] broadcast table, d = lane
        __syncwarp();

        // ---- fused fwd: h1pre = hxe + y@E1y ; u = cc + y@P ----
        u64 A[4][4], U[4][4];
#pragma unroll
        for (int m = 0; m < 4; m++)
#pragma unroll
            for (int p = 0; p < 4; p++) { A[m][p] = hxe[m][p]; U[m][p] = cc[m][p]; }
#pragma unroll 4
        for (int d = 0; d < 32; d++) {
            u64 b0, b1, b2, b3; ld8(scr, d, b0, b1, b2, b3);
            int base = d * 128 + (lane ^ d);
#pragma unroll
            for (int m = 0; m < 4; m++) {
                u64 w = pks(sE1y[base + 32 * m]);
                A[m][0] = ffma2(b0, w, A[m][0]); A[m][1] = ffma2(b1, w, A[m][1]);
                A[m][2] = ffma2(b2, w, A[m][2]); A[m][3] = ffma2(b3, w, A[m][3]);
                u64 v = pks(sP[base + 32 * m]);
                U[m][0] = ffma2(b0, v, U[m][0]); U[m][1] = ffma2(b1, v, U[m][1]);
                U[m][2] = ffma2(b2, v, U[m][2]); U[m][3] = ffma2(b3, v, U[m][3]);
            }
        }
        // relu(h1) + sign mask
        unsigned m1 = 0;
#pragma unroll
        for (int m = 0; m < 4; m++)
#pragma unroll
            for (int p = 0; p < 4; p++) {
                float x, z; up2(A[m][p], x, z);
                m1 |= (x > 0.f ? 1u : 0u) << (m * 8 + 2 * p);
                m1 |= (z > 0.f ? 1u : 0u) << (m * 8 + 2 * p + 1);
                A[m][p] = pk2(fmaxf(x, 0.f), fmaxf(z, 0.f));
            }
        __syncwarp();
#pragma unroll
        for (int m = 0; m < 4; m++) st8(scr, lane + 32 * m, A[m][0], A[m][1], A[m][2], A[m][3]);
        __syncwarp();

        // ---- W2 fwd (exact fp32): only the relu mask of h2 is needed ----
        unsigned m2 = 0;
        {
            u64 B[4][4];
#pragma unroll
            for (int m = 0; m < 4; m++) {
                float bb = sb2[32 * m + lane];
#pragma unroll
                for (int p = 0; p < 4; p++) B[m][p] = pks(bb);
            }
#pragma unroll 4
            for (int j = 0; j < 128; j++) {
                u64 b0, b1, b2, b3; ld8(scr, j, b0, b1, b2, b3);
                int base = j * 128 + (lane ^ (j & 31));
#pragma unroll
                for (int m = 0; m < 4; m++) {
                    u64 w = pks(sW2[base + 32 * m]);
                    B[m][0] = ffma2(b0, w, B[m][0]); B[m][1] = ffma2(b1, w, B[m][1]);
                    B[m][2] = ffma2(b2, w, B[m][2]); B[m][3] = ffma2(b3, w, B[m][3]);
                }
            }
#pragma unroll
            for (int m = 0; m < 4; m++)
#pragma unroll
                for (int p = 0; p < 4; p++) {
                    float x, z; up2(B[m][p], x, z);
                    m2 |= (x > 0.f ? 1u : 0u) << (m * 8 + 2 * p);
                    m2 |= (z > 0.f ? 1u : 0u) << (m * 8 + 2 * p + 1);
                }
        }

        // ---- logits partials, warp reduction, softmax -> dlogits ----
        u64 lg[4][4];
#pragma unroll
        for (int k = 0; k < 4; k++)
#pragma unroll
            for (int p = 0; p < 4; p++) lg[k][p] = 0ull;
#pragma unroll
        for (int m = 0; m < 4; m++) {
            float4 t2 = *reinterpret_cast<const float4*>(&sT2[(lane + 32 * m) * 4]);
#pragma unroll
            for (int p = 0; p < 4; p++) {
                float ux, uz; up2(U[m][p], ux, uz);
                float ax = ux * __fdividef(1.f, 1.f + __expf(-ux));
                float az = uz * __fdividef(1.f, 1.f + __expf(-uz));
                u64 a2 = pk2(ax, az);
                lg[0][p] = ffma2(a2, pks(t2.x), lg[0][p]);
                lg[1][p] = ffma2(a2, pks(t2.y), lg[1][p]);
                lg[2][p] = ffma2(a2, pks(t2.z), lg[2][p]);
                lg[3][p] = ffma2(a2, pks(t2.w), lg[3][p]);
            }
        }
#pragma unroll
        for (int off = 16; off > 0; off >>= 1)
#pragma unroll
            for (int k = 0; k < 4; k++)
#pragma unroll
                for (int p = 0; p < 4; p++)
                    lg[k][p] = fadd2(lg[k][p], __shfl_xor_sync(0xffffffffu, lg[k][p], off));

        u64 dl[4][4];
#pragma unroll
        for (int p = 0; p < 4; p++) {
            float l0[4], l1[4];
#pragma unroll
            for (int k = 0; k < 4; k++) {
                float x, z; up2(lg[k][p], x, z);
                l0[k] = x + st2b[k]; l1[k] = z + st2b[k];
            }
            float dlo[4], dhi[4];
            {
                float mx = fmaxf(fmaxf(l0[0], l0[1]), fmaxf(l0[2], l0[3]));
                float e0 = __expf(l0[0] - mx), e1 = __expf(l0[1] - mx);
                float e2 = __expf(l0[2] - mx), e3 = __expf(l0[3] - mx);
                float sw = svf[2 * p]; int tc = tci[2 * p];
                float inv = sw * __fdividef(1.f, e0 + e1 + e2 + e3);
                dlo[0] = e0 * inv - (tc == 0 ? sw : 0.f);
                dlo[1] = e1 * inv - (tc == 1 ? sw : 0.f);
                dlo[2] = e2 * inv - (tc == 2 ? sw : 0.f);
                dlo[3] = e3 * inv - (tc == 3 ? sw : 0.f);
            }
            {
                float mx = fmaxf(fmaxf(l1[0], l1[1]), fmaxf(l1[2], l1[3]));
                float e0 = __expf(l1[0] - mx), e1 = __expf(l1[1] - mx);
                float e2 = __expf(l1[2] - mx), e3 = __expf(l1[3] - mx);
                float sw = svf[2 * p + 1]; int tc = tci[2 * p + 1];
                float inv = sw * __fdividef(1.f, e0 + e1 + e2 + e3);
                dhi[0] = e0 * inv - (tc == 0 ? sw : 0.f);
                dhi[1] = e1 * inv - (tc == 1 ? sw : 0.f);
                dhi[2] = e2 * inv - (tc == 2 ? sw : 0.f);
                dhi[3] = e3 * inv - (tc == 3 ? sw : 0.f);
            }
#pragma unroll
            for (int k = 0; k < 4; k++) dl[k][p] = pk2(dlo[k], dhi[k]);
        }

        // ---- du = (tr2w @ dl) * silu'(u), store ----
        __syncwarp();
#pragma unroll
        for (int m = 0; m < 4; m++) {
            int jj = lane + 32 * m;
            float4 t2 = *reinterpret_cast<const float4*>(&sT2[jj * 4]);
            u64 dv[4];
#pragma unroll
            for (int p = 0; p < 4; p++) {
                u64 da = fmul2(dl[0][p], pks(t2.x));
                da = ffma2(dl[1][p], pks(t2.y), da);
                da = ffma2(dl[2][p], pks(t2.z), da);
                da = ffma2(dl[3][p], pks(t2.w), da);
                float ux, uz; up2(U[m][p], ux, uz);
                float sgx = __fdividef(1.f, 1.f + __expf(-ux));
                float sgz = __fdividef(1.f, 1.f + __expf(-uz));
                float dsx = sgx * (1.f + ux * (1.f - sgx));
                float dsz = sgz * (1.f + uz * (1.f - sgz));
                dv[p] = fmul2(da, pk2(dsx, dsz));
            }
            st8(scr, jj, dv[0], dv[1], dv[2], dv[3]);
        }
        __syncwarp();

        // ---- folded transition bwd: gy = 2*REG*y + P[lane,:] . du ----
        u64 gy[4];
#pragma unroll
        for (int p = 0; p < 4; p++) gy[p] = fmul2(pks(2.f * C_REG), y[p]);
#pragma unroll 4
        for (int k = 0; k < 128; k++) {
            u64 b0, b1, b2, b3; ld8(scr, k, b0, b1, b2, b3);
            u64 w = pks(sP[lane * 128 + (k & 96) + ((k & 31) ^ lane)]);
            gy[0] = ffma2(b0, w, gy[0]); gy[1] = ffma2(b1, w, gy[1]);
            gy[2] = ffma2(b2, w, gy[2]); gy[3] = ffma2(b3, w, gy[3]);
        }

        // ---- energy bwd: dh2pre = (h2>0) * e_w3[:, tci] ----
        __syncwarp();
#pragma unroll
        for (int m = 0; m < 4; m++) {
            int jj = lane + 32 * m;
            u64 dv[4];
#pragma unroll
            for (int p = 0; p < 4; p++) {
                float e0 = ((m2 >> (m * 8 + 2 * p)) & 1)     ? sE3T[tci[2 * p] * 128 + jj]     : 0.f;
                float e1 = ((m2 >> (m * 8 + 2 * p + 1)) & 1) ? sE3T[tci[2 * p + 1] * 128 + jj] : 0.f;
                dv[p] = pk2(e0, e1);
            }
            st8(scr, jj, dv[0], dv[1], dv[2], dv[3]);
        }
        __syncwarp();

        // ---- W2 bwd: dh1 (masked by h1>0) ----
        u64 D[4][4];
#pragma unroll
        for (int m = 0; m < 4; m++)
#pragma unroll
            for (int p = 0; p < 4; p++) D[m][p] = 0ull;
#pragma unroll 4
        for (int k = 0; k < 128; k++) {
            u64 b0, b1, b2, b3; ld8(scr, k, b0, b1, b2, b3);
            int off = (k & 96) + ((k & 31) ^ lane);
#pragma unroll
            for (int m = 0; m < 4; m++) {
                u64 w = pks(sW2[(lane + 32 * m) * 128 + off]);
                D[m][0] = ffma2(b0, w, D[m][0]); D[m][1] = ffma2(b1, w, D[m][1]);
                D[m][2] = ffma2(b2, w, D[m][2]); D[m][3] = ffma2(b3, w, D[m][3]);
            }
        }
#pragma unroll
        for (int m = 0; m < 4; m++)
#pragma unroll
            for (int p = 0; p < 4; p++) {
                float x, z; up2(D[m][p], x, z);
                x = ((m1 >> (m * 8 + 2 * p)) & 1)     ? x : 0.f;
                z = ((m1 >> (m * 8 + 2 * p + 1)) & 1) ? z : 0.f;
                D[m][p] = pk2(x, z);
            }
        __syncwarp();
#pragma unroll
        for (int m = 0; m < 4; m++) st8(scr, lane + 32 * m, D[m][0], D[m][1], D[m][2], D[m][3]);
        __syncwarp();

        // ---- gy += E1y[lane,:] . dh1pre ----
#pragma unroll 4
        for (int j = 0; j < 128; j++) {
            u64 b0, b1, b2, b3; ld8(scr, j, b0, b1, b2, b3);
            u64 w = pks(sE1y[lane * 128 + (j & 96) + ((j & 31) ^ lane)]);
            gy[0] = ffma2(b0, w, gy[0]); gy[1] = ffma2(b1, w, gy[1]);
            gy[2] = ffma2(b2, w, gy[2]); gy[3] = ffma2(b3, w, gy[3]);
        }

        // ---- SGD update ----
#pragma unroll
        for (int p = 0; p < 4; p++) y[p] = ffma2(gy[p], pks(-C_LR), y[p]);
    }

#pragma unroll
    for (int p = 0; p < 4; p++) {
        float a, b; up2(y[p], a, b);
        out[(r0 + 2 * p) * NDY + lane] = a;
        out[(r0 + 2 * p + 1) * NDY + lane] = b;
    }
}

// ---------------- launcher ----------------
extern "C" void kernel_launch(void* const* d_in, const int* in_sizes, int n_in,
                              void* d_out, int out_size) {
    const float* x      = (const float*)d_in[0];
    const int*   t      = (const int*)d_in[1];
    const float* e_w1   = (const float*)d_in[2];
    const float* e_b1   = (const float*)d_in[3];
    const float* e_w2   = (const float*)d_in[4];
    const float* e_b2   = (const float*)d_in[5];
    const float* e_w3   = (const float*)d_in[6];
    const float* s_xw   = (const float*)d_in[8];
    const float* s_xb   = (const float*)d_in[9];
    const float* s_yw   = (const float*)d_in[10];
    const float* s_yb   = (const float*)d_in[11];
    const float* s_temb = (const float*)d_in[12];
    const float* s_t1w  = (const float*)d_in[13];
    const float* s_t1b  = (const float*)d_in[14];
    const float* s_t2w  = (const float*)d_in[15];
    const float* s_t2b  = (const float*)d_in[16];
    const float* tr1w   = (const float*)d_in[17];
    const float* tr1b   = (const float*)d_in[18];
    const float* tr2w   = (const float*)d_in[19];
    const float* tr2b   = (const float*)d_in[20];
    const int*   steps  = (const int*)d_in[21];
    float* out = (float*)d_out;

    float *p_hxe, *p_hxs, *p_c, *p_cth;
    cudaGetSymbolAddress((void**)&p_hxe, g_hxe);
    cudaGetSymbolAddress((void**)&p_hxs, g_hxs);
    cudaGetSymbolAddress((void**)&p_c,   g_c);
    cudaGetSymbolAddress((void**)&p_cth, g_cth);

    // 1) per-class constants, then fold Syw@T1y (and s_yb@T1y into cth)
    cth_kernel<<<1, NH>>>(s_temb, s_t1w, s_t1b, s_t2w, s_t2b, tr1w, tr1b);
    p_kernel<<<NDY, NH>>>(s_yw, s_yb, tr1w);

    // 2) per-row constants: hx_e + hx_s fused (x read once), then c
    gemm128_dual_kernel<<<NB / 64, 256>>>(x, NDX, NDX, e_w1, e_b1, s_xw, s_xb, p_hxe, p_hxs);
    gemm128_kernel<<<NB / 64, 256>>>(p_hxs, NH, NH, tr1w, nullptr, p_cth, t, p_c);

    // 3) 20 SGD steps, warp-per-8-rows, folded transition, exact fp32 f32x2
    cudaFuncSetAttribute(edi_main_kernel, cudaFuncAttributeMaxDynamicSharedMemorySize, SMEM_BYTES);
    edi_main_kernel<<<NB / 64, 256, SMEM_BYTES>>>(t, e_w1, e_w2, e_b2, e_w3,
                                                  tr2w, tr2b, steps, out);
}

// round 11
// speedup vs baseline: 2.4888x; 1.0006x over previous
#include <cuda_runtime.h>

typedef unsigned long long u64;

#define NB   131072
#define NDX  256
#define NDY  32
#define NK   4
#define NH   128
#define C_LR  0.1f
#define C_REG 0.01f
#define C_SW  1.0f

// ---------------- scratch (device globals: no allocation allowed) ----------------
__device__ float g_hxe[NB * NH];   // x @ e_w1[:DX] + e_b1
__device__ float g_hxs[NB * NH];   // x @ s_xw + s_xb
__device__ float g_c[NB * NH];     // static part of transition pre-activation
__device__ float g_cth[NK * NH];   // per-class constant (incl. s_yb@T1y fold)
__device__ float g_P[NDY * NH];    // Syw @ T1y  (32 x 128) -- folded transition matrix

// ---------------- packed f32x2 helpers ----------------
__device__ __forceinline__ u64 pk2(float x, float y) {
    u64 r; asm("mov.b64 %0, {%1,%2};" : "=l"(r) : "f"(x), "f"(y)); return r;
}
__device__ __forceinline__ u64 pks(float x) {
    u64 r; asm("mov.b64 %0, {%1,%1};" : "=l"(r) : "f"(x)); return r;
}
__device__ __forceinline__ void up2(u64 v, float& x, float& y) {
    asm("mov.b64 {%0,%1}, %2;" : "=f"(x), "=f"(y) : "l"(v));
}
__device__ __forceinline__ u64 ffma2(u64 a, u64 b, u64 c) {
    u64 d; asm("fma.rn.f32x2 %0, %1, %2, %3;" : "=l"(d) : "l"(a), "l"(b), "l"(c)); return d;
}
__device__ __forceinline__ u64 fmul2(u64 a, u64 b) {
    u64 d; asm("mul.rn.f32x2 %0, %1, %2;" : "=l"(d) : "l"(a), "l"(b)); return d;
}
__device__ __forceinline__ u64 fadd2(u64 a, u64 b) {
    u64 d; asm("add.rn.f32x2 %0, %1, %2;" : "=l"(d) : "l"(a), "l"(b)); return d;
}

// Per-warp activation scratch: two regions of 512 floats (float4 per j).
__device__ __forceinline__ void st8(float* scr, int j, u64 v0, u64 v1, u64 v2, u64 v3) {
    *reinterpret_cast<ulonglong2*>(scr + j * 4)       = make_ulonglong2(v0, v1);
    *reinterpret_cast<ulonglong2*>(scr + 512 + j * 4) = make_ulonglong2(v2, v3);
}
__device__ __forceinline__ void ld8(const float* scr, int j, u64& v0, u64& v1, u64& v2, u64& v3) {
    ulonglong2 a = *reinterpret_cast<const ulonglong2*>(scr + j * 4);
    ulonglong2 b = *reinterpret_cast<const ulonglong2*>(scr + 512 + j * 4);
    v0 = a.x; v1 = a.y; v2 = b.x; v3 = b.y;
}

// ---------------- kernel B: per-class constants ----------------
__global__ void cth_kernel(const float* __restrict__ s_temb,
                           const float* __restrict__ s_t1w,
                           const float* __restrict__ s_t1b,
                           const float* __restrict__ s_t2w,
                           const float* __restrict__ s_t2b,
                           const float* __restrict__ tr1w,
                           const float* __restrict__ tr1b) {
    int j = threadIdx.x;                 // 0..127
    __shared__ float v[NH], th[NH];
    for (int k = 0; k < NK; k++) {
        float tau = fmaxf((float)k / 1000.0f, 1e-6f);
        float z = tau * s_t1w[j] + s_t1b[j];
        float sg = 1.0f / (1.0f + expf(-z));
        v[j] = z * sg;
        __syncthreads();
        float acc = s_t2b[j];
        for (int q = 0; q < NH; q++) acc += v[q] * s_t2w[q * NH + j];
        th[j] = acc;
        __syncthreads();
        float c = tr1b[j];
        for (int q = 0; q < NH; q++) {
            c += s_temb[k * NH + q] * tr1w[(2 * NH + q) * NH + j];
            c += th[q] * tr1w[(3 * NH + q) * NH + j];
        }
        g_cth[k * NH + j] = c;
        __syncthreads();
    }
}

// ---------------- kernel P: fold Syw@T1y and s_yb@T1y ----------------
__global__ void p_kernel(const float* __restrict__ s_yw,
                         const float* __restrict__ s_yb,
                         const float* __restrict__ tr1w) {
    int k = threadIdx.x;
    int d = blockIdx.x;
    float acc = 0.0f;
    for (int j = 0; j < NH; j++)
        acc += s_yw[d * NH + j] * tr1w[(NH + j) * NH + k];
    g_P[d * NH + k] = acc;
    if (d == 0) {
        float bp = 0.0f;
        for (int j = 0; j < NH; j++)
            bp += s_yb[j] * tr1w[(NH + j) * NH + k];
        for (int c = 0; c < NK; c++) g_cth[c * NH + k] += bp;
    }
}

// ---------------- kernel A: tiled FP32 GEMM, N fixed at 128 ----------------
__global__ __launch_bounds__(256)
void gemm128_kernel(const float* __restrict__ X, int ldx, int Kdim,
                    const float* __restrict__ Wm,
                    const float* __restrict__ bias,
                    const float* __restrict__ table,
                    const int* __restrict__ tt,
                    float* __restrict__ out) {
    __shared__ float Xs[64 * 33];
    __shared__ float Ws[32 * 128];
    int tid = threadIdx.x;
    int tcol = tid & 31;
    int trow = tid >> 5;
    int m0 = blockIdx.x * 64;

    float acc[8][4];
#pragma unroll
    for (int p = 0; p < 8; p++)
#pragma unroll
        for (int q = 0; q < 4; q++) acc[p][q] = 0.0f;

    for (int k0 = 0; k0 < Kdim; k0 += 32) {
#pragma unroll
        for (int i = 0; i < 8; i++) {
            int e = tid + 256 * i;
            int m = e >> 5, kk = e & 31;
            Xs[m * 33 + kk] = X[(m0 + m) * ldx + k0 + kk];
        }
#pragma unroll
        for (int i = 0; i < 16; i++) {
            int e = tid + 256 * i;
            int kk = e >> 7, n = e & 127;
            Ws[kk * 128 + n] = Wm[(k0 + kk) * NH + n];
        }
        __syncthreads();
#pragma unroll 8
        for (int kk = 0; kk < 32; kk++) {
            float xv[8], wv[4];
#pragma unroll
            for (int p = 0; p < 8; p++) xv[p] = Xs[(trow + 8 * p) * 33 + kk];
#pragma unroll
            for (int q = 0; q < 4; q++) wv[q] = Ws[kk * 128 + tcol + 32 * q];
#pragma unroll
            for (int p = 0; p < 8; p++)
#pragma unroll
                for (int q = 0; q < 4; q++) acc[p][q] += xv[p] * wv[q];
        }
        __syncthreads();
    }
#pragma unroll
    for (int p = 0; p < 8; p++) {
        int m = m0 + trow + 8 * p;
        int tc = 0;
        if (table) { int tv = tt[m]; tc = tv > 0 ? tv : 0; }
#pragma unroll
        for (int q = 0; q < 4; q++) {
            int n = tcol + 32 * q;
            float vv = acc[p][q];
            if (bias)  vv += bias[n];
            if (table) vv += table[tc * NH + n];
            out[m * NH + n] = vv;
        }
    }
}

// ---------------- kernel A2: dual-output GEMM (shares X tiles) ----------------
__global__ __launch_bounds__(256)
void gemm128_dual_kernel(const float* __restrict__ X, int ldx, int Kdim,
                         const float* __restrict__ W0, const float* __restrict__ b0v,
                         const float* __restrict__ W1, const float* __restrict__ b1v,
                         float* __restrict__ out0, float* __restrict__ out1) {
    __shared__ float Xs[64 * 33];
    __shared__ float Ws0[32 * 128];
    __shared__ float Ws1[32 * 128];
    int tid = threadIdx.x;
    int tcol = tid & 31;
    int trow = tid >> 5;
    int m0 = blockIdx.x * 64;

    float a0[8][4], a1[8][4];
#pragma unroll
    for (int p = 0; p < 8; p++)
#pragma unroll
        for (int q = 0; q < 4; q++) { a0[p][q] = 0.0f; a1[p][q] = 0.0f; }

    for (int k0 = 0; k0 < Kdim; k0 += 32) {
#pragma unroll
        for (int i = 0; i < 8; i++) {
            int e = tid + 256 * i;
            int m = e >> 5, kk = e & 31;
            Xs[m * 33 + kk] = X[(m0 + m) * ldx + k0 + kk];
        }
#pragma unroll
        for (int i = 0; i < 16; i++) {
            int e = tid + 256 * i;
            int kk = e >> 7, n = e & 127;
            Ws0[kk * 128 + n] = W0[(k0 + kk) * NH + n];
            Ws1[kk * 128 + n] = W1[(k0 + kk) * NH + n];
        }
        __syncthreads();
#pragma unroll 4
        for (int kk = 0; kk < 32; kk++) {
            float xv[8], w0[4], w1[4];
#pragma unroll
            for (int p = 0; p < 8; p++) xv[p] = Xs[(trow + 8 * p) * 33 + kk];
#pragma unroll
            for (int q = 0; q < 4; q++) { w0[q] = Ws0[kk * 128 + tcol + 32 * q]; w1[q] = Ws1[kk * 128 + tcol + 32 * q]; }
#pragma unroll
            for (int p = 0; p < 8; p++)
#pragma unroll
                for (int q = 0; q < 4; q++) { a0[p][q] += xv[p] * w0[q]; a1[p][q] += xv[p] * w1[q]; }
        }
        __syncthreads();
    }
#pragma unroll
    for (int p = 0; p < 8; p++) {
        int m = m0 + trow + 8 * p;
#pragma unroll
        for (int q = 0; q < 4; q++) {
            int n = tcol + 32 * q;
            out0[m * NH + n] = a0[p][q] + b0v[n];
            out1[m * NH + n] = a1[p][q] + b1v[n];
        }
    }
}

// ---------------- main kernel: 20 SGD steps, warp-per-8-rows, exact fp32 ----------------
// SMEM floats: sE1y 4096 | sW2 16384 | sP 4096 | sE3T 512 | sT2 512 | sb2 128 | st2b 8 | scr 8*1024
#define SMEM_FLOATS (4096 + 16384 + 4096 + 512 + 512 + 128 + 8 + 8 * 1024)
#define SMEM_BYTES  (SMEM_FLOATS * 4)

__global__ __launch_bounds__(256, 1)
void edi_main_kernel(const int* __restrict__ t,
                     const float* __restrict__ e_w1,
                     const float* __restrict__ e_w2,
                     const float* __restrict__ e_b2,
                     const float* __restrict__ e_w3,
                     const float* __restrict__ tr2w,
                     const float* __restrict__ tr2b,
                     const int* __restrict__ steps_p,
                     float* __restrict__ out) {
    extern __shared__ float sm[];
    float* sE1y = sm;
    float* sW2  = sE1y + 4096;
    float* sP   = sW2 + 16384;
    float* sE3T = sP + 4096;      // transposed: [k][j]
    float* sT2  = sE3T + 512;
    float* sb2  = sT2 + 512;
    float* st2b = sb2 + 128;
    float* sscr = st2b + 8;

    int tid = threadIdx.x;
    // XOR-swizzled weight layouts: row-read and col-read both conflict-free.
    for (int idx = tid; idx < 32 * 128; idx += 256) {
        int d = idx >> 7, k = idx & 127;
        int swi = d * 128 + (k & 96) + ((k & 31) ^ d);
        sE1y[swi] = e_w1[(NDX + d) * NH + k];
        sP[swi]   = g_P[idx];
    }
    for (int idx = tid; idx < 128 * 128; idx += 256) {
        int j = idx >> 7, k = idx & 127;
        int swi = j * 128 + (k & 96) + ((k & 31) ^ (j & 31));
        sW2[swi]  = e_w2[idx];
    }
    for (int idx = tid; idx < 512; idx += 256) {
        sE3T[(idx & 3) * 128 + (idx >> 2)] = e_w3[idx];
        sT2[idx] = tr2w[idx];
    }
    if (tid < 128) sb2[tid] = e_b2[tid];
    if (tid < 4)   st2b[tid] = tr2b[tid];
    __syncthreads();

    const int lane = tid & 31;
    const int warp = tid >> 5;
    float* scr = sscr + warp * 1024;
    const int r0 = (blockIdx.x * 8 + warp) * 8;    // 8 rows per warp
    const int nsteps = *steps_p;

    int tci[8]; float svf[8];
#pragma unroll
    for (int r = 0; r < 8; r++) {
        int tv = t[r0 + r];
        tci[r] = tv > 0 ? tv : 0;
        svf[r] = tv >= 0 ? C_SW : 0.0f;
    }

    u64 y[4] = {0ull, 0ull, 0ull, 0ull};           // pairs (rows 2p, 2p+1); lane d owns y[d]
    u64 hxe[4][4], cc[4][4];                       // [m][pair]
#pragma unroll
    for (int m = 0; m < 4; m++)
#pragma unroll
        for (int p = 0; p < 4; p++) {
            int col = 32 * m + lane;
            hxe[m][p] = pk2(g_hxe[(r0 + 2 * p) * NH + col], g_hxe[(r0 + 2 * p + 1) * NH + col]);
            cc[m][p]  = pk2(g_c[(r0 + 2 * p) * NH + col],   g_c[(r0 + 2 * p + 1) * NH + col]);
        }

    for (int s = 0; s < nsteps; s++) {
        __syncwarp();
        st8(scr, lane, y[0], y[1], y[2], y[3]);    // y[d] broadcast table, d = lane
        __syncwarp();

        // ---- fused fwd: h1pre = hxe + y@E1y ; u = cc + y@P ----
        u64 A[4][4], U[4][4];
#pragma unroll
        for (int m = 0; m < 4; m++)
#pragma unroll
            for (int p = 0; p < 4; p++) { A[m][p] = hxe[m][p]; U[m][p] = cc[m][p]; }
#pragma unroll 4
        for (int d = 0; d < 32; d++) {
            u64 b0, b1, b2, b3; ld8(scr, d, b0, b1, b2, b3);
            int base = d * 128 + (lane ^ d);
#pragma unroll
            for (int m = 0; m < 4; m++) {
                u64 w = pks(sE1y[base + 32 * m]);
                A[m][0] = ffma2(b0, w, A[m][0]); A[m][1] = ffma2(b1, w, A[m][1]);
                A[m][2] = ffma2(b2, w, A[m][2]); A[m][3] = ffma2(b3, w, A[m][3]);
                u64 v = pks(sP[base + 32 * m]);
                U[m][0] = ffma2(b0, v, U[m][0]); U[m][1] = ffma2(b1, v, U[m][1]);
                U[m][2] = ffma2(b2, v, U[m][2]); U[m][3] = ffma2(b3, v, U[m][3]);
            }
        }
        // relu(h1) + sign mask
        unsigned m1 = 0;
#pragma unroll
        for (int m = 0; m < 4; m++)
#pragma unroll
            for (int p = 0; p < 4; p++) {
                float x, z; up2(A[m][p], x, z);
                m1 |= (x > 0.f ? 1u : 0u) << (m * 8 + 2 * p);
                m1 |= (z > 0.f ? 1u : 0u) << (m * 8 + 2 * p + 1);
                A[m][p] = pk2(fmaxf(x, 0.f), fmaxf(z, 0.f));
            }
        __syncwarp();
#pragma unroll
        for (int m = 0; m < 4; m++) st8(scr, lane + 32 * m, A[m][0], A[m][1], A[m][2], A[m][3]);
        __syncwarp();

        // ---- W2 fwd (exact fp32): only the relu mask of h2 is needed ----
        unsigned m2 = 0;
        {
            u64 B[4][4];
#pragma unroll
            for (int m = 0; m < 4; m++) {
                float bb = sb2[32 * m + lane];
#pragma unroll
                for (int p = 0; p < 4; p++) B[m][p] = pks(bb);
            }
#pragma unroll 4
            for (int j = 0; j < 128; j++) {
                u64 b0, b1, b2, b3; ld8(scr, j, b0, b1, b2, b3);
                int base = j * 128 + (lane ^ (j & 31));
#pragma unroll
                for (int m = 0; m < 4; m++) {
                    u64 w = pks(sW2[base + 32 * m]);
                    B[m][0] = ffma2(b0, w, B[m][0]); B[m][1] = ffma2(b1, w, B[m][1]);
                    B[m][2] = ffma2(b2, w, B[m][2]); B[m][3] = ffma2(b3, w, B[m][3]);
                }
            }
#pragma unroll
            for (int m = 0; m < 4; m++)
#pragma unroll
                for (int p = 0; p < 4; p++) {
                    float x, z; up2(B[m][p], x, z);
                    m2 |= (x > 0.f ? 1u : 0u) << (m * 8 + 2 * p);
                    m2 |= (z > 0.f ? 1u : 0u) << (m * 8 + 2 * p + 1);
                }
        }

        // ---- logits partials, warp reduction, softmax -> dlogits ----
        u64 lg[4][4];
#pragma unroll
        for (int k = 0; k < 4; k++)
#pragma unroll
            for (int p = 0; p < 4; p++) lg[k][p] = 0ull;
#pragma unroll
        for (int m = 0; m < 4; m++) {
            float4 t2 = *reinterpret_cast<const float4*>(&sT2[(lane + 32 * m) * 4]);
#pragma unroll
            for (int p = 0; p < 4; p++) {
                float ux, uz; up2(U[m][p], ux, uz);
                float ax = ux * __fdividef(1.f, 1.f + __expf(-ux));
                float az = uz * __fdividef(1.f, 1.f + __expf(-uz));
                u64 a2 = pk2(ax, az);
                lg[0][p] = ffma2(a2, pks(t2.x), lg[0][p]);
                lg[1][p] = ffma2(a2, pks(t2.y), lg[1][p]);
                lg[2][p] = ffma2(a2, pks(t2.z), lg[2][p]);
                lg[3][p] = ffma2(a2, pks(t2.w), lg[3][p]);
            }
        }
#pragma unroll
        for (int off = 16; off > 0; off >>= 1)
#pragma unroll
            for (int k = 0; k < 4; k++)
#pragma unroll
                for (int p = 0; p < 4; p++)
                    lg[k][p] = fadd2(lg[k][p], __shfl_xor_sync(0xffffffffu, lg[k][p], off));

        u64 dl[4][4];
#pragma unroll
        for (int p = 0; p < 4; p++) {
            float l0[4], l1[4];
#pragma unroll
            for (int k = 0; k < 4; k++) {
                float x, z; up2(lg[k][p], x, z);
                l0[k] = x + st2b[k]; l1[k] = z + st2b[k];
            }
            float dlo[4], dhi[4];
            {
                float mx = fmaxf(fmaxf(l0[0], l0[1]), fmaxf(l0[2], l0[3]));
                float e0 = __expf(l0[0] - mx), e1 = __expf(l0[1] - mx);
                float e2 = __expf(l0[2] - mx), e3 = __expf(l0[3] - mx);
                float sw = svf[2 * p]; int tc = tci[2 * p];
                float inv = sw * __fdividef(1.f, e0 + e1 + e2 + e3);
                dlo[0] = e0 * inv - (tc == 0 ? sw : 0.f);
                dlo[1] = e1 * inv - (tc == 1 ? sw : 0.f);
                dlo[2] = e2 * inv - (tc == 2 ? sw : 0.f);
                dlo[3] = e3 * inv - (tc == 3 ? sw : 0.f);
            }
            {
                float mx = fmaxf(fmaxf(l1[0], l1[1]), fmaxf(l1[2], l1[3]));
                float e0 = __expf(l1[0] - mx), e1 = __expf(l1[1] - mx);
                float e2 = __expf(l1[2] - mx), e3 = __expf(l1[3] - mx);
                float sw = svf[2 * p + 1]; int tc = tci[2 * p + 1];
                float inv = sw * __fdividef(1.f, e0 + e1 + e2 + e3);
                dhi[0] = e0 * inv - (tc == 0 ? sw : 0.f);
                dhi[1] = e1 * inv - (tc == 1 ? sw : 0.f);
                dhi[2] = e2 * inv - (tc == 2 ? sw : 0.f);
                dhi[3] = e3 * inv - (tc == 3 ? sw : 0.f);
            }
#pragma unroll
            for (int k = 0; k < 4; k++) dl[k][p] = pk2(dlo[k], dhi[k]);
        }

        // ---- du = (tr2w @ dl) * silu'(u), store ----
        __syncwarp();
#pragma unroll
        for (int m = 0; m < 4; m++) {
            int jj = lane + 32 * m;
            float4 t2 = *reinterpret_cast<const float4*>(&sT2[jj * 4]);
            u64 dv[4];
#pragma unroll
            for (int p = 0; p < 4; p++) {
                u64 da = fmul2(dl[0][p], pks(t2.x));
                da = ffma2(dl[1][p], pks(t2.y), da);
                da = ffma2(dl[2][p], pks(t2.z), da);
                da = ffma2(dl[3][p], pks(t2.w), da);
                float ux, uz; up2(U[m][p], ux, uz);
                float sgx = __fdividef(1.f, 1.f + __expf(-ux));
                float sgz = __fdividef(1.f, 1.f + __expf(-uz));
                float dsx = sgx * (1.f + ux * (1.f - sgx));
                float dsz = sgz * (1.f + uz * (1.f - sgz));
                dv[p] = fmul2(da, pk2(dsx, dsz));
            }
            st8(scr, jj, dv[0], dv[1], dv[2], dv[3]);
        }
        __syncwarp();

        // ---- folded transition bwd: gy = 2*REG*y + P[lane,:] . du ----
        u64 gy[4];
#pragma unroll
        for (int p = 0; p < 4; p++) gy[p] = fmul2(pks(2.f * C_REG), y[p]);
#pragma unroll 4
        for (int k = 0; k < 128; k++) {
            u64 b0, b1, b2, b3; ld8(scr, k, b0, b1, b2, b3);
            u64 w = pks(sP[lane * 128 + (k & 96) + ((k & 31) ^ lane)]);
            gy[0] = ffma2(b0, w, gy[0]); gy[1] = ffma2(b1, w, gy[1]);
            gy[2] = ffma2(b2, w, gy[2]); gy[3] = ffma2(b3, w, gy[3]);
        }

        // ---- energy bwd: dh2pre = (h2>0) * e_w3[:, tci] ----
        __syncwarp();
#pragma unroll
        for (int m = 0; m < 4; m++) {
            int jj = lane + 32 * m;
            u64 dv[4];
#pragma unroll
            for (int p = 0; p < 4; p++) {
                float e0 = ((m2 >> (m * 8 + 2 * p)) & 1)     ? sE3T[tci[2 * p] * 128 + jj]     : 0.f;
                float e1 = ((m2 >> (m * 8 + 2 * p + 1)) & 1) ? sE3T[tci[2 * p + 1] * 128 + jj] : 0.f;
                dv[p] = pk2(e0, e1);
            }
            st8(scr, jj, dv[0], dv[1], dv[2], dv[3]);
        }
        __syncwarp();

        // ---- W2 bwd: dh1 (masked by h1>0) ----
        u64 D[4][4];
#pragma unroll
        for (int m = 0; m < 4; m++)
#pragma unroll
            for (int p = 0; p < 4; p++) D[m][p] = 0ull;
#pragma unroll 4
        for (int k = 0; k < 128; k++) {
            u64 b0, b1, b2, b3; ld8(scr, k, b0, b1, b2, b3);
            int off = (k & 96) + ((k & 31) ^ lane);
#pragma unroll
            for (int m = 0; m < 4; m++) {
                u64 w = pks(sW2[(lane + 32 * m) * 128 + off]);
                D[m][0] = ffma2(b0, w, D[m][0]); D[m][1] = ffma2(b1, w, D[m][1]);
                D[m][2] = ffma2(b2, w, D[m][2]); D[m][3] = ffma2(b3, w, D[m][3]);
            }
        }
#pragma unroll
        for (int m = 0; m < 4; m++)
#pragma unroll
            for (int p = 0; p < 4; p++) {
                float x, z; up2(D[m][p], x, z);
                x = ((m1 >> (m * 8 + 2 * p)) & 1)     ? x : 0.f;
                z = ((m1 >> (m * 8 + 2 * p + 1)) & 1) ? z : 0.f;
                D[m][p] = pk2(x, z);
            }
        __syncwarp();
#pragma unroll
        for (int m = 0; m < 4; m++) st8(scr, lane + 32 * m, D[m][0], D[m][1], D[m][2], D[m][3]);
        __syncwarp();

        // ---- gy += E1y[lane,:] . dh1pre ----
#pragma unroll 4
        for (int j = 0; j < 128; j++) {
            u64 b0, b1, b2, b3; ld8(scr, j, b0, b1, b2, b3);
            u64 w = pks(sE1y[lane * 128 + (j & 96) + ((j & 31) ^ lane)]);
            gy[0] = ffma2(b0, w, gy[0]); gy[1] = ffma2(b1, w, gy[1]);
            gy[2] = ffma2(b2, w, gy[2]); gy[3] = ffma2(b3, w, gy[3]);
        }

        // ---- SGD update ----
#pragma unroll
        for (int p = 0; p < 4; p++) y[p] = ffma2(gy[p], pks(-C_LR), y[p]);
    }

#pragma unroll
    for (int p = 0; p < 4; p++) {
        float a, b; up2(y[p], a, b);
        out[(r0 + 2 * p) * NDY + lane] = a;
        out[(r0 + 2 * p + 1) * NDY + lane] = b;
    }
}

// ---------------- launcher ----------------
extern "C" void kernel_launch(void* const* d_in, const int* in_sizes, int n_in,
                              void* d_out, int out_size) {
    const float* x      = (const float*)d_in[0];
    const int*   t      = (const int*)d_in[1];
    const float* e_w1   = (const float*)d_in[2];
    const float* e_b1   = (const float*)d_in[3];
    const float* e_w2   = (const float*)d_in[4];
    const float* e_b2   = (const float*)d_in[5];
    const float* e_w3   = (const float*)d_in[6];
    const float* s_xw   = (const float*)d_in[8];
    const float* s_xb   = (const float*)d_in[9];
    const float* s_yw   = (const float*)d_in[10];
    const float* s_yb   = (const float*)d_in[11];
    const float* s_temb = (const float*)d_in[12];
    const float* s_t1w  = (const float*)d_in[13];
    const float* s_t1b  = (const float*)d_in[14];
    const float* s_t2w  = (const float*)d_in[15];
    const float* s_t2b  = (const float*)d_in[16];
    const float* tr1w   = (const float*)d_in[17];
    const float* tr1b   = (const float*)d_in[18];
    const float* tr2w   = (const float*)d_in[19];
    const float* tr2b   = (const float*)d_in[20];
    const int*   steps  = (const int*)d_in[21];
    float* out = (float*)d_out;

    float *p_hxe, *p_hxs, *p_c, *p_cth;
    cudaGetSymbolAddress((void**)&p_hxe, g_hxe);
    cudaGetSymbolAddress((void**)&p_hxs, g_hxs);
    cudaGetSymbolAddress((void**)&p_c,   g_c);
    cudaGetSymbolAddress((void**)&p_cth, g_cth);

    // 1) per-class constants, then fold Syw@T1y (and s_yb@T1y into cth)
    cth_kernel<<<1, NH>>>(s_temb, s_t1w, s_t1b, s_t2w, s_t2b, tr1w, tr1b);
    p_kernel<<<NDY, NH>>>(s_yw, s_yb, tr1w);

    // 2) per-row constants: hx_e + hx_s fused (x read once), then c
    gemm128_dual_kernel<<<NB / 64, 256>>>(x, NDX, NDX, e_w1, e_b1, s_xw, s_xb, p_hxe, p_hxs);
    gemm128_kernel<<<NB / 64, 256>>>(p_hxs, NH, NH, tr1w, nullptr, p_cth, t, p_c);

    // 3) 20 SGD steps, warp-per-8-rows, folded transition, exact fp32 f32x2
    cudaFuncSetAttribute(edi_main_kernel, cudaFuncAttributeMaxDynamicSharedMemorySize, SMEM_BYTES);
    edi_main_kernel<<<NB / 64, 256, SMEM_BYTES>>>(t, e_w1, e_w2, e_b2, e_w3,
                                                  tr2w, tr2b, steps, out);
}

// round 12
// speedup vs baseline: 2.5137x; 1.0100x over previous
#include <cuda_runtime.h>
#include <cuda_fp16.h>
typedef unsigned long long u64;
typedef unsigned int u32;

#define NB   131072
#define NDX  256
#define NDY  32
#define NK   4
#define NH   128
#define C_LR  0.1f
#define C_REG 0.01f
#define C_SW  1.0f

__device__ float g_hxe[NB * NH];
__device__ float g_hxs[NB * NH];
__device__ float g_c[NB * NH];
__device__ float g_cth[NK * NH];
__device__ float g_P[NDY * NH];

__device__ __forceinline__ u64 pk2(float x, float y) {
    u64 r; asm("mov.b64 %0, {%1,%2};" : "=l"(r) : "f"(x), "f"(y)); return r;
}
__device__ __forceinline__ u64 pks(float x) {
    u64 r; asm("mov.b64 %0, {%1,%1};" : "=l"(r) : "f"(x)); return r;
}
__device__ __forceinline__ void up2(u64 v, float& x, float& y) {
    asm("mov.b64 {%0,%1}, %2;" : "=f"(x), "=f"(y) : "l"(v));
}
__device__ __forceinline__ u64 ffma2(u64 a, u64 b, u64 c) {
    u64 d; asm("fma.rn.f32x2 %0, %1, %2, %3;" : "=l"(d) : "l"(a), "l"(b), "l"(c)); return d;
}
__device__ __forceinline__ u64 fmul2(u64 a, u64 b) {
    u64 d; asm("mul.rn.f32x2 %0, %1, %2;" : "=l"(d) : "l"(a), "l"(b)); return d;
}
__device__ __forceinline__ u64 fadd2(u64 a, u64 b) {
    u64 d; asm("add.rn.f32x2 %0, %1, %2;" : "=l"(d) : "l"(a), "l"(b)); return d;
}
__device__ __forceinline__ u32 smemu(const void* p) {
    return (u32)__cvta_generic_to_shared(p);
}
__device__ __forceinline__ void ldsm4(u32 a, u32& r0, u32& r1, u32& r2, u32& r3) {
    asm volatile("ldmatrix.sync.aligned.m8n8.x4.shared.b16 {%0,%1,%2,%3}, [%4];"
                 : "=r"(r0), "=r"(r1), "=r"(r2), "=r"(r3) : "r"(a));
}
__device__ __forceinline__ void ldsm2t(u32 a, u32& r0, u32& r1) {
    asm volatile("ldmatrix.sync.aligned.m8n8.x2.trans.shared.b16 {%0,%1}, [%2];"
                 : "=r"(r0), "=r"(r1) : "r"(a));
}
__device__ __forceinline__ void mma16816(float& d0, float& d1, float& d2, float& d3,
                                         u32 a0, u32 a1, u32 a2, u32 a3, u32 b0, u32 b1) {
    asm volatile("mma.sync.aligned.m16n8k16.row.col.f32.f16.f16.f32 "
                 "{%0,%1,%2,%3},{%4,%5,%6,%7},{%8,%9},{%0,%1,%2,%3};"
                 : "+f"(d0), "+f"(d1), "+f"(d2), "+f"(d3)
                 : "r"(a0), "r"(a1), "r"(a2), "r"(a3), "r"(b0), "r"(b1));
}

__device__ __forceinline__ void st8(float* scr, int j, u64 v0, u64 v1, u64 v2, u64 v3) {
    *reinterpret_cast<ulonglong2*>(scr + j * 4)       = make_ulonglong2(v0, v1);
    *reinterpret_cast<ulonglong2*>(scr + 512 + j * 4) = make_ulonglong2(v2, v3);
}
__device__ __forceinline__ void ld8(const float* scr, int j, u64& v0, u64& v1, u64& v2, u64& v3) {
    ulonglong2 a = *reinterpret_cast<const ulonglong2*>(scr + j * 4);
    ulonglong2 b = *reinterpret_cast<const ulonglong2*>(scr + 512 + j * 4);
    v0 = a.x; v1 = a.y; v2 = b.x; v3 = b.y;
}

__global__ void cth_kernel(const float* __restrict__ s_temb, const float* __restrict__ s_t1w,
                           const float* __restrict__ s_t1b, const float* __restrict__ s_t2w,
                           const float* __restrict__ s_t2b, const float* __restrict__ tr1w,
                           const float* __restrict__ tr1b) {
    int j = threadIdx.x;
    __shared__ float v[NH], th[NH];
    for (int k = 0; k < NK; k++) {
        float tau = fmaxf((float)k / 1000.0f, 1e-6f);
        float z = tau * s_t1w[j] + s_t1b[j];
        v[j] = z / (1.0f + expf(-z));
        __syncthreads();
        float acc = s_t2b[j];
        for (int q = 0; q < NH; q++) acc += v[q] * s_t2w[q * NH + j];
        th[j] = acc;
        __syncthreads();
        float c = tr1b[j];
        for (int q = 0; q < NH; q++) {
            c += s_temb[k * NH + q] * tr1w[(2 * NH + q) * NH + j];
            c += th[q] * tr1w[(3 * NH + q) * NH + j];
        }
        g_cth[k * NH + j] = c;
        __syncthreads();
    }
}

__global__ void p_kernel(const float* __restrict__ s_yw, const float* __restrict__ s_yb,
                         const float* __restrict__ tr1w) {
    int k = threadIdx.x, d = blockIdx.x;
    float acc = 0.0f;
    for (int j = 0; j < NH; j++) acc += s_yw[d * NH + j] * tr1w[(NH + j) * NH + k];
    g_P[d * NH + k] = acc;
    if (d == 0) {
        float bp = 0.0f;
        for (int j = 0; j < NH; j++) bp += s_yb[j] * tr1w[(NH + j) * NH + k];
        for (int c = 0; c < NK; c++) g_cth[c * NH + k] += bp;
    }
}

__global__ __launch_bounds__(256)
void gemm128_kernel(const float* __restrict__ X, int ldx, int Kdim,
                    const float* __restrict__ Wm, const float* __restrict__ bias,
                    const float* __restrict__ table, const int* __restrict__ tt,
                    float* __restrict__ out) {
    __shared__ float Xs[64 * 33];
    __shared__ float Ws[32 * 128];
    int tid = threadIdx.x, tcol = tid & 31, trow = tid >> 5, m0 = blockIdx.x * 64;
    float acc[8][4];
#pragma unroll
    for (int p = 0; p < 8; p++)
#pragma unroll
        for (int q = 0; q < 4; q++) acc[p][q] = 0.0f;
    for (int k0 = 0; k0 < Kdim; k0 += 32) {
#pragma unroll
        for (int i = 0; i < 8; i++) {
            int e = tid + 256 * i;
            Xs[(e >> 5) * 33 + (e & 31)] = X[(m0 + (e >> 5)) * ldx + k0 + (e & 31)];
        }
#pragma unroll
        for (int i = 0; i < 16; i++) {
            int e = tid + 256 * i;
            Ws[(e >> 7) * 128 + (e & 127)] = Wm[(k0 + (e >> 7)) * NH + (e & 127)];
        }
        __syncthreads();
#pragma unroll 8
        for (int kk = 0; kk < 32; kk++) {
            float xv[8], wv[4];
#pragma unroll
            for (int p = 0; p < 8; p++) xv[p] = Xs[(trow + 8 * p) * 33 + kk];
#pragma unroll
            for (int q = 0; q < 4; q++) wv[q] = Ws[kk * 128 + tcol + 32 * q];
#pragma unroll
            for (int p = 0; p < 8; p++)
#pragma unroll
                for (int q = 0; q < 4; q++) acc[p][q] += xv[p] * wv[q];
        }
        __syncthreads();
    }
#pragma unroll
    for (int p = 0; p < 8; p++) {
        int m = m0 + trow + 8 * p;
        int tc = 0;
        if (table) { int tv = tt[m]; tc = tv > 0 ? tv : 0; }
#pragma unroll
        for (int q = 0; q < 4; q++) {
            int n = tcol + 32 * q;
            float vv = acc[p][q];
            if (bias)  vv += bias[n];
            if (table) vv += table[tc * NH + n];
            out[m * NH + n] = vv;
        }
    }
}

__global__ __launch_bounds__(256)
void gemm128_dual_kernel(const float* __restrict__ X, int ldx, int Kdim,
                         const float* __restrict__ W0, const float* __restrict__ b0v,
                         const float* __restrict__ W1, const float* __restrict__ b1v,
                         float* __restrict__ out0, float* __restrict__ out1) {
    __shared__ float Xs[64 * 33];
    __shared__ float Ws0[32 * 128];
    __shared__ float Ws1[32 * 128];
    int tid = threadIdx.x, tcol = tid & 31, trow = tid >> 5, m0 = blockIdx.x * 64;
    float a0[8][4], a1[8][4];
#pragma unroll
    for (int p = 0; p < 8; p++)
#pragma unroll
        for (int q = 0; q < 4; q++) { a0[p][q] = 0.0f; a1[p][q] = 0.0f; }
    for (int k0 = 0; k0 < Kdim; k0 += 32) {
#pragma unroll
        for (int i = 0; i < 8; i++) {
            int e = tid + 256 * i;
            Xs[(e >> 5) * 33 + (e & 31)] = X[(m0 + (e >> 5)) * ldx + k0 + (e & 31)];
        }
#pragma unroll
        for (int i = 0; i < 16; i++) {
            int e = tid + 256 * i;
            Ws0[(e >> 7) * 128 + (e & 127)] = W0[(k0 + (e >> 7)) * NH + (e & 127)];
            Ws1[(e >> 7) * 128 + (e & 127)] = W1[(k0 + (e >> 7)) * NH + (e & 127)];
        }
        __syncthreads();
#pragma unroll 4
        for (int kk = 0; kk < 32; kk++) {
            float xv[8], w0[4], w1[4];
#pragma unroll
            for (int p = 0; p < 8; p++) xv[p] = Xs[(trow + 8 * p) * 33 + kk];
#pragma unroll
            for (int q = 0; q < 4; q++) { w0[q] = Ws0[kk * 128 + tcol + 32 * q]; w1[q] = Ws1[kk * 128 + tcol + 32 * q]; }
#pragma unroll
            for (int p = 0; p < 8; p++)
#pragma unroll
                for (int q = 0; q < 4; q++) { a0[p][q] += xv[p] * w0[q]; a1[p][q] += xv[p] * w1[q]; }
        }
        __syncthreads();
    }
#pragma unroll
    for (int p = 0; p < 8; p++) {
        int m = m0 + trow + 8 * p;
#pragma unroll
        for (int q = 0; q < 4; q++) {
            int n = tcol + 32 * q;
            out0[m * NH + n] = a0[p][q] + b0v[n];
            out1[m * NH + n] = a1[p][q] + b1v[n];
        }
    }
}

// SMEM float-slot offsets
#define OFF_E1Y  0
#define OFF_W2   4096
#define OFF_PM   20480
#define OFF_E3T  24576
#define OFF_T2   25088
#define OFF_B2   25600
#define OFF_T2B  25728
#define OFF_M2   25736
#define OFF_ZERO 25992
#define OFF_WA   26000
#define OFF_WE   34192
#define OFF_SCR  42384
#define SMEM_FLOATS (OFF_SCR + 8 * 1024)
#define SMEM_BYTES  (SMEM_FLOATS * 4)

__global__ __launch_bounds__(256, 1)
void edi_main_kernel(const int* __restrict__ t, const float* __restrict__ e_w1,
                     const float* __restrict__ e_w2, const float* __restrict__ e_b2,
                     const float* __restrict__ e_w3, const float* __restrict__ tr2w,
                     const float* __restrict__ tr2b, const int* __restrict__ steps_p,
                     float* __restrict__ out) {
    extern __shared__ float sm[];
    float*  sE1y = sm + OFF_E1Y;
    float*  sW2  = sm + OFF_W2;
    float*  sP   = sm + OFF_PM;
    float*  sE3T = sm + OFF_E3T;
    float*  sT2  = sm + OFF_T2;
    float*  sb2  = sm + OFF_B2;
    float*  st2b = sm + OFF_T2B;
    u32*    sM2  = (u32*)(sm + OFF_M2);
    float*  zeroL= sm + OFF_ZERO;
    __half* sWa  = (__half*)(sm + OFF_WA);
    __half* sWe  = (__half*)(sm + OFF_WE);
    float*  sscr = sm + OFF_SCR;

    int tid = threadIdx.x;
    for (int idx = tid; idx < 32 * 128; idx += 256) {
        int d = idx >> 7, k = idx & 127;
        int swi = d * 128 + (k & 96) + ((k & 31) ^ d);
        sE1y[swi] = e_w1[(NDX + d) * NH + k];
        sP[swi]   = g_P[idx];
    }
    // W2: f32 swizzled (exact bwd) + split-fp16 copies, 16B chunks XORed by j&7 for LDSM.
    for (int idx = tid; idx < 128 * 128; idx += 256) {
        int j = idx >> 7, c = idx & 127;
        float w = e_w2[idx];
        sW2[j * 128 + (c & 96) + ((c & 31) ^ (j & 31))] = w;
        __half ha = __float2half_rn(w);
        int hp = j * 128 + (((c >> 3) ^ (j & 7)) << 3) + (c & 7);
        sWa[hp] = ha;
        sWe[hp] = __float2half_rn(w - __half2float(ha));
    }
    for (int idx = tid; idx < 512; idx += 256) {
        sE3T[(idx & 3) * 128 + (idx >> 2)] = e_w3[idx];
        sT2[idx] = tr2w[idx];
    }
    if (tid < 128) sb2[tid] = e_b2[tid];
    if (tid < 4)   st2b[tid] = tr2b[tid];
    if (tid < 8)   zeroL[tid] = 0.0f;
    __syncthreads();

    const int lane = tid & 31;
    const int warp = tid >> 5;
    float* scr = sscr + warp * 1024;
    char*  scb = (char*)scr;
    const int r0 = (blockIdx.x * 8 + warp) * 8;
    const int nsteps = *steps_p;

    const u32 scrU = smemu(scr);
    const u32 zU   = smemu(zeroL);
    const u32 waU  = smemu(sWa);
    const u32 weU  = smemu(sWe);
    const bool aZero = (lane & 8) != 0;           // ldmatrix rows 8-15 -> zero line (M pad)
    const u32 aOff = (u32)((lane & 7) * 256 + ((lane & 16) ? 16 : 0));
    u32* myM2 = sM2 + warp * 32;
    const int cb = 2 * (lane & 3);

    int tci[8]; float svf[8];
#pragma unroll
    for (int r = 0; r < 8; r++) {
        int tv = t[r0 + r];
        tci[r] = tv > 0 ? tv : 0;
        svf[r] = tv >= 0 ? C_SW : 0.0f;
    }

    u64 y[4] = {0ull, 0ull, 0ull, 0ull};
    u64 hxe[4][4], cc[4][4];
#pragma unroll
    for (int m = 0; m < 4; m++)
#pragma unroll
        for (int p = 0; p < 4; p++) {
            int col = 32 * m + lane;
            hxe[m][p] = pk2(g_hxe[(r0 + 2 * p) * NH + col], g_hxe[(r0 + 2 * p + 1) * NH + col]);
            cc[m][p]  = pk2(g_c[(r0 + 2 * p) * NH + col],   g_c[(r0 + 2 * p + 1) * NH + col]);
        }

    for (int s = 0; s < nsteps; s++) {
        __syncwarp();
        st8(scr, lane, y[0], y[1], y[2], y[3]);
        __syncwarp();

        // fused fwd: h1pre = hxe + y@E1y ; u = cc + y@P
        u64 A[4][4], U[4][4];
#pragma unroll
        for (int m = 0; m < 4; m++)
#pragma unroll
            for (int p = 0; p < 4; p++) { A[m][p] = hxe[m][p]; U[m][p] = cc[m][p]; }
#pragma unroll 4
        for (int d = 0; d < 32; d++) {
            u64 b0, b1, b2, b3; ld8(scr, d, b0, b1, b2, b3);
            int base = d * 128 + (lane ^ d);
#pragma unroll
            for (int m = 0; m < 4; m++) {
                u64 w = pks(sE1y[base + 32 * m]);
                A[m][0] = ffma2(b0, w, A[m][0]); A[m][1] = ffma2(b1, w, A[m][1]);
                A[m][2] = ffma2(b2, w, A[m][2]); A[m][3] = ffma2(b3, w, A[m][3]);
                u64 v = pks(sP[base + 32 * m]);
                U[m][0] = ffma2(b0, v, U[m][0]); U[m][1] = ffma2(b1, v, U[m][1]);
                U[m][2] = ffma2(b2, v, U[m][2]); U[m][3] = ffma2(b3, v, U[m][3]);
            }
        }
        unsigned m1 = 0;
#pragma unroll
        for (int m = 0; m < 4; m++)
#pragma unroll
            for (int p = 0; p < 4; p++) {
                float x, z; up2(A[m][p], x, z);
                m1 |= (x > 0.f ? 1u : 0u) << (m * 8 + 2 * p);
                m1 |= (z > 0.f ? 1u : 0u) << (m * 8 + 2 * p + 1);
                A[m][p] = pk2(fmaxf(x, 0.f), fmaxf(z, 0.f));
            }
        __syncwarp();
        // store split-fp16 A tiles: hi rows at bytes [0,2048), lo at [2048,4096); 256B row stride
#pragma unroll
        for (int m = 0; m < 4; m++) {
            int jj = lane + 32 * m;
#pragma unroll
            for (int p = 0; p < 4; p++) {
                float x, z; up2(A[m][p], x, z);
                __half hx = __float2half_rn(x), hz = __float2half_rn(z);
                *(__half*)(scb + (2 * p) * 256 + jj * 2)            = hx;
                *(__half*)(scb + (2 * p + 1) * 256 + jj * 2)        = hz;
                *(__half*)(scb + 2048 + (2 * p) * 256 + jj * 2)     = __float2half_rn(x - __half2float(hx));
                *(__half*)(scb + 2048 + (2 * p + 1) * 256 + jj * 2) = __float2half_rn(z - __half2float(hz));
            }
        }
        __syncwarp();

        // W2 fwd via mma: h2pre = a@wa + e@wa + a@we (drop e@we); f32 accum; signs -> sM2
        {
            float D0[16], D1[16], dj0 = 0.f, dj1 = 0.f;
#pragma unroll
            for (int nt = 0; nt < 16; nt++) { D0[nt] = 0.f; D1[nt] = 0.f; }
#pragma unroll 1
            for (int kt = 0; kt < 8; kt++) {
                u32 aa0, aa1, aa2, aa3, ae0, ae1, ae2, ae3;
                u32 adA = aZero ? zU : (scrU + aOff + (u32)(kt * 32));
                u32 adE = aZero ? zU : (scrU + 2048u + aOff + (u32)(kt * 32));
                ldsm4(adA, aa0, aa1, aa2, aa3);
                ldsm4(adE, ae0, ae1, ae2, ae3);
                int jr = kt * 16 + (lane & 15);
                u32 br = (u32)(jr * 256);
                int bs = jr & 7;
#pragma unroll
                for (int nt = 0; nt < 16; nt++) {
                    u32 off = br + (u32)(((nt ^ bs) & 15) * 16);
                    u32 b0, b1, c0r, c1r;
                    ldsm2t(waU + off, b0, b1);
                    ldsm2t(weU + off, c0r, c1r);
                    mma16816(D0[nt], D1[nt], dj0, dj1, aa0, aa1, aa2, aa3, b0, b1);
                    mma16816(D0[nt], D1[nt], dj0, dj1, ae0, ae1, ae2, ae3, b0, b1);
                    mma16816(D0[nt], D1[nt], dj0, dj1, aa0, aa1, aa2, aa3, c0r, c1r);
                }
            }
            u32 mw[4] = {0u, 0u, 0u, 0u};
#pragma unroll
            for (int nt = 0; nt < 16; nt++) {
                int cg = nt * 8 + cb;
                u32 bits = ((D0[nt] + sb2[cg] > 0.f) ? 1u : 0u)
                         | ((D1[nt] + sb2[cg + 1] > 0.f) ? 2u : 0u);
                mw[nt >> 2] |= bits << ((nt & 3) * 8 + cb);
            }
#pragma unroll
            for (int w = 0; w < 4; w++) {
                mw[w] |= __shfl_xor_sync(0xffffffffu, mw[w], 1);
                mw[w] |= __shfl_xor_sync(0xffffffffu, mw[w], 2);
            }
            if ((lane & 3) == 0) {
                int rr = lane >> 2;
#pragma unroll
                for (int w = 0; w < 4; w++) myM2[rr * 4 + w] = mw[w];
            }
        }
        __syncwarp();

        // logits partials, warp reduce, softmax -> dlogits
        u64 lg[4][4];
#pragma unroll
        for (int k = 0; k < 4; k++)
#pragma unroll
            for (int p = 0; p < 4; p++) lg[k][p] = 0ull;
#pragma unroll
        for (int m = 0; m < 4; m++) {
            float4 t2 = *reinterpret_cast<const float4*>(&sT2[(lane + 32 * m) * 4]);
#pragma unroll
            for (int p = 0; p < 4; p++) {
                float ux, uz; up2(U[m][p], ux, uz);
                float ax = ux * __fdividef(1.f, 1.f + __expf(-ux));
                float az = uz * __fdividef(1.f, 1.f + __expf(-uz));
                u64 a2 = pk2(ax, az);
                lg[0][p] = ffma2(a2, pks(t2.x), lg[0][p]);
                lg[1][p] = ffma2(a2, pks(t2.y), lg[1][p]);
                lg[2][p] = ffma2(a2, pks(t2.z), lg[2][p]);
                lg[3][p] = ffma2(a2, pks(t2.w), lg[3][p]);
            }
        }
#pragma unroll
        for (int off = 16; off > 0; off >>= 1)
#pragma unroll
            for (int k = 0; k < 4; k++)
#pragma unroll
                for (int p = 0; p < 4; p++)
                    lg[k][p] = fadd2(lg[k][p], __shfl_xor_sync(0xffffffffu, lg[k][p], off));

        u64 dl[4][4];
#pragma unroll
        for (int p = 0; p < 4; p++) {
            float l0[4], l1[4];
#pragma unroll
            for (int k = 0; k < 4; k++) {
                float x, z; up2(lg[k][p], x, z);
                l0[k] = x + st2b[k]; l1[k] = z + st2b[k];
            }
            float dlo[4], dhi[4];
            {
                float mx = fmaxf(fmaxf(l0[0], l0[1]), fmaxf(l0[2], l0[3]));
                float e0 = __expf(l0[0] - mx), e1 = __expf(l0[1] - mx);
                float e2 = __expf(l0[2] - mx), e3 = __expf(l0[3] - mx);
                float sw = svf[2 * p]; int tc = tci[2 * p];
                float inv = sw * __fdividef(1.f, e0 + e1 + e2 + e3);
                dlo[0] = e0 * inv - (tc == 0 ? sw : 0.f);
                dlo[1] = e1 * inv - (tc == 1 ? sw : 0.f);
                dlo[2] = e2 * inv - (tc == 2 ? sw : 0.f);
                dlo[3] = e3 * inv - (tc == 3 ? sw : 0.f);
            }
            {
                float mx = fmaxf(fmaxf(l1[0], l1[1]), fmaxf(l1[2], l1[3]));
                float e0 = __expf(l1[0] - mx), e1 = __expf(l1[1] - mx);
                float e2 = __expf(l1[2] - mx), e3 = __expf(l1[3] - mx);
                float sw = svf[2 * p + 1]; int tc = tci[2 * p + 1];
                float inv = sw * __fdividef(1.f, e0 + e1 + e2 + e3);
                dhi[0] = e0 * inv - (tc == 0 ? sw : 0.f);
                dhi[1] = e1 * inv - (tc == 1 ? sw : 0.f);
                dhi[2] = e2 * inv - (tc == 2 ? sw : 0.f);
                dhi[3] = e3 * inv - (tc == 3 ? sw : 0.f);
            }
#pragma unroll
            for (int k = 0; k < 4; k++) dl[k][p] = pk2(dlo[k], dhi[k]);
        }

        // du = (tr2w @ dl) * silu'(u)
        __syncwarp();
#pragma unroll
        for (int m = 0; m < 4; m++) {
            int jj = lane + 32 * m;
            float4 t2 = *reinterpret_cast<const float4*>(&sT2[jj * 4]);
            u64 dv[4];
#pragma unroll
            for (int p = 0; p < 4; p++) {
                u64 da = fmul2(dl[0][p], pks(t2.x));
                da = ffma2(dl[1][p], pks(t2.y), da);
                da = ffma2(dl[2][p], pks(t2.z), da);
                da = ffma2(dl[3][p], pks(t2.w), da);
                float ux, uz; up2(U[m][p], ux, uz);
                float sgx = __fdividef(1.f, 1.f + __expf(-ux));
                float sgz = __fdividef(1.f, 1.f + __expf(-uz));
                dv[p] = fmul2(da, pk2(sgx * (1.f + ux * (1.f - sgx)),
                                      sgz * (1.f + uz * (1.f - sgz))));
            }
            st8(scr, jj, dv[0], dv[1], dv[2], dv[3]);
        }
        __syncwarp();

        // gy = 2*REG*y + P[lane,:] . du
        u64 gy[4];
#pragma unroll
        for (int p = 0; p < 4; p++) gy[p] = fmul2(pks(2.f * C_REG), y[p]);
#pragma unroll 4
        for (int k = 0; k < 128; k++) {
            u64 b0, b1, b2, b3; ld8(scr, k, b0, b1, b2, b3);
            u64 w = pks(sP[lane * 128 + (k & 96) + ((k & 31) ^ lane)]);
            gy[0] = ffma2(b0, w, gy[0]); gy[1] = ffma2(b1, w, gy[1]);
            gy[2] = ffma2(b2, w, gy[2]); gy[3] = ffma2(b3, w, gy[3]);
        }

        // energy bwd: dh2pre = (h2>0 via sM2) * e_w3[:, tci]
        __syncwarp();
#pragma unroll
        for (int m = 0; m < 4; m++) {
            int jj = lane + 32 * m;
            u64 dv[4];
#pragma unroll
            for (int p = 0; p < 4; p++) {
                u32 w0 = myM2[(2 * p) * 4 + m];
                u32 w1 = myM2[(2 * p + 1) * 4 + m];
                float e0 = ((w0 >> lane) & 1u) ? sE3T[tci[2 * p] * 128 + jj]     : 0.f;
                float e1 = ((w1 >> lane) & 1u) ? sE3T[tci[2 * p + 1] * 128 + jj] : 0.f;
                dv[p] = pk2(e0, e1);
            }
            st8(scr, jj, dv[0], dv[1], dv[2], dv[3]);
        }
        __syncwarp();

        // W2 bwd (exact fp32): dh1 masked by h1>0
        u64 D[4][4];
#pragma unroll
        for (int m = 0; m < 4; m++)
#pragma unroll
            for (int p = 0; p < 4; p++) D[m][p] = 0ull;
#pragma unroll 4
        for (int k = 0; k < 128; k++) {
            u64 b0, b1, b2, b3; ld8(scr, k, b0, b1, b2, b3);
            int off = (k & 96) + ((k & 31) ^ lane);
#pragma unroll
            for (int m = 0; m < 4; m++) {
                u64 w = pks(sW2[(lane + 32 * m) * 128 + off]);
                D[m][0] = ffma2(b0, w, D[m][0]); D[m][1] = ffma2(b1, w, D[m][1]);
                D[m][2] = ffma2(b2, w, D[m][2]); D[m][3] = ffma2(b3, w, D[m][3]);
            }
        }
#pragma unroll
        for (int m = 0; m < 4; m++)
#pragma unroll
            for (int p = 0; p < 4; p++) {
                float x, z; up2(D[m][p], x, z);
                x = ((m1 >> (m * 8 + 2 * p)) & 1)     ? x : 0.f;
                z = ((m1 >> (m * 8 + 2 * p + 1)) & 1) ? z : 0.f;
                D[m][p] = pk2(x, z);
            }
        __syncwarp();
#pragma unroll
        for (int m = 0; m < 4; m++) st8(scr, lane + 32 * m, D[m][0], D[m][1], D[m][2], D[m][3]);
        __syncwarp();

        // gy += E1y[lane,:] . dh1pre
#pragma unroll 4
        for (int j = 0; j < 128; j++) {
            u64 b0, b1, b2, b3; ld8(scr, j, b0, b1, b2, b3);
            u64 w = pks(sE1y[lane * 128 + (j & 96) + ((j & 31) ^ lane)]);
            gy[0] = ffma2(b0, w, gy[0]); gy[1] = ffma2(b1, w, gy[1]);
            gy[2] = ffma2(b2, w, gy[2]); gy[3] = ffma2(b3, w, gy[3]);
        }

#pragma unroll
        for (int p = 0; p < 4; p++) y[p] = ffma2(gy[p], pks(-C_LR), y[p]);
    }

#pragma unroll
    for (int p = 0; p < 4; p++) {
        float a, b; up2(y[p], a, b);
        out[(r0 + 2 * p) * NDY + lane] = a;
        out[(r0 + 2 * p + 1) * NDY + lane] = b;
    }
}

extern "C" void kernel_launch(void* const* d_in, const int* in_sizes, int n_in,
                              void* d_out, int out_size) {
    const float* x      = (const float*)d_in[0];
    const int*   t      = (const int*)d_in[1];
    const float* e_w1   = (const float*)d_in[2];
    const float* e_b1   = (const float*)d_in[3];
    const float* e_w2   = (const float*)d_in[4];
    const float* e_b2   = (const float*)d_in[5];
    const float* e_w3   = (const float*)d_in[6];
    const float* s_xw   = (const float*)d_in[8];
    const float* s_xb   = (const float*)d_in[9];
    const float* s_yw   = (const float*)d_in[10];
    const float* s_yb   = (const float*)d_in[11];
    const float* s_temb = (const float*)d_in[12];
    const float* s_t1w  = (const float*)d_in[13];
    const float* s_t1b  = (const float*)d_in[14];
    const float* s_t2w  = (const float*)d_in[15];
    const float* s_t2b  = (const float*)d_in[16];
    const float* tr1w   = (const float*)d_in[17];
    const float* tr1b   = (const float*)d_in[18];
    const float* tr2w   = (const float*)d_in[19];
    const float* tr2b   = (const float*)d_in[20];
    const int*   steps  = (const int*)d_in[21];
    float* out = (float*)d_out;

    float *p_hxe, *p_hxs, *p_c, *p_cth;
    cudaGetSymbolAddress((void**)&p_hxe, g_hxe);
    cudaGetSymbolAddress((void**)&p_hxs, g_hxs);
    cudaGetSymbolAddress((void**)&p_c,   g_c);
    cudaGetSymbolAddress((void**)&p_cth, g_cth);

    cth_kernel<<<1, NH>>>(s_temb, s_t1w, s_t1b, s_t2w, s_t2b, tr1w, tr1b);
    p_kernel<<<NDY, NH>>>(s_yw, s_yb, tr1w);
    gemm128_dual_kernel<<<NB / 64, 256>>>(x, NDX, NDX, e_w1, e_b1, s_xw, s_xb, p_hxe, p_hxs);
    gemm128_kernel<<<NB / 64, 256>>>(p_hxs, NH, NH, tr1w, nullptr, p_cth, t, p_c);

    cudaFuncSetAttribute(edi_main_kernel, cudaFuncAttributeMaxDynamicSharedMemorySize, SMEM_BYTES);
    edi_main_kernel<<<NB / 64, 256, SMEM_BYTES>>>(t, e_w1, e_w2, e_b2, e_w3,
                                                  tr2w, tr2b, steps, out);
}

// round 13
// speedup vs baseline: 2.7325x; 1.0871x over previous
#include <cuda_runtime.h>
#include <cuda_fp16.h>
typedef unsigned long long u64;
typedef unsigned int u32;
typedef unsigned short u16;

#define NB   131072
#define NDX  256
#define NDY  32
#define NK   4
#define NH   128
#define C_LR  0.1f
#define C_REG 0.01f
#define C_SW  1.0f

__device__ float g_hxe[NB * NH];
__device__ float g_hxs[NB * NH];
__device__ float g_c[NB * NH];
__device__ float g_cth[NK * NH];
__device__ float g_P[NDY * NH];

__device__ __forceinline__ u64 pk2(float x, float y) {
    u64 r; asm("mov.b64 %0, {%1,%2};" : "=l"(r) : "f"(x), "f"(y)); return r;
}
__device__ __forceinline__ u64 pks(float x) {
    u64 r; asm("mov.b64 %0, {%1,%1};" : "=l"(r) : "f"(x)); return r;
}
__device__ __forceinline__ void up2(u64 v, float& x, float& y) {
    asm("mov.b64 {%0,%1}, %2;" : "=f"(x), "=f"(y) : "l"(v));
}
__device__ __forceinline__ u64 ffma2(u64 a, u64 b, u64 c) {
    u64 d; asm("fma.rn.f32x2 %0, %1, %2, %3;" : "=l"(d) : "l"(a), "l"(b), "l"(c)); return d;
}
__device__ __forceinline__ u64 fmul2(u64 a, u64 b) {
    u64 d; asm("mul.rn.f32x2 %0, %1, %2;" : "=l"(d) : "l"(a), "l"(b)); return d;
}
__device__ __forceinline__ u64 fadd2(u64 a, u64 b) {
    u64 d; asm("add.rn.f32x2 %0, %1, %2;" : "=l"(d) : "l"(a), "l"(b)); return d;
}
__device__ __forceinline__ u32 smemu(const void* p) {
    return (u32)__cvta_generic_to_shared(p);
}
__device__ __forceinline__ void ldsm4(u32 a, u32& r0, u32& r1, u32& r2, u32& r3) {
    asm volatile("ldmatrix.sync.aligned.m8n8.x4.shared.b16 {%0,%1,%2,%3}, [%4];"
                 : "=r"(r0), "=r"(r1), "=r"(r2), "=r"(r3) : "r"(a));
}
__device__ __forceinline__ void ldsm2t(u32 a, u32& r0, u32& r1) {
    asm volatile("ldmatrix.sync.aligned.m8n8.x2.trans.shared.b16 {%0,%1}, [%2];"
                 : "=r"(r0), "=r"(r1) : "r"(a));
}
__device__ __forceinline__ void mma16816(float& d0, float& d1, float& d2, float& d3,
                                         u32 a0, u32 a1, u32 a2, u32 a3, u32 b0, u32 b1) {
    asm volatile("mma.sync.aligned.m16n8k16.row.col.f32.f16.f16.f32 "
                 "{%0,%1,%2,%3},{%4,%5,%6,%7},{%8,%9},{%0,%1,%2,%3};"
                 : "+f"(d0), "+f"(d1), "+f"(d2), "+f"(d3)
                 : "r"(a0), "r"(a1), "r"(a2), "r"(a3), "r"(b0), "r"(b1));
}
__device__ __forceinline__ void st8(float* scr, int j, u64 v0, u64 v1, u64 v2, u64 v3) {
    *reinterpret_cast<ulonglong2*>(scr + j * 4)       = make_ulonglong2(v0, v1);
    *reinterpret_cast<ulonglong2*>(scr + 512 + j * 4) = make_ulonglong2(v2, v3);
}
__device__ __forceinline__ void ld8(const float* scr, int j, u64& v0, u64& v1, u64& v2, u64& v3) {
    ulonglong2 a = *reinterpret_cast<const ulonglong2*>(scr + j * 4);
    ulonglong2 b = *reinterpret_cast<const ulonglong2*>(scr + 512 + j * 4);
    v0 = a.x; v1 = a.y; v2 = b.x; v3 = b.y;
}

__global__ void cth_kernel(const float* __restrict__ s_temb, const float* __restrict__ s_t1w,
                           const float* __restrict__ s_t1b, const float* __restrict__ s_t2w,
                           const float* __restrict__ s_t2b, const float* __restrict__ tr1w,
                           const float* __restrict__ tr1b) {
    int j = threadIdx.x;
    __shared__ float v[NH], th[NH];
    for (int k = 0; k < NK; k++) {
        float tau = fmaxf((float)k / 1000.0f, 1e-6f);
        float z = tau * s_t1w[j] + s_t1b[j];
        v[j] = z / (1.0f + expf(-z));
        __syncthreads();
        float acc = s_t2b[j];
        for (int q = 0; q < NH; q++) acc += v[q] * s_t2w[q * NH + j];
        th[j] = acc;
        __syncthreads();
        float c = tr1b[j];
        for (int q = 0; q < NH; q++) {
            c += s_temb[k * NH + q] * tr1w[(2 * NH + q) * NH + j];
            c += th[q] * tr1w[(3 * NH + q) * NH + j];
        }
        g_cth[k * NH + j] = c;
        __syncthreads();
    }
}

__global__ void p_kernel(const float* __restrict__ s_yw, const float* __restrict__ s_yb,
                         const float* __restrict__ tr1w) {
    int k = threadIdx.x, d = blockIdx.x;
    float acc = 0.0f;
    for (int j = 0; j < NH; j++) acc += s_yw[d * NH + j] * tr1w[(NH + j) * NH + k];
    g_P[d * NH + k] = acc;
    if (d == 0) {
        float bp = 0.0f;
        for (int j = 0; j < NH; j++) bp += s_yb[j] * tr1w[(NH + j) * NH + k];
        for (int c = 0; c < NK; c++) g_cth[c * NH + k] += bp;
    }
}

__global__ __launch_bounds__(256)
void gemm128_kernel(const float* __restrict__ X, int ldx, int Kdim,
                    const float* __restrict__ Wm, const float* __restrict__ bias,
                    const float* __restrict__ table, const int* __restrict__ tt,
                    float* __restrict__ out) {
    __shared__ float Xs[64 * 33];
    __shared__ float Ws[32 * 128];
    int tid = threadIdx.x, tcol = tid & 31, trow = tid >> 5, m0 = blockIdx.x * 64;
    float acc[8][4];
#pragma unroll
    for (int p = 0; p < 8; p++)
#pragma unroll
        for (int q = 0; q < 4; q++) acc[p][q] = 0.0f;
    for (int k0 = 0; k0 < Kdim; k0 += 32) {
#pragma unroll
        for (int i = 0; i < 8; i++) {
            int e = tid + 256 * i;
            Xs[(e >> 5) * 33 + (e & 31)] = X[(m0 + (e >> 5)) * ldx + k0 + (e & 31)];
        }
#pragma unroll
        for (int i = 0; i < 16; i++) {
            int e = tid + 256 * i;
            Ws[(e >> 7) * 128 + (e & 127)] = Wm[(k0 + (e >> 7)) * NH + (e & 127)];
        }
        __syncthreads();
#pragma unroll 8
        for (int kk = 0; kk < 32; kk++) {
            float xv[8], wv[4];
#pragma unroll
            for (int p = 0; p < 8; p++) xv[p] = Xs[(trow + 8 * p) * 33 + kk];
#pragma unroll
            for (int q = 0; q < 4; q++) wv[q] = Ws[kk * 128 + tcol + 32 * q];
#pragma unroll
            for (int p = 0; p < 8; p++)
#pragma unroll
                for (int q = 0; q < 4; q++) acc[p][q] += xv[p] * wv[q];
        }
        __syncthreads();
    }
#pragma unroll
    for (int p = 0; p < 8; p++) {
        int m = m0 + trow + 8 * p;
        int tc = 0;
        if (table) { int tv = tt[m]; tc = tv > 0 ? tv : 0; }
#pragma unroll
        for (int q = 0; q < 4; q++) {
            int n = tcol + 32 * q;
            float vv = acc[p][q];
            if (bias)  vv += bias[n];
            if (table) vv += table[tc * NH + n];
            out[m * NH + n] = vv;
        }
    }
}

__global__ __launch_bounds__(256)
void gemm128_dual_kernel(const float* __restrict__ X, int ldx, int Kdim,
                         const float* __restrict__ W0, const float* __restrict__ b0v,
                         const float* __restrict__ W1, const float* __restrict__ b1v,
                         float* __restrict__ out0, float* __restrict__ out1) {
    __shared__ float Xs[64 * 33];
    __shared__ float Ws0[32 * 128];
    __shared__ float Ws1[32 * 128];
    int tid = threadIdx.x, tcol = tid & 31, trow = tid >> 5, m0 = blockIdx.x * 64;
    float a0[8][4], a1[8][4];
#pragma unroll
    for (int p = 0; p < 8; p++)
#pragma unroll
        for (int q = 0; q < 4; q++) { a0[p][q] = 0.0f; a1[p][q] = 0.0f; }
    for (int k0 = 0; k0 < Kdim; k0 += 32) {
#pragma unroll
        for (int i = 0; i < 8; i++) {
            int e = tid + 256 * i;
            Xs[(e >> 5) * 33 + (e & 31)] = X[(m0 + (e >> 5)) * ldx + k0 + (e & 31)];
        }
#pragma unroll
        for (int i = 0; i < 16; i++) {
            int e = tid + 256 * i;
            Ws0[(e >> 7) * 128 + (e & 127)] = W0[(k0 + (e >> 7)) * NH + (e & 127)];
            Ws1[(e >> 7) * 128 + (e & 127)] = W1[(k0 + (e >> 7)) * NH + (e & 127)];
        }
        __syncthreads();
#pragma unroll 4
        for (int kk = 0; kk < 32; kk++) {
            float xv[8], w0[4], w1[4];
#pragma unroll
            for (int p = 0; p < 8; p++) xv[p] = Xs[(trow + 8 * p) * 33 + kk];
#pragma unroll
            for (int q = 0; q < 4; q++) { w0[q] = Ws0[kk * 128 + tcol + 32 * q]; w1[q] = Ws1[kk * 128 + tcol + 32 * q]; }
#pragma unroll
            for (int p = 0; p < 8; p++)
#pragma unroll
                for (int q = 0; q < 4; q++) { a0[p][q] += xv[p] * w0[q]; a1[p][q] += xv[p] * w1[q]; }
        }
        __syncthreads();
    }
#pragma unroll
    for (int p = 0; p < 8; p++) {
        int m = m0 + trow + 8 * p;
#pragma unroll
        for (int q = 0; q < 4; q++) {
            int n = tcol + 32 * q;
            out0[m * NH + n] = a0[p][q] + b0v[n];
            out1[m * NH + n] = a1[p][q] + b1v[n];
        }
    }
}

// SMEM float-slot offsets
#define OFF_E1Y  0
#define OFF_W2   4096
#define OFF_PM   20480
#define OFF_E3T  24576
#define OFF_T2   25088
#define OFF_B2   25600
#define OFF_T2B  25728
#define OFF_M2V  25736      /* 256 u32 worth: 512 u16 = [64 rows][8 warps] */
#define OFF_M2W  25992      /* 256 u32: [64 rows][4 words] assembled masks */
#define OFF_WA   26248
#define OFF_WE   34440
#define OFF_SCR  42632      /* 8 warps x 1024 floats; doubles as 64x128 fp16 A hi+lo */
#define SMEM_FLOATS (OFF_SCR + 8 * 1024)
#define SMEM_BYTES  (SMEM_FLOATS * 4)

__global__ __launch_bounds__(256, 1)
void edi_main_kernel(const int* __restrict__ t, const float* __restrict__ e_w1,
                     const float* __restrict__ e_w2, const float* __restrict__ e_b2,
                     const float* __restrict__ e_w3, const float* __restrict__ tr2w,
                     const float* __restrict__ tr2b, const int* __restrict__ steps_p,
                     float* __restrict__ out) {
    extern __shared__ float sm[];
    float*  sE1y = sm + OFF_E1Y;
    float*  sW2  = sm + OFF_W2;
    float*  sP   = sm + OFF_PM;
    float*  sE3T = sm + OFF_E3T;
    float*  sT2  = sm + OFF_T2;
    float*  sb2  = sm + OFF_B2;
    float*  st2b = sm + OFF_T2B;
    u16*    sM2v = (u16*)(sm + OFF_M2V);
    u32*    sM2w = (u32*)(sm + OFF_M2W);
    __half* sWa  = (__half*)(sm + OFF_WA);
    __half* sWe  = (__half*)(sm + OFF_WE);
    float*  sscr = sm + OFF_SCR;
    __half* sAh  = (__half*)sscr;             // 64 rows x 128 halves, chunk-XOR swizzle
    __half* sAl  = (__half*)(sscr + 4096);

    int tid = threadIdx.x;
    for (int idx = tid; idx < 32 * 128; idx += 256) {
        int d = idx >> 7, k = idx & 127;
        int swi = d * 128 + (k & 96) + ((k & 31) ^ d);
        sE1y[swi] = e_w1[(NDX + d) * NH + k];
        sP[swi]   = g_P[idx];
    }
    for (int idx = tid; idx < 128 * 128; idx += 256) {
        int j = idx >> 7, c = idx & 127;
        float w = e_w2[idx];
        sW2[j * 128 + (c & 96) + ((c & 31) ^ (j & 31))] = w;
        __half ha = __float2half_rn(w);
        int hp = j * 128 + (((c >> 3) ^ (j & 7)) << 3) + (c & 7);
        sWa[hp] = ha;
        sWe[hp] = __float2half_rn(w - __half2float(ha));
    }
    for (int idx = tid; idx < 512; idx += 256) {
        sE3T[(idx & 3) * 128 + (idx >> 2)] = e_w3[idx];
        sT2[idx] = tr2w[idx];
    }
    if (tid < 128) sb2[tid] = e_b2[tid];
    if (tid < 4)   st2b[tid] = tr2b[tid];
    __syncthreads();

    const int lane = tid & 31;
    const int warp = tid >> 5;
    float* scr = sscr + warp * 1024;
    const int r0 = (blockIdx.x * 8 + warp) * 8;
    const int nsteps = *steps_p;
    const u32 waU = smemu(sWa);
    const u32 weU = smemu(sWe);
    const u32 ahU = smemu(sAh);
    const u32 alU = smemu(sAl);
    const int cb = 2 * (lane & 3);
    const int ntg0 = 2 * warp;

    int tci[8]; float svf[8];
#pragma unroll
    for (int r = 0; r < 8; r++) {
        int tv = t[r0 + r];
        tci[r] = tv > 0 ? tv : 0;
        svf[r] = tv >= 0 ? C_SW : 0.0f;
    }

    u64 y[4] = {0ull, 0ull, 0ull, 0ull};
    u64 hxe[4][4], cc[4][4];
#pragma unroll
    for (int m = 0; m < 4; m++)
#pragma unroll
        for (int p = 0; p < 4; p++) {
            int col = 32 * m + lane;
            hxe[m][p] = pk2(g_hxe[(r0 + 2 * p) * NH + col], g_hxe[(r0 + 2 * p + 1) * NH + col]);
            cc[m][p]  = pk2(g_c[(r0 + 2 * p) * NH + col],   g_c[(r0 + 2 * p + 1) * NH + col]);
        }

    for (int s = 0; s < nsteps; s++) {
        __syncwarp();
        st8(scr, lane, y[0], y[1], y[2], y[3]);
        __syncwarp();

        // fused fwd: h1pre = hxe + y@E1y ; u = cc + y@P
        u64 A[4][4], U[4][4];
#pragma unroll
        for (int m = 0; m < 4; m++)
#pragma unroll
            for (int p = 0; p < 4; p++) { A[m][p] = hxe[m][p]; U[m][p] = cc[m][p]; }
#pragma unroll 4
        for (int d = 0; d < 32; d++) {
            u64 b0, b1, b2, b3; ld8(scr, d, b0, b1, b2, b3);
            int base = d * 128 + (lane ^ d);
#pragma unroll
            for (int m = 0; m < 4; m++) {
                u64 w = pks(sE1y[base + 32 * m]);
                A[m][0] = ffma2(b0, w, A[m][0]); A[m][1] = ffma2(b1, w, A[m][1]);
                A[m][2] = ffma2(b2, w, A[m][2]); A[m][3] = ffma2(b3, w, A[m][3]);
                u64 v = pks(sP[base + 32 * m]);
                U[m][0] = ffma2(b0, v, U[m][0]); U[m][1] = ffma2(b1, v, U[m][1]);
                U[m][2] = ffma2(b2, v, U[m][2]); U[m][3] = ffma2(b3, v, U[m][3]);
            }
        }
        unsigned m1 = 0;
#pragma unroll
        for (int m = 0; m < 4; m++)
#pragma unroll
            for (int p = 0; p < 4; p++) {
                float x, z; up2(A[m][p], x, z);
                m1 |= (x > 0.f ? 1u : 0u) << (m * 8 + 2 * p);
                m1 |= (z > 0.f ? 1u : 0u) << (m * 8 + 2 * p + 1);
                A[m][p] = pk2(fmaxf(x, 0.f), fmaxf(z, 0.f));
            }

        // CTA-wide split-fp16 staging of relu(h1): rows = warp*8 + {2p,2p+1}
        __syncthreads();
#pragma unroll
        for (int m = 0; m < 4; m++) {
            int jj = lane + 32 * m;
#pragma unroll
            for (int p = 0; p < 4; p++) {
                float x, z; up2(A[m][p], x, z);
                __half hx = __float2half_rn(x), hz = __float2half_rn(z);
                int R0 = warp * 8 + 2 * p, R1 = R0 + 1;
                int i0 = R0 * 128 + (((jj >> 3) ^ (R0 & 7)) << 3) + (jj & 7);
                int i1 = R1 * 128 + (((jj >> 3) ^ (R1 & 7)) << 3) + (jj & 7);
                sAh[i0] = hx; sAh[i1] = hz;
                sAl[i0] = __float2half_rn(x - __half2float(hx));
                sAl[i1] = __float2half_rn(z - __half2float(hz));
            }
        }
        __syncthreads();

        // Cooperative W2 fwd: each warp computes all 64 rows x its 16-col slice.
        {
            float D[4][2][4];
#pragma unroll
            for (int mt = 0; mt < 4; mt++)
#pragma unroll
                for (int n = 0; n < 2; n++)
#pragma unroll
                    for (int q = 0; q < 4; q++) D[mt][n][q] = 0.f;
#pragma unroll 1
            for (int kt = 0; kt < 8; kt++) {
                int jr = kt * 16 + (lane & 15);
                u32 broff = (u32)(jr * 256);
                int js = jr & 7;
                u32 bw0[2], bw1[2], be0[2], be1[2];
#pragma unroll
                for (int n = 0; n < 2; n++) {
                    u32 off = broff + (u32)((((ntg0 + n) ^ js) & 15) << 4);
                    ldsm2t(waU + off, bw0[n], bw1[n]);
                    ldsm2t(weU + off, be0[n], be1[n]);
                }
#pragma unroll
                for (int mt = 0; mt < 4; mt++) {
                    int row = mt * 16 + (lane & 15);
                    u32 pch = (u32)((((kt * 2 + (lane >> 4)) ^ (lane & 7))) << 4);
                    u32 ro = (u32)(row * 256) + pch;
                    u32 a0, a1, a2, a3, e0, e1, e2, e3;
                    ldsm4(ahU + ro, a0, a1, a2, a3);
                    ldsm4(alU + ro, e0, e1, e2, e3);
#pragma unroll
                    for (int n = 0; n < 2; n++) {
                        mma16816(D[mt][n][0], D[mt][n][1], D[mt][n][2], D[mt][n][3],
                                 a0, a1, a2, a3, bw0[n], bw1[n]);
                        mma16816(D[mt][n][0], D[mt][n][1], D[mt][n][2], D[mt][n][3],
                                 e0, e1, e2, e3, bw0[n], bw1[n]);
                        mma16816(D[mt][n][0], D[mt][n][1], D[mt][n][2], D[mt][n][3],
                                 a0, a1, a2, a3, be0[n], be1[n]);
                    }
                }
            }
            // signs -> per-warp u16 slices (rows mt*16 + lane>>2 and +8)
#pragma unroll
            for (int mt = 0; mt < 4; mt++) {
                u32 v = 0;
#pragma unroll
                for (int n = 0; n < 2; n++) {
                    int cg = (ntg0 + n) * 8 + cb, bp = n * 8 + cb;
                    if (D[mt][n][0] + sb2[cg]     > 0.f) v |= 1u << bp;
                    if (D[mt][n][1] + sb2[cg + 1] > 0.f) v |= 1u << (bp + 1);
                    if (D[mt][n][2] + sb2[cg]     > 0.f) v |= 1u << (16 + bp);
                    if (D[mt][n][3] + sb2[cg + 1] > 0.f) v |= 1u << (16 + bp + 1);
                }
                v |= __shfl_xor_sync(0xffffffffu, v, 1);
                v |= __shfl_xor_sync(0xffffffffu, v, 2);
                if ((lane & 3) == 0) {
                    int Ra = mt * 16 + (lane >> 2);
                    sM2v[Ra * 8 + warp]       = (u16)(v & 0xffff);
                    sM2v[(Ra + 8) * 8 + warp] = (u16)(v >> 16);
                }
            }
        }
        __syncthreads();
        // assemble 128-bit row masks: word wd covers cols 32wd..32wd+31
        {
            int row = tid >> 2, wd = tid & 3;
            u32 lo = sM2v[row * 8 + wd * 2], hi = sM2v[row * 8 + wd * 2 + 1];
            sM2w[row * 4 + wd] = lo | (hi << 16);
        }

        // logits partials, warp reduce, softmax -> dlogits
        u64 lg[4][4];
#pragma unroll
        for (int k = 0; k < 4; k++)
#pragma unroll
            for (int p = 0; p < 4; p++) lg[k][p] = 0ull;
#pragma unroll
        for (int m = 0; m < 4; m++) {
            float4 t2 = *reinterpret_cast<const float4*>(&sT2[(lane + 32 * m) * 4]);
#pragma unroll
            for (int p = 0; p < 4; p++) {
                float ux, uz; up2(U[m][p], ux, uz);
                float ax = ux * __fdividef(1.f, 1.f + __expf(-ux));
                float az = uz * __fdividef(1.f, 1.f + __expf(-uz));
                u64 a2 = pk2(ax, az);
                lg[0][p] = ffma2(a2, pks(t2.x), lg[0][p]);
                lg[1][p] = ffma2(a2, pks(t2.y), lg[1][p]);
                lg[2][p] = ffma2(a2, pks(t2.z), lg[2][p]);
                lg[3][p] = ffma2(a2, pks(t2.w), lg[3][p]);
            }
        }
#pragma unroll
        for (int off = 16; off > 0; off >>= 1)
#pragma unroll
            for (int k = 0; k < 4; k++)
#pragma unroll
                for (int p = 0; p < 4; p++)
                    lg[k][p] = fadd2(lg[k][p], __shfl_xor_sync(0xffffffffu, lg[k][p], off));

        u64 dl[4][4];
#pragma unroll
        for (int p = 0; p < 4; p++) {
            float l0[4], l1[4];
#pragma unroll
            for (int k = 0; k < 4; k++) {
                float x, z; up2(lg[k][p], x, z);
                l0[k] = x + st2b[k]; l1[k] = z + st2b[k];
            }
            float dlo[4], dhi[4];
            {
                float mx = fmaxf(fmaxf(l0[0], l0[1]), fmaxf(l0[2], l0[3]));
                float e0 = __expf(l0[0] - mx), e1 = __expf(l0[1] - mx);
                float e2 = __expf(l0[2] - mx), e3 = __expf(l0[3] - mx);
                float sw = svf[2 * p]; int tc = tci[2 * p];
                float inv = sw * __fdividef(1.f, e0 + e1 + e2 + e3);
                dlo[0] = e0 * inv - (tc == 0 ? sw : 0.f);
                dlo[1] = e1 * inv - (tc == 1 ? sw : 0.f);
                dlo[2] = e2 * inv - (tc == 2 ? sw : 0.f);
                dlo[3] = e3 * inv - (tc == 3 ? sw : 0.f);
            }
            {
                float mx = fmaxf(fmaxf(l1[0], l1[1]), fmaxf(l1[2], l1[3]));
                float e0 = __expf(l1[0] - mx), e1 = __expf(l1[1] - mx);
                float e2 = __expf(l1[2] - mx), e3 = __expf(l1[3] - mx);
                float sw = svf[2 * p + 1]; int tc = tci[2 * p + 1];
                float inv = sw * __fdividef(1.f, e0 + e1 + e2 + e3);
                dhi[0] = e0 * inv - (tc == 0 ? sw : 0.f);
                dhi[1] = e1 * inv - (tc == 1 ? sw : 0.f);
                dhi[2] = e2 * inv - (tc == 2 ? sw : 0.f);
                dhi[3] = e3 * inv - (tc == 3 ? sw : 0.f);
            }
#pragma unroll
            for (int k = 0; k < 4; k++) dl[k][p] = pk2(dlo[k], dhi[k]);
        }

        // du = (tr2w @ dl) * silu'(u) -> private scr (sA region dead for this warp)
        __syncwarp();
#pragma unroll
        for (int m = 0; m < 4; m++) {
            int jj = lane + 32 * m;
            float4 t2 = *reinterpret_cast<const float4*>(&sT2[jj * 4]);
            u64 dv[4];
#pragma unroll
            for (int p = 0; p < 4; p++) {
                u64 da = fmul2(dl[0][p], pks(t2.x));
                da = ffma2(dl[1][p], pks(t2.y), da);
                da = ffma2(dl[2][p], pks(t2.z), da);
                da = ffma2(dl[3][p], pks(t2.w), da);
                float ux, uz; up2(U[m][p], ux, uz);
                float sgx = __fdividef(1.f, 1.f + __expf(-ux));
                float sgz = __fdividef(1.f, 1.f + __expf(-uz));
                dv[p] = fmul2(da, pk2(sgx * (1.f + ux * (1.f - sgx)),
                                      sgz * (1.f + uz * (1.f - sgz))));
            }
            st8(scr, jj, dv[0], dv[1], dv[2], dv[3]);
        }
        __syncthreads();   // sM2w visible; all warps past mma reads

        // gy = 2*REG*y + P[lane,:] . du
        u64 gy[4];
#pragma unroll
        for (int p = 0; p < 4; p++) gy[p] = fmul2(pks(2.f * C_REG), y[p]);
#pragma unroll 4
        for (int k = 0; k < 128; k++) {
            u64 b0, b1, b2, b3; ld8(scr, k, b0, b1, b2, b3);
            u64 w = pks(sP[lane * 128 + (k & 96) + ((k & 31) ^ lane)]);
            gy[0] = ffma2(b0, w, gy[0]); gy[1] = ffma2(b1, w, gy[1]);
            gy[2] = ffma2(b2, w, gy[2]); gy[3] = ffma2(b3, w, gy[3]);
        }

        // energy bwd: dh2pre = (h2>0 via sM2w) * e_w3[:, tci]
        __syncwarp();
#pragma unroll
        for (int m = 0; m < 4; m++) {
            int jj = lane + 32 * m;
            u64 dv[4];
#pragma unroll
            for (int p = 0; p < 4; p++) {
                u32 w0 = sM2w[(warp * 8 + 2 * p) * 4 + m];
                u32 w1 = sM2w[(warp * 8 + 2 * p + 1) * 4 + m];
                float e0 = ((w0 >> lane) & 1u) ? sE3T[tci[2 * p] * 128 + jj]     : 0.f;
                float e1 = ((w1 >> lane) & 1u) ? sE3T[tci[2 * p + 1] * 128 + jj] : 0.f;
                dv[p] = pk2(e0, e1);
            }
            st8(scr, jj, dv[0], dv[1], dv[2], dv[3]);
        }
        __syncwarp();

        // W2 bwd (exact fp32): dh1 masked by h1>0
        u64 D2[4][4];
#pragma unroll
        for (int m = 0; m < 4; m++)
#pragma unroll
            for (int p = 0; p < 4; p++) D2[m][p] = 0ull;
#pragma unroll 4
        for (int k = 0; k < 128; k++) {
            u64 b0, b1, b2, b3; ld8(scr, k, b0, b1, b2, b3);
            int off = (k & 96) + ((k & 31) ^ lane);
#pragma unroll
            for (int m = 0; m < 4; m++) {
                u64 w = pks(sW2[(lane + 32 * m) * 128 + off]);
                D2[m][0] = ffma2(b0, w, D2[m][0]); D2[m][1] = ffma2(b1, w, D2[m][1]);
                D2[m][2] = ffma2(b2, w, D2[m][2]); D2[m][3] = ffma2(b3, w, D2[m][3]);
            }
        }
#pragma unroll
        for (int m = 0; m < 4; m++)
#pragma unroll
            for (int p = 0; p < 4; p++) {
                float x, z; up2(D2[m][p], x, z);
                x = ((m1 >> (m * 8 + 2 * p)) & 1)     ? x : 0.f;
                z = ((m1 >> (m * 8 + 2 * p + 1)) & 1) ? z : 0.f;
                D2[m][p] = pk2(x, z);
            }
        __syncwarp();
#pragma unroll
        for (int m = 0; m < 4; m++) st8(scr, lane + 32 * m, D2[m][0], D2[m][1], D2[m][2], D2[m][3]);
        __syncwarp();

        // gy += E1y[lane,:] . dh1pre
#pragma unroll 4
        for (int j = 0; j < 128; j++) {
            u64 b0, b1, b2, b3; ld8(scr, j, b0, b1, b2, b3);
            u64 w = pks(sE1y[lane * 128 + (j & 96) + ((j & 31) ^ lane)]);
            gy[0] = ffma2(b0, w, gy[0]); gy[1] = ffma2(b1, w, gy[1]);
            gy[2] = ffma2(b2, w, gy[2]); gy[3] = ffma2(b3, w, gy[3]);
        }

#pragma unroll
        for (int p = 0; p < 4; p++) y[p] = ffma2(gy[p], pks(-C_LR), y[p]);
    }

#pragma unroll
    for (int p = 0; p < 4; p++) {
        float a, b; up2(y[p], a, b);
        out[(r0 + 2 * p) * NDY + lane] = a;
        out[(r0 + 2 * p + 1) * NDY + lane] = b;
    }
}

extern "C" void kernel_launch(void* const* d_in, const int* in_sizes, int n_in,
                              void* d_out, int out_size) {
    const float* x      = (const float*)d_in[0];
    const int*   t      = (const int*)d_in[1];
    const float* e_w1   = (const float*)d_in[2];
    const float* e_b1   = (const float*)d_in[3];
    const float* e_w2   = (const float*)d_in[4];
    const float* e_b2   = (const float*)d_in[5];
    const float* e_w3   = (const float*)d_in[6];
    const float* s_xw   = (const float*)d_in[8];
    const float* s_xb   = (const float*)d_in[9];
    const float* s_yw   = (const float*)d_in[10];
    const float* s_yb   = (const float*)d_in[11];
    const float* s_temb = (const float*)d_in[12];
    const float* s_t1w  = (const float*)d_in[13];
    const float* s_t1b  = (const float*)d_in[14];
    const float* s_t2w  = (const float*)d_in[15];
    const float* s_t2b  = (const float*)d_in[16];
    const float* tr1w   = (const float*)d_in[17];
    const float* tr1b   = (const float*)d_in[18];
    const float* tr2w   = (const float*)d_in[19];
    const float* tr2b   = (const float*)d_in[20];
    const int*   steps  = (const int*)d_in[21];
    float* out = (float*)d_out;

    float *p_hxe, *p_hxs, *p_c, *p_cth;
    cudaGetSymbolAddress((void**)&p_hxe, g_hxe);
    cudaGetSymbolAddress((void**)&p_hxs, g_hxs);
    cudaGetSymbolAddress((void**)&p_c,   g_c);
    cudaGetSymbolAddress((void**)&p_cth, g_cth);

    cth_kernel<<<1, NH>>>(s_temb, s_t1w, s_t1b, s_t2w, s_t2b, tr1w, tr1b);
    p_kernel<<<NDY, NH>>>(s_yw, s_yb, tr1w);
    gemm128_dual_kernel<<<NB / 64, 256>>>(x, NDX, NDX, e_w1, e_b1, s_xw, s_xb, p_hxe, p_hxs);
    gemm128_kernel<<<NB / 64, 256>>>(p_hxs, NH, NH, tr1w, nullptr, p_cth, t, p_c);

    cudaFuncSetAttribute(edi_main_kernel, cudaFuncAttributeMaxDynamicSharedMemorySize, SMEM_BYTES);
    edi_main_kernel<<<NB / 64, 256, SMEM_BYTES>>>(t, e_w1, e_w2, e_b2, e_w3,
                                                  tr2w, tr2b, steps, out);
}

// round 15
// speedup vs baseline: 3.2230x; 1.1795x over previous
#include <cuda_runtime.h>
#include <cuda_fp16.h>
typedef unsigned long long u64;
typedef unsigned int u32;
typedef unsigned short u16;

#define NB   131072
#define NDX  256
#define NDY  32
#define NK   4
#define NH   128
#define C_LR  0.1f
#define C_REG 0.01f
#define C_SW  1.0f

__device__ float g_hxe[NB * NH];
__device__ float g_hxs[NB * NH];
__device__ float g_c[NB * NH];
__device__ float g_cth[NK * NH];
__device__ float g_P[NDY * NH];

__device__ __forceinline__ u64 pk2(float x, float y) {
    u64 r; asm("mov.b64 %0, {%1,%2};" : "=l"(r) : "f"(x), "f"(y)); return r;
}
__device__ __forceinline__ u64 pks(float x) {
    u64 r; asm("mov.b64 %0, {%1,%1};" : "=l"(r) : "f"(x)); return r;
}
__device__ __forceinline__ void up2(u64 v, float& x, float& y) {
    asm("mov.b64 {%0,%1}, %2;" : "=f"(x), "=f"(y) : "l"(v));
}
__device__ __forceinline__ u64 ffma2(u64 a, u64 b, u64 c) {
    u64 d; asm("fma.rn.f32x2 %0, %1, %2, %3;" : "=l"(d) : "l"(a), "l"(b), "l"(c)); return d;
}
__device__ __forceinline__ u64 fmul2(u64 a, u64 b) {
    u64 d; asm("mul.rn.f32x2 %0, %1, %2;" : "=l"(d) : "l"(a), "l"(b)); return d;
}
__device__ __forceinline__ u64 fadd2(u64 a, u64 b) {
    u64 d; asm("add.rn.f32x2 %0, %1, %2;" : "=l"(d) : "l"(a), "l"(b)); return d;
}
__device__ __forceinline__ u32 smemu(const void* p) {
    return (u32)__cvta_generic_to_shared(p);
}
__device__ __forceinline__ void ldsm4(u32 a, u32& r0, u32& r1, u32& r2, u32& r3) {
    asm volatile("ldmatrix.sync.aligned.m8n8.x4.shared.b16 {%0,%1,%2,%3}, [%4];"
                 : "=r"(r0), "=r"(r1), "=r"(r2), "=r"(r3) : "r"(a));
}
__device__ __forceinline__ void ldsm2t(u32 a, u32& r0, u32& r1) {
    asm volatile("ldmatrix.sync.aligned.m8n8.x2.trans.shared.b16 {%0,%1}, [%2];"
                 : "=r"(r0), "=r"(r1) : "r"(a));
}
__device__ __forceinline__ void mma16816(float& d0, float& d1, float& d2, float& d3,
                                         u32 a0, u32 a1, u32 a2, u32 a3, u32 b0, u32 b1) {
    asm volatile("mma.sync.aligned.m16n8k16.row.col.f32.f16.f16.f32 "
                 "{%0,%1,%2,%3},{%4,%5,%6,%7},{%8,%9},{%0,%1,%2,%3};"
                 : "+f"(d0), "+f"(d1), "+f"(d2), "+f"(d3)
                 : "r"(a0), "r"(a1), "r"(a2), "r"(a3), "r"(b0), "r"(b1));
}
__device__ __forceinline__ void st8(float* scr, int j, u64 v0, u64 v1, u64 v2, u64 v3) {
    *reinterpret_cast<ulonglong2*>(scr + j * 4)       = make_ulonglong2(v0, v1);
    *reinterpret_cast<ulonglong2*>(scr + 512 + j * 4) = make_ulonglong2(v2, v3);
}
__device__ __forceinline__ void ld8(const float* scr, int j, u64& v0, u64& v1, u64& v2, u64& v3) {
    ulonglong2 a = *reinterpret_cast<const ulonglong2*>(scr + j * 4);
    ulonglong2 b = *reinterpret_cast<const ulonglong2*>(scr + 512 + j * 4);
    v0 = a.x; v1 = a.y; v2 = b.x; v3 = b.y;
}

__global__ void cth_kernel(const float* __restrict__ s_temb, const float* __restrict__ s_t1w,
                           const float* __restrict__ s_t1b, const float* __restrict__ s_t2w,
                           const float* __restrict__ s_t2b, const float* __restrict__ tr1w,
                           const float* __restrict__ tr1b) {
    int j = threadIdx.x;
    __shared__ float v[NH], th[NH];
    for (int k = 0; k < NK; k++) {
        float tau = fmaxf((float)k / 1000.0f, 1e-6f);
        float z = tau * s_t1w[j] + s_t1b[j];
        v[j] = z / (1.0f + expf(-z));
        __syncthreads();
        float acc = s_t2b[j];
        for (int q = 0; q < NH; q++) acc += v[q] * s_t2w[q * NH + j];
        th[j] = acc;
        __syncthreads();
        float c = tr1b[j];
        for (int q = 0; q < NH; q++) {
            c += s_temb[k * NH + q] * tr1w[(2 * NH + q) * NH + j];
            c += th[q] * tr1w[(3 * NH + q) * NH + j];
        }
        g_cth[k * NH + j] = c;
        __syncthreads();
    }
}

__global__ void p_kernel(const float* __restrict__ s_yw, const float* __restrict__ s_yb,
                         const float* __restrict__ tr1w) {
    int k = threadIdx.x, d = blockIdx.x;
    float acc = 0.0f;
    for (int j = 0; j < NH; j++) acc += s_yw[d * NH + j] * tr1w[(NH + j) * NH + k];
    g_P[d * NH + k] = acc;
    if (d == 0) {
        float bp = 0.0f;
        for (int j = 0; j < NH; j++) bp += s_yb[j] * tr1w[(NH + j) * NH + k];
        for (int c = 0; c < NK; c++) g_cth[c * NH + k] += bp;
    }
}

__global__ __launch_bounds__(256)
void gemm128_kernel(const float* __restrict__ X, int ldx, int Kdim,
                    const float* __restrict__ Wm, const float* __restrict__ bias,
                    const float* __restrict__ table, const int* __restrict__ tt,
                    float* __restrict__ out) {
    __shared__ float Xs[64 * 33];
    __shared__ float Ws[32 * 128];
    int tid = threadIdx.x, tcol = tid & 31, trow = tid >> 5, m0 = blockIdx.x * 64;
    float acc[8][4];
#pragma unroll
    for (int p = 0; p < 8; p++)
#pragma unroll
        for (int q = 0; q < 4; q++) acc[p][q] = 0.0f;
    for (int k0 = 0; k0 < Kdim; k0 += 32) {
#pragma unroll
        for (int i = 0; i < 8; i++) {
            int e = tid + 256 * i;
            Xs[(e >> 5) * 33 + (e & 31)] = X[(m0 + (e >> 5)) * ldx + k0 + (e & 31)];
        }
#pragma unroll
        for (int i = 0; i < 16; i++) {
            int e = tid + 256 * i;
            Ws[(e >> 7) * 128 + (e & 127)] = Wm[(k0 + (e >> 7)) * NH + (e & 127)];
        }
        __syncthreads();
#pragma unroll 8
        for (int kk = 0; kk < 32; kk++) {
            float xv[8], wv[4];
#pragma unroll
            for (int p = 0; p < 8; p++) xv[p] = Xs[(trow + 8 * p) * 33 + kk];
#pragma unroll
            for (int q = 0; q < 4; q++) wv[q] = Ws[kk * 128 + tcol + 32 * q];
#pragma unroll
            for (int p = 0; p < 8; p++)
#pragma unroll
                for (int q = 0; q < 4; q++) acc[p][q] += xv[p] * wv[q];
        }
        __syncthreads();
    }
#pragma unroll
    for (int p = 0; p < 8; p++) {
        int m = m0 + trow + 8 * p;
        int tc = 0;
        if (table) { int tv = tt[m]; tc = tv > 0 ? tv : 0; }
#pragma unroll
        for (int q = 0; q < 4; q++) {
            int n = tcol + 32 * q;
            float vv = acc[p][q];
            if (bias)  vv += bias[n];
            if (table) vv += table[tc * NH + n];
            out[m * NH + n] = vv;
        }
    }
}

__global__ __launch_bounds__(256)
void gemm128_dual_kernel(const float* __restrict__ X, int ldx, int Kdim,
                         const float* __restrict__ W0, const float* __restrict__ b0v,
                         const float* __restrict__ W1, const float* __restrict__ b1v,
                         float* __restrict__ out0, float* __restrict__ out1) {
    __shared__ float Xs[64 * 33];
    __shared__ float Ws0[32 * 128];
    __shared__ float Ws1[32 * 128];
    int tid = threadIdx.x, tcol = tid & 31, trow = tid >> 5, m0 = blockIdx.x * 64;
    float a0[8][4], a1[8][4];
#pragma unroll
    for (int p = 0; p < 8; p++)
#pragma unroll
        for (int q = 0; q < 4; q++) { a0[p][q] = 0.0f; a1[p][q] = 0.0f; }
    for (int k0 = 0; k0 < Kdim; k0 += 32) {
#pragma unroll
        for (int i = 0; i < 8; i++) {
            int e = tid + 256 * i;
            Xs[(e >> 5) * 33 + (e & 31)] = X[(m0 + (e >> 5)) * ldx + k0 + (e & 31)];
        }
#pragma unroll
        for (int i = 0; i < 16; i++) {
            int e = tid + 256 * i;
            Ws0[(e >> 7) * 128 + (e & 127)] = W0[(k0 + (e >> 7)) * NH + (e & 127)];
            Ws1[(e >> 7) * 128 + (e & 127)] = W1[(k0 + (e >> 7)) * NH + (e & 127)];
        }
        __syncthreads();
#pragma unroll 4
        for (int kk = 0; kk < 32; kk++) {
            float xv[8], w0[4], w1[4];
#pragma unroll
            for (int p = 0; p < 8; p++) xv[p] = Xs[(trow + 8 * p) * 33 + kk];
#pragma unroll
            for (int q = 0; q < 4; q++) { w0[q] = Ws0[kk * 128 + tcol + 32 * q]; w1[q] = Ws1[kk * 128 + tcol + 32 * q]; }
#pragma unroll
            for (int p = 0; p < 8; p++)
#pragma unroll
                for (int q = 0; q < 4; q++) { a0[p][q] += xv[p] * w0[q]; a1[p][q] += xv[p] * w1[q]; }
        }
        __syncthreads();
    }
#pragma unroll
    for (int p = 0; p < 8; p++) {
        int m = m0 + trow + 8 * p;
#pragma unroll
        for (int q = 0; q < 4; q++) {
            int n = tcol + 32 * q;
            out0[m * NH + n] = a0[p][q] + b0v[n];
            out1[m * NH + n] = a1[p][q] + b1v[n];
        }
    }
}

// SMEM float-slot offsets
#define OFF_E1Y  0
#define OFF_PM   4096
#define OFF_E3T  8192
#define OFF_T2   8704
#define OFF_B2   9216
#define OFF_T2B  9344
#define OFF_M2V  9352
#define OFF_M2W  9608
#define OFF_M1W  9864
#define OFF_WA   10120
#define OFF_WE   18312
#define OFF_SCR  26504
#define SMEM_FLOATS (OFF_SCR + 8 * 1024)
#define SMEM_BYTES  (SMEM_FLOATS * 4)

__global__ __launch_bounds__(256, 1)
void edi_main_kernel(const int* __restrict__ t, const float* __restrict__ e_w1,
                     const float* __restrict__ e_w2, const float* __restrict__ e_b2,
                     const float* __restrict__ e_w3, const float* __restrict__ tr2w,
                     const float* __restrict__ tr2b, const int* __restrict__ steps_p,
                     float* __restrict__ out) {
    extern __shared__ float sm[];
    float*  sE1y = sm + OFF_E1Y;
    float*  sP   = sm + OFF_PM;
    float*  sE3T = sm + OFF_E3T;
    float*  sT2  = sm + OFF_T2;
    float*  sb2  = sm + OFF_B2;
    float*  st2b = sm + OFF_T2B;
    u16*    sM2v = (u16*)(sm + OFF_M2V);
    u32*    sM2w = (u32*)(sm + OFF_M2W);
    u32*    sM1w = (u32*)(sm + OFF_M1W);
    __half* sWa  = (__half*)(sm + OFF_WA);
    __half* sWe  = (__half*)(sm + OFF_WE);
    float*  sscr = sm + OFF_SCR;
    __half* sAh  = (__half*)sscr;
    __half* sAl  = (__half*)(sscr + 4096);

    int tid = threadIdx.x;
    for (int idx = tid; idx < 32 * 128; idx += 256) {
        int d = idx >> 7, k = idx & 127;
        int swi = d * 128 + (k & 96) + ((k & 31) ^ d);
        sE1y[swi] = e_w1[(NDX + d) * NH + k];
        sP[swi]   = g_P[idx];
    }
    for (int idx = tid; idx < 128 * 128; idx += 256) {
        int j = idx >> 7, c = idx & 127;
        float w = e_w2[idx];
        __half ha = __float2half_rn(w);
        int hp = j * 128 + (((c >> 3) ^ (j & 7)) << 3) + (c & 7);
        sWa[hp] = ha;
        sWe[hp] = __float2half_rn(w - __half2float(ha));
    }
    for (int idx = tid; idx < 512; idx += 256) {
        sE3T[(idx & 3) * 128 + (idx >> 2)] = e_w3[idx];
        sT2[idx] = tr2w[idx];
    }
    if (tid < 128) sb2[tid] = e_b2[tid];
    if (tid < 4)   st2b[tid] = tr2b[tid];
    __syncthreads();

    const int lane = tid & 31;
    const int warp = tid >> 5;
    float* scr = sscr + warp * 1024;
    const int r0 = (blockIdx.x * 8 + warp) * 8;
    const int nsteps = *steps_p;
    const u32 waU = smemu(sWa);
    const u32 weU = smemu(sWe);
    const u32 ahU = smemu(sAh);
    const u32 alU = smemu(sAl);
    const int cb = 2 * (lane & 3);
    const int ntg0 = 2 * warp;

    int tci[8]; float svf[8];
#pragma unroll
    for (int r = 0; r < 8; r++) {
        int tv = t[r0 + r];
        tci[r] = tv > 0 ? tv : 0;
        svf[r] = tv >= 0 ? C_SW : 0.0f;
    }

    u64 y[4] = {0ull, 0ull, 0ull, 0ull};
    u64 hxe[4][4], cc[4][4];
#pragma unroll
    for (int m = 0; m < 4; m++)
#pragma unroll
        for (int p = 0; p < 4; p++) {
            int col = 32 * m + lane;
            hxe[m][p] = pk2(g_hxe[(r0 + 2 * p) * NH + col], g_hxe[(r0 + 2 * p + 1) * NH + col]);
            cc[m][p]  = pk2(g_c[(r0 + 2 * p) * NH + col],   g_c[(r0 + 2 * p + 1) * NH + col]);
        }

    for (int s = 0; s < nsteps; s++) {
        __syncwarp();
        st8(scr, lane, y[0], y[1], y[2], y[3]);
        __syncwarp();

        // fused fwd: h1pre = hxe + y@E1y ; u = cc + y@P
        u64 A[4][4], U[4][4];
#pragma unroll
        for (int m = 0; m < 4; m++)
#pragma unroll
            for (int p = 0; p < 4; p++) { A[m][p] = hxe[m][p]; U[m][p] = cc[m][p]; }
#pragma unroll 4
        for (int d = 0; d < 32; d++) {
            u64 b0, b1, b2, b3; ld8(scr, d, b0, b1, b2, b3);
            int base = d * 128 + (lane ^ d);
#pragma unroll
            for (int m = 0; m < 4; m++) {
                u64 w = pks(sE1y[base + 32 * m]);
                A[m][0] = ffma2(b0, w, A[m][0]); A[m][1] = ffma2(b1, w, A[m][1]);
                A[m][2] = ffma2(b2, w, A[m][2]); A[m][3] = ffma2(b3, w, A[m][3]);
                u64 v = pks(sP[base + 32 * m]);
                U[m][0] = ffma2(b0, v, U[m][0]); U[m][1] = ffma2(b1, v, U[m][1]);
                U[m][2] = ffma2(b2, v, U[m][2]); U[m][3] = ffma2(b3, v, U[m][3]);
            }
        }
        unsigned m1 = 0;
#pragma unroll
        for (int m = 0; m < 4; m++)
#pragma unroll
            for (int p = 0; p < 4; p++) {
                float x, z; up2(A[m][p], x, z);
                m1 |= (x > 0.f ? 1u : 0u) << (m * 8 + 2 * p);
                m1 |= (z > 0.f ? 1u : 0u) << (m * 8 + 2 * p + 1);
                A[m][p] = pk2(fmaxf(x, 0.f), fmaxf(z, 0.f));
            }
        // h1 relu mask -> CTA table sM1w[row][word]: 32 ballots, lane i keeps (r=i>>2, m=i&3)
        {
            u32 mword = 0;
#pragma unroll
            for (int i = 0; i < 32; i++) {
                u32 b = __ballot_sync(0xffffffffu, (m1 >> (((i & 3) * 8) + (i >> 2))) & 1u);
                if (lane == i) mword = b;
            }
            sM1w[(warp * 8 + (lane >> 2)) * 4 + (lane & 3)] = mword;
        }

        __syncthreads();
        // CTA-wide split-fp16 staging of relu(h1)
#pragma unroll
        for (int m = 0; m < 4; m++) {
            int jj = lane + 32 * m;
#pragma unroll
            for (int p = 0; p < 4; p++) {
                float x, z; up2(A[m][p], x, z);
                __half hx = __float2half_rn(x), hz = __float2half_rn(z);
                int R0 = warp * 8 + 2 * p, R1 = R0 + 1;
                int i0 = R0 * 128 + (((jj >> 3) ^ (R0 & 7)) << 3) + (jj & 7);
                int i1 = R1 * 128 + (((jj >> 3) ^ (R1 & 7)) << 3) + (jj & 7);
                sAh[i0] = hx; sAh[i1] = hz;
                sAl[i0] = __float2half_rn(x - __half2float(hx));
                sAl[i1] = __float2half_rn(z - __half2float(hz));
            }
        }
        __syncthreads();

        // Cooperative W2 fwd (mask-only): each warp does 64 rows x its 16-col slice
        {
            float D[4][2][4];
#pragma unroll
            for (int mt = 0; mt < 4; mt++)
#pragma unroll
                for (int n = 0; n < 2; n++)
#pragma unroll
                    for (int q = 0; q < 4; q++) D[mt][n][q] = 0.f;
#pragma unroll 1
            for (int kt = 0; kt < 8; kt++) {
                int jr = kt * 16 + (lane & 15);
                u32 broff = (u32)(jr * 256);
                int js = jr & 7;
                u32 bw0[2], bw1[2], be0[2], be1[2];
#pragma unroll
                for (int n = 0; n < 2; n++) {
                    u32 off = broff + (u32)((((ntg0 + n) ^ js) & 15) << 4);
                    ldsm2t(waU + off, bw0[n], bw1[n]);
                    ldsm2t(weU + off, be0[n], be1[n]);
                }
#pragma unroll
                for (int mt = 0; mt < 4; mt++) {
                    int row = mt * 16 + (lane & 15);
                    u32 pch = (u32)((((kt * 2 + (lane >> 4)) ^ (lane & 7))) << 4);
                    u32 ro = (u32)(row * 256) + pch;
                    u32 a0, a1, a2, a3, e0, e1, e2, e3;
                    ldsm4(ahU + ro, a0, a1, a2, a3);
                    ldsm4(alU + ro, e0, e1, e2, e3);
#pragma unroll
                    for (int n = 0; n < 2; n++) {
                        mma16816(D[mt][n][0], D[mt][n][1], D[mt][n][2], D[mt][n][3],
                                 a0, a1, a2, a3, bw0[n], bw1[n]);
                        mma16816(D[mt][n][0], D[mt][n][1], D[mt][n][2], D[mt][n][3],
                                 e0, e1, e2, e3, bw0[n], bw1[n]);
                        mma16816(D[mt][n][0], D[mt][n][1], D[mt][n][2], D[mt][n][3],
                                 a0, a1, a2, a3, be0[n], be1[n]);
                    }
                }
            }
#pragma unroll
            for (int mt = 0; mt < 4; mt++) {
                u32 v = 0;
#pragma unroll
                for (int n = 0; n < 2; n++) {
                    int cg = (ntg0 + n) * 8 + cb, bp = n * 8 + cb;
                    if (D[mt][n][0] + sb2[cg]     > 0.f) v |= 1u << bp;
                    if (D[mt][n][1] + sb2[cg + 1] > 0.f) v |= 1u << (bp + 1);
                    if (D[mt][n][2] + sb2[cg]     > 0.f) v |= 1u << (16 + bp);
                    if (D[mt][n][3] + sb2[cg + 1] > 0.f) v |= 1u << (16 + bp + 1);
                }
                v |= __shfl_xor_sync(0xffffffffu, v, 1);
                v |= __shfl_xor_sync(0xffffffffu, v, 2);
                if ((lane & 3) == 0) {
                    int Ra = mt * 16 + (lane >> 2);
                    sM2v[Ra * 8 + warp]       = (u16)(v & 0xffff);
                    sM2v[(Ra + 8) * 8 + warp] = (u16)(v >> 16);
                }
            }
        }
        __syncthreads();
        {
            int row = tid >> 2, wd = tid & 3;
            u32 lo = sM2v[row * 8 + wd * 2], hi = sM2v[row * 8 + wd * 2 + 1];
            sM2w[row * 4 + wd] = lo | (hi << 16);
        }

        // logits, softmax -> dlogits
        u64 lg[4][4];
#pragma unroll
        for (int k = 0; k < 4; k++)
#pragma unroll
            for (int p = 0; p < 4; p++) lg[k][p] = 0ull;
#pragma unroll
        for (int m = 0; m < 4; m++) {
            float4 t2 = *reinterpret_cast<const float4*>(&sT2[(lane + 32 * m) * 4]);
#pragma unroll
            for (int p = 0; p < 4; p++) {
                float ux, uz; up2(U[m][p], ux, uz);
                float ax = ux * __fdividef(1.f, 1.f + __expf(-ux));
                float az = uz * __fdividef(1.f, 1.f + __expf(-uz));
                u64 a2 = pk2(ax, az);
                lg[0][p] = ffma2(a2, pks(t2.x), lg[0][p]);
                lg[1][p] = ffma2(a2, pks(t2.y), lg[1][p]);
                lg[2][p] = ffma2(a2, pks(t2.z), lg[2][p]);
                lg[3][p] = ffma2(a2, pks(t2.w), lg[3][p]);
            }
        }
#pragma unroll
        for (int off = 16; off > 0; off >>= 1)
#pragma unroll
            for (int k = 0; k < 4; k++)
#pragma unroll
                for (int p = 0; p < 4; p++)
                    lg[k][p] = fadd2(lg[k][p], __shfl_xor_sync(0xffffffffu, lg[k][p], off));

        u64 dl[4][4];
#pragma unroll
        for (int p = 0; p < 4; p++) {
            float l0[4], l1[4];
#pragma unroll
            for (int k = 0; k < 4; k++) {
                float x, z; up2(lg[k][p], x, z);
                l0[k] = x + st2b[k]; l1[k] = z + st2b[k];
            }
            float dlo[4], dhi[4];
            {
                float mx = fmaxf(fmaxf(l0[0], l0[1]), fmaxf(l0[2], l0[3]));
                float e0 = __expf(l0[0] - mx), e1 = __expf(l0[1] - mx);
                float e2 = __expf(l0[2] - mx), e3 = __expf(l0[3] - mx);
                float sw = svf[2 * p]; int tc = tci[2 * p];
                float inv = sw * __fdividef(1.f, e0 + e1 + e2 + e3);
                dlo[0] = e0 * inv - (tc == 0 ? sw : 0.f);
                dlo[1] = e1 * inv - (tc == 1 ? sw : 0.f);
                dlo[2] = e2 * inv - (tc == 2 ? sw : 0.f);
                dlo[3] = e3 * inv - (tc == 3 ? sw : 0.f);
            }
            {
                float mx = fmaxf(fmaxf(l1[0], l1[1]), fmaxf(l1[2], l1[3]));
                float e0 = __expf(l1[0] - mx), e1 = __expf(l1[1] - mx);
                float e2 = __expf(l1[2] - mx), e3 = __expf(l1[3] - mx);
                float sw = svf[2 * p + 1]; int tc = tci[2 * p + 1];
                float inv = sw * __fdividef(1.f, e0 + e1 + e2 + e3);
                dhi[0] = e0 * inv - (tc == 0 ? sw : 0.f);
                dhi[1] = e1 * inv - (tc == 1 ? sw : 0.f);
                dhi[2] = e2 * inv - (tc == 2 ? sw : 0.f);
                dhi[3] = e3 * inv - (tc == 3 ? sw : 0.f);
            }
#pragma unroll
            for (int k = 0; k < 4; k++) dl[k][p] = pk2(dlo[k], dhi[k]);
        }

        // du = (tr2w @ dl) * silu'(u) -> own scr
        __syncwarp();
#pragma unroll
        for (int m = 0; m < 4; m++) {
            int jj = lane + 32 * m;
            float4 t2 = *reinterpret_cast<const float4*>(&sT2[jj * 4]);
            u64 dv[4];
#pragma unroll
            for (int p = 0; p < 4; p++) {
                u64 da = fmul2(dl[0][p], pks(t2.x));
                da = ffma2(dl[1][p], pks(t2.y), da);
                da = ffma2(dl[2][p], pks(t2.z), da);
                da = ffma2(dl[3][p], pks(t2.w), da);
                float ux, uz; up2(U[m][p], ux, uz);
                float sgx = __fdividef(1.f, 1.f + __expf(-ux));
                float sgz = __fdividef(1.f, 1.f + __expf(-uz));
                dv[p] = fmul2(da, pk2(sgx * (1.f + ux * (1.f - sgx)),
                                      sgz * (1.f + uz * (1.f - sgz))));
            }
            st8(scr, jj, dv[0], dv[1], dv[2], dv[3]);
        }
        __syncthreads();

        // gy = 2*REG*y + P[lane,:] . du
        u64 gy[4];
#pragma unroll
        for (int p = 0; p < 4; p++) gy[p] = fmul2(pks(2.f * C_REG), y[p]);
#pragma unroll 4
        for (int k = 0; k < 128; k++) {
            u64 b0, b1, b2, b3; ld8(scr, k, b0, b1, b2, b3);
            u64 w = pks(sP[lane * 128 + (k & 96) + ((k & 31) ^ lane)]);
            gy[0] = ffma2(b0, w, gy[0]); gy[1] = ffma2(b1, w, gy[1]);
            gy[2] = ffma2(b2, w, gy[2]); gy[3] = ffma2(b3, w, gy[3]);
        }
        __syncthreads();   // du reads done CTA-wide; scr reusable as staging

        // energy bwd: dh2pre = (h2>0 via sM2w) * e_w3[:, tci] -> split-fp16 staging
#pragma unroll
        for (int m = 0; m < 4; m++) {
            int jj = lane + 32 * m;
#pragma unroll
            for (int p = 0; p < 4; p++) {
                u32 w0 = sM2w[(warp * 8 + 2 * p) * 4 + m];
                u32 w1 = sM2w[(warp * 8 + 2 * p + 1) * 4 + m];
                float e0 = ((w0 >> lane) & 1u) ? sE3T[tci[2 * p] * 128 + jj]     : 0.f;
                float e1 = ((w1 >> lane) & 1u) ? sE3T[tci[2 * p + 1] * 128 + jj] : 0.f;
                __half h0 = __float2half_rn(e0), h1v = __float2half_rn(e1);
                int R0 = warp * 8 + 2 * p, R1 = R0 + 1;
                int i0 = R0 * 128 + (((jj >> 3) ^ (R0 & 7)) << 3) + (jj & 7);
                int i1 = R1 * 128 + (((jj >> 3) ^ (R1 & 7)) << 3) + (jj & 7);
                sAh[i0] = h0; sAh[i1] = h1v;
                sAl[i0] = __float2half_rn(e0 - __half2float(h0));
                sAl[i1] = __float2half_rn(e1 - __half2float(h1v));
            }
        }
        __syncthreads();

        // Cooperative W2 bwd: dh1 = dh2pre @ W2^T; B = W2 rows non-trans.
        {
            float D[4][2][4];
#pragma unroll
            for (int mt = 0; mt < 4; mt++)
#pragma unroll
                for (int n = 0; n < 2; n++)
#pragma unroll
                    for (int q = 0; q < 4; q++) D[mt][n][q] = 0.f;
            int jB = 16 * warp + (lane & 7) + ((lane & 16) ? 8 : 0);
#pragma unroll 1
            for (int kt = 0; kt < 8; kt++) {
                int ch = kt * 2 + ((lane >> 3) & 1);
                u32 boff = (u32)(jB * 256 + ((ch ^ (jB & 7)) << 4));
                u32 bw0, bw1, bw2, bw3, be0, be1, be2, be3;
                ldsm4(waU + boff, bw0, bw1, bw2, bw3);
                ldsm4(weU + boff, be0, be1, be2, be3);
#pragma unroll
                for (int mt = 0; mt < 4; mt++) {
                    int row = mt * 16 + (lane & 15);
                    u32 pch = (u32)((((kt * 2 + (lane >> 4)) ^ (lane & 7))) << 4);
                    u32 ro = (u32)(row * 256) + pch;
                    u32 a0, a1, a2, a3, e0, e1, e2, e3;
                    ldsm4(ahU + ro, a0, a1, a2, a3);
                    ldsm4(alU + ro, e0, e1, e2, e3);
                    mma16816(D[mt][0][0], D[mt][0][1], D[mt][0][2], D[mt][0][3],
                             a0, a1, a2, a3, bw0, bw1);
                    mma16816(D[mt][0][0], D[mt][0][1], D[mt][0][2], D[mt][0][3],
                             e0, e1, e2, e3, bw0, bw1);
                    mma16816(D[mt][0][0], D[mt][0][1], D[mt][0][2], D[mt][0][3],
                             a0, a1, a2, a3, be0, be1);
                    mma16816(D[mt][1][0], D[mt][1][1], D[mt][1][2], D[mt][1][3],
                             a0, a1, a2, a3, bw2, bw3);
                    mma16816(D[mt][1][0], D[mt][1][1], D[mt][1][2], D[mt][1][3],
                             e0, e1, e2, e3, bw2, bw3);
                    mma16816(D[mt][1][0], D[mt][1][1], D[mt][1][2], D[mt][1][3],
                             a0, a1, a2, a3, be2, be3);
                }
            }
            __syncthreads();   // all staging reads done; scr writable
            // mask by m1 table, scatter into owner warps' scr in st8 layout
#pragma unroll
            for (int mt = 0; mt < 4; mt++)
#pragma unroll
                for (int q = 0; q < 4; q++) {
                    int row = mt * 16 + (lane >> 2) + ((q >= 2) ? 8 : 0);
                    u32 mw = sM1w[row * 4 + (warp >> 1)];
                    int owner = row >> 3;
                    int base = owner * 1024 + ((row & 4) ? 512 : 0) + (row & 3);
#pragma unroll
                    for (int n = 0; n < 2; n++) {
                        int j = 16 * warp + n * 8 + cb + (q & 1);
                        float v = ((mw >> (j & 31)) & 1u) ? D[mt][n][q] : 0.f;
                        sscr[base + j * 4] = v;
                    }
                }
        }
        __syncthreads();

        // gy += E1y[lane,:] . dh1pre
#pragma unroll 4
        for (int j = 0; j < 128; j++) {
            u64 b0, b1, b2, b3; ld8(scr, j, b0, b1, b2, b3);
            u64 w = pks(sE1y[lane * 128 + (j & 96) + ((j & 31) ^ lane)]);
            gy[0] = ffma2(b0, w, gy[0]); gy[1] = ffma2(b1, w, gy[1]);
            gy[2] = ffma2(b2, w, gy[2]); gy[3] = ffma2(b3, w, gy[3]);
        }

#pragma unroll
        for (int p = 0; p < 4; p++) y[p] = ffma2(gy[p], pks(-C_LR), y[p]);
    }

#pragma unroll
    for (int p = 0; p < 4; p++) {
        float a, b; up2(y[p], a, b);
        out[(r0 + 2 * p) * NDY + lane] = a;
        out[(r0 + 2 * p + 1) * NDY + lane] = b;
    }
}

extern "C" void kernel_launch(void* const* d_in, const int* in_sizes, int n_in,
                              void* d_out, int out_size) {
    const float* x      = (const float*)d_in[0];
    const int*   t      = (const int*)d_in[1];
    const float* e_w1   = (const float*)d_in[2];
    const float* e_b1   = (const float*)d_in[3];
    const float* e_w2   = (const float*)d_in[4];
    const float* e_b2   = (const float*)d_in[5];
    const float* e_w3   = (const float*)d_in[6];
    const float* s_xw   = (const float*)d_in[8];
    const float* s_xb   = (const float*)d_in[9];
    const float* s_yw   = (const float*)d_in[10];
    const float* s_yb   = (const float*)d_in[11];
    const float* s_temb = (const float*)d_in[12];
    const float* s_t1w  = (const float*)d_in[13];
    const float* s_t1b  = (const float*)d_in[14];
    const float* s_t2w  = (const float*)d_in[15];
    const float* s_t2b  = (const float*)d_in[16];
    const float* tr1w   = (const float*)d_in[17];
    const float* tr1b   = (const float*)d_in[18];
    const float* tr2w   = (const float*)d_in[19];
    const float* tr2b   = (const float*)d_in[20];
    const int*   steps  = (const int*)d_in[21];
    float* out = (float*)d_out;

    float *p_hxe, *p_hxs, *p_c, *p_cth;
    cudaGetSymbolAddress((void**)&p_hxe, g_hxe);
    cudaGetSymbolAddress((void**)&p_hxs, g_hxs);
    cudaGetSymbolAddress((void**)&p_c,   g_c);
    cudaGetSymbolAddress((void**)&p_cth, g_cth);

    cth_kernel<<<1, NH>>>(s_temb, s_t1w, s_t1b, s_t2w, s_t2b, tr1w, tr1b);
    p_kernel<<<NDY, NH>>>(s_yw, s_yb, tr1w);
    gemm128_dual_kernel<<<NB / 64, 256>>>(x, NDX, NDX, e_w1, e_b1, s_xw, s_xb, p_hxe, p_hxs);
    gemm128_kernel<<<NB / 64, 256>>>(p_hxs, NH, NH, tr1w, nullptr, p_cth, t, p_c);

    cudaFuncSetAttribute(edi_main_kernel, cudaFuncAttributeMaxDynamicSharedMemorySize, SMEM_BYTES);
    edi_main_kernel<<<NB / 64, 256, SMEM_BYTES>>>(t, e_w1, e_w2, e_b2, e_w3,
                                                  tr2w, tr2b, steps, out);
}

// round 16
// speedup vs baseline: 3.7734x; 1.1708x over previous
#include <cuda_runtime.h>
#include <cuda_fp16.h>
typedef unsigned long long u64;
typedef unsigned int u32;
typedef unsigned short u16;

#define NB   131072
#define NDX  256
#define NDY  32
#define NK   4
#define NH   128
#define C_LR  0.1f
#define C_REG 0.01f
#define C_SW  1.0f

__device__ float g_hxe[NB * NH];
__device__ float g_hxs[NB * NH];
__device__ float g_c[NB * NH];
__device__ float g_cth[NK * NH];
__device__ float g_P[NDY * NH];

__device__ __forceinline__ u64 pk2(float x, float y) {
    u64 r; asm("mov.b64 %0, {%1,%2};" : "=l"(r) : "f"(x), "f"(y)); return r;
}
__device__ __forceinline__ u64 pks(float x) {
    u64 r; asm("mov.b64 %0, {%1,%1};" : "=l"(r) : "f"(x)); return r;
}
__device__ __forceinline__ void up2(u64 v, float& x, float& y) {
    asm("mov.b64 {%0,%1}, %2;" : "=f"(x), "=f"(y) : "l"(v));
}
__device__ __forceinline__ u64 ffma2(u64 a, u64 b, u64 c) {
    u64 d; asm("fma.rn.f32x2 %0, %1, %2, %3;" : "=l"(d) : "l"(a), "l"(b), "l"(c)); return d;
}
__device__ __forceinline__ u64 fmul2(u64 a, u64 b) {
    u64 d; asm("mul.rn.f32x2 %0, %1, %2;" : "=l"(d) : "l"(a), "l"(b)); return d;
}
__device__ __forceinline__ u64 fadd2(u64 a, u64 b) {
    u64 d; asm("add.rn.f32x2 %0, %1, %2;" : "=l"(d) : "l"(a), "l"(b)); return d;
}
__device__ __forceinline__ u32 smemu(const void* p) {
    return (u32)__cvta_generic_to_shared(p);
}
__device__ __forceinline__ void ldsm4(u32 a, u32& r0, u32& r1, u32& r2, u32& r3) {
    asm volatile("ldmatrix.sync.aligned.m8n8.x4.shared.b16 {%0,%1,%2,%3}, [%4];"
                 : "=r"(r0), "=r"(r1), "=r"(r2), "=r"(r3) : "r"(a));
}
__device__ __forceinline__ void ldsm2t(u32 a, u32& r0, u32& r1) {
    asm volatile("ldmatrix.sync.aligned.m8n8.x2.trans.shared.b16 {%0,%1}, [%2];"
                 : "=r"(r0), "=r"(r1) : "r"(a));
}
__device__ __forceinline__ void mma16816(float& d0, float& d1, float& d2, float& d3,
                                         u32 a0, u32 a1, u32 a2, u32 a3, u32 b0, u32 b1) {
    asm volatile("mma.sync.aligned.m16n8k16.row.col.f32.f16.f16.f32 "
                 "{%0,%1,%2,%3},{%4,%5,%6,%7},{%8,%9},{%0,%1,%2,%3};"
                 : "+f"(d0), "+f"(d1), "+f"(d2), "+f"(d3)
                 : "r"(a0), "r"(a1), "r"(a2), "r"(a3), "r"(b0), "r"(b1));
}
__device__ __forceinline__ void st8(float* scr, int j, u64 v0, u64 v1, u64 v2, u64 v3) {
    *reinterpret_cast<ulonglong2*>(scr + j * 4)       = make_ulonglong2(v0, v1);
    *reinterpret_cast<ulonglong2*>(scr + 512 + j * 4) = make_ulonglong2(v2, v3);
}
__device__ __forceinline__ void ld8(const float* scr, int j, u64& v0, u64& v1, u64& v2, u64& v3) {
    ulonglong2 a = *reinterpret_cast<const ulonglong2*>(scr + j * 4);
    ulonglong2 b = *reinterpret_cast<const ulonglong2*>(scr + 512 + j * 4);
    v0 = a.x; v1 = a.y; v2 = b.x; v3 = b.y;
}

__global__ void cth_kernel(const float* __restrict__ s_temb, const float* __restrict__ s_t1w,
                           const float* __restrict__ s_t1b, const float* __restrict__ s_t2w,
                           const float* __restrict__ s_t2b, const float* __restrict__ tr1w,
                           const float* __restrict__ tr1b) {
    int j = threadIdx.x;
    __shared__ float v[NH], th[NH];
    for (int k = 0; k < NK; k++) {
        float tau = fmaxf((float)k / 1000.0f, 1e-6f);
        float z = tau * s_t1w[j] + s_t1b[j];
        v[j] = z / (1.0f + expf(-z));
        __syncthreads();
        float acc = s_t2b[j];
        for (int q = 0; q < NH; q++) acc += v[q] * s_t2w[q * NH + j];
        th[j] = acc;
        __syncthreads();
        float c = tr1b[j];
        for (int q = 0; q < NH; q++) {
            c += s_temb[k * NH + q] * tr1w[(2 * NH + q) * NH + j];
            c += th[q] * tr1w[(3 * NH + q) * NH + j];
        }
        g_cth[k * NH + j] = c;
        __syncthreads();
    }
}

__global__ void p_kernel(const float* __restrict__ s_yw, const float* __restrict__ s_yb,
                         const float* __restrict__ tr1w) {
    int k = threadIdx.x, d = blockIdx.x;
    float acc = 0.0f;
    for (int j = 0; j < NH; j++) acc += s_yw[d * NH + j] * tr1w[(NH + j) * NH + k];
    g_P[d * NH + k] = acc;
    if (d == 0) {
        float bp = 0.0f;
        for (int j = 0; j < NH; j++) bp += s_yb[j] * tr1w[(NH + j) * NH + k];
        for (int c = 0; c < NK; c++) g_cth[c * NH + k] += bp;
    }
}

__global__ __launch_bounds__(256)
void gemm128_kernel(const float* __restrict__ X, int ldx, int Kdim,
                    const float* __restrict__ Wm, const float* __restrict__ bias,
                    const float* __restrict__ table, const int* __restrict__ tt,
                    float* __restrict__ out) {
    __shared__ float Xs[64 * 33];
    __shared__ float Ws[32 * 128];
    int tid = threadIdx.x, tcol = tid & 31, trow = tid >> 5, m0 = blockIdx.x * 64;
    float acc[8][4];
#pragma unroll
    for (int p = 0; p < 8; p++)
#pragma unroll
        for (int q = 0; q < 4; q++) acc[p][q] = 0.0f;
    for (int k0 = 0; k0 < Kdim; k0 += 32) {
#pragma unroll
        for (int i = 0; i < 8; i++) {
            int e = tid + 256 * i;
            Xs[(e >> 5) * 33 + (e & 31)] = X[(m0 + (e >> 5)) * ldx + k0 + (e & 31)];
        }
#pragma unroll
        for (int i = 0; i < 16; i++) {
            int e = tid + 256 * i;
            Ws[(e >> 7) * 128 + (e & 127)] = Wm[(k0 + (e >> 7)) * NH + (e & 127)];
        }
        __syncthreads();
#pragma unroll 8
        for (int kk = 0; kk < 32; kk++) {
            float xv[8], wv[4];
#pragma unroll
            for (int p = 0; p < 8; p++) xv[p] = Xs[(trow + 8 * p) * 33 + kk];
#pragma unroll
            for (int q = 0; q < 4; q++) wv[q] = Ws[kk * 128 + tcol + 32 * q];
#pragma unroll
            for (int p = 0; p < 8; p++)
#pragma unroll
                for (int q = 0; q < 4; q++) acc[p][q] += xv[p] * wv[q];
        }
        __syncthreads();
    }
#pragma unroll
    for (int p = 0; p < 8; p++) {
        int m = m0 + trow + 8 * p;
        int tc = 0;
        if (table) { int tv = tt[m]; tc = tv > 0 ? tv : 0; }
#pragma unroll
        for (int q = 0; q < 4; q++) {
            int n = tcol + 32 * q;
            float vv = acc[p][q];
            if (bias)  vv += bias[n];
            if (table) vv += table[tc * NH + n];
            out[m * NH + n] = vv;
        }
    }
}

__global__ __launch_bounds__(256)
void gemm128_dual_kernel(const float* __restrict__ X, int ldx, int Kdim,
                         const float* __restrict__ W0, const float* __restrict__ b0v,
                         const float* __restrict__ W1, const float* __restrict__ b1v,
                         float* __restrict__ out0, float* __restrict__ out1) {
    __shared__ float Xs[64 * 33];
    __shared__ float Ws0[32 * 128];
    __shared__ float Ws1[32 * 128];
    int tid = threadIdx.x, tcol = tid & 31, trow = tid >> 5, m0 = blockIdx.x * 64;
    float a0[8][4], a1[8][4];
#pragma unroll
    for (int p = 0; p < 8; p++)
#pragma unroll
        for (int q = 0; q < 4; q++) { a0[p][q] = 0.0f; a1[p][q] = 0.0f; }
    for (int k0 = 0; k0 < Kdim; k0 += 32) {
#pragma unroll
        for (int i = 0; i < 8; i++) {
            int e = tid + 256 * i;
            Xs[(e >> 5) * 33 + (e & 31)] = X[(m0 + (e >> 5)) * ldx + k0 + (e & 31)];
        }
#pragma unroll
        for (int i = 0; i < 16; i++) {
            int e = tid + 256 * i;
            Ws0[(e >> 7) * 128 + (e & 127)] = W0[(k0 + (e >> 7)) * NH + (e & 127)];
            Ws1[(e >> 7) * 128 + (e & 127)] = W1[(k0 + (e >> 7)) * NH + (e & 127)];
        }
        __syncthreads();
#pragma unroll 4
        for (int kk = 0; kk < 32; kk++) {
            float xv[8], w0[4], w1[4];
#pragma unroll
            for (int p = 0; p < 8; p++) xv[p] = Xs[(trow + 8 * p) * 33 + kk];
#pragma unroll
            for (int q = 0; q < 4; q++) { w0[q] = Ws0[kk * 128 + tcol + 32 * q]; w1[q] = Ws1[kk * 128 + tcol + 32 * q]; }
#pragma unroll
            for (int p = 0; p < 8; p++)
#pragma unroll
                for (int q = 0; q < 4; q++) { a0[p][q] += xv[p] * w0[q]; a1[p][q] += xv[p] * w1[q]; }
        }
        __syncthreads();
    }
#pragma unroll
    for (int p = 0; p < 8; p++) {
        int m = m0 + trow + 8 * p;
#pragma unroll
        for (int q = 0; q < 4; q++) {
            int n = tcol + 32 * q;
            out0[m * NH + n] = a0[p][q] + b0v[n];
            out1[m * NH + n] = a1[p][q] + b1v[n];
        }
    }
}

// SMEM float-slot offsets
#define OFF_E1Y  0
#define OFF_PM   4096
#define OFF_E3T  8192
#define OFF_T2   8704
#define OFF_B2   9216
#define OFF_T2B  9344
#define OFF_M2V  9352
#define OFF_M2W  9608
#define OFF_M1W  9864
#define OFF_WA   10120
#define OFF_WE   18312
#define OFF_E1F  26504
#define OFF_E1FL 28552
#define OFF_PF   30600
#define OFF_PFL  32648
#define OFF_YH   34696
#define OFF_YL   35976
#define OFF_AH   37256
#define OFF_AL   41352
#define OFF_SCR  45448
#define SMEM_FLOATS (OFF_SCR + 8 * 1024)
#define SMEM_BYTES  (SMEM_FLOATS * 4)

__global__ __launch_bounds__(256, 1)
void edi_main_kernel(const int* __restrict__ t, const float* __restrict__ e_w1,
                     const float* __restrict__ e_w2, const float* __restrict__ e_b2,
                     const float* __restrict__ e_w3, const float* __restrict__ tr2w,
                     const float* __restrict__ tr2b, const int* __restrict__ steps_p,
                     float* __restrict__ out) {
    extern __shared__ float sm[];
    float*  sE1y = sm + OFF_E1Y;
    float*  sP   = sm + OFF_PM;
    float*  sE3T = sm + OFF_E3T;
    float*  sT2  = sm + OFF_T2;
    float*  sb2  = sm + OFF_B2;
    float*  st2b = sm + OFF_T2B;
    u16*    sM2v = (u16*)(sm + OFF_M2V);
    u32*    sM2w = (u32*)(sm + OFF_M2W);
    u32*    sM1w = (u32*)(sm + OFF_M1W);
    __half* sWa  = (__half*)(sm + OFF_WA);
    __half* sWe  = (__half*)(sm + OFF_WE);
    __half* sE1F = (__half*)(sm + OFF_E1F);
    __half* sE1L = (__half*)(sm + OFF_E1FL);
    __half* sPF  = (__half*)(sm + OFF_PF);
    __half* sPL  = (__half*)(sm + OFF_PFL);
    __half* sYh  = (__half*)(sm + OFF_YH);
    __half* sYl  = (__half*)(sm + OFF_YL);
    __half* sAh  = (__half*)(sm + OFF_AH);
    __half* sAl  = (__half*)(sm + OFF_AL);
    float*  sscr = sm + OFF_SCR;

    int tid = threadIdx.x;
    for (int idx = tid; idx < 32 * 128; idx += 256) {
        int d = idx >> 7, k = idx & 127;
        int swi = d * 128 + (k & 96) + ((k & 31) ^ d);
        float wv = e_w1[(NDX + d) * NH + k];
        float pv = g_P[idx];
        sE1y[swi] = wv;
        sP[swi]   = pv;
        int hp = d * 128 + (((k >> 3) ^ (d & 7)) << 3) + (k & 7);
        __half hw = __float2half_rn(wv);
        sE1F[hp] = hw; sE1L[hp] = __float2half_rn(wv - __half2float(hw));
        __half hq = __float2half_rn(pv);
        sPF[hp] = hq; sPL[hp] = __float2half_rn(pv - __half2float(hq));
    }
    for (int idx = tid; idx < 128 * 128; idx += 256) {
        int j = idx >> 7, c = idx & 127;
        float w = e_w2[idx];
        __half ha = __float2half_rn(w);
        int hp = j * 128 + (((c >> 3) ^ (j & 7)) << 3) + (c & 7);
        sWa[hp] = ha;
        sWe[hp] = __float2half_rn(w - __half2float(ha));
    }
    for (int idx = tid; idx < 512; idx += 256) {
        sE3T[(idx & 3) * 128 + (idx >> 2)] = e_w3[idx];
        sT2[idx] = tr2w[idx];
    }
    if (tid < 128) sb2[tid] = e_b2[tid];
    if (tid < 4)   st2b[tid] = tr2b[tid];
    __syncthreads();

    const int lane = tid & 31;
    const int warp = tid >> 5;
    float* scr = sscr + warp * 1024;
    const int r0 = (blockIdx.x * 8 + warp) * 8;
    const int nsteps = *steps_p;
    const u32 waU = smemu(sWa);
    const u32 weU = smemu(sWe);
    const u32 e1fU = smemu(sE1F);
    const u32 e1lU = smemu(sE1L);
    const u32 pfU = smemu(sPF);
    const u32 plU = smemu(sPL);
    const u32 yhU = smemu(sYh);
    const u32 ylU = smemu(sYl);
    const u32 ahU = smemu(sAh);
    const u32 alU = smemu(sAl);
    const int cb = 2 * (lane & 3);
    const int ntg0 = 2 * warp;

    int tci[8]; float svf[8];
#pragma unroll
    for (int r = 0; r < 8; r++) {
        int tv = t[r0 + r];
        tci[r] = tv > 0 ? tv : 0;
        svf[r] = tv >= 0 ? C_SW : 0.0f;
    }

    u64 y[4] = {0ull, 0ull, 0ull, 0ull};
    u64 hxe[4][4], cc[4][4];
#pragma unroll
    for (int m = 0; m < 4; m++)
#pragma unroll
        for (int p = 0; p < 4; p++) {
            int col = 32 * m + lane;
            hxe[m][p] = pk2(g_hxe[(r0 + 2 * p) * NH + col], g_hxe[(r0 + 2 * p + 1) * NH + col]);
            cc[m][p]  = pk2(g_c[(r0 + 2 * p) * NH + col],   g_c[(r0 + 2 * p + 1) * NH + col]);
        }

    for (int s = 0; s < nsteps; s++) {
        __syncthreads();               // S0: prior-step scr reads done
        // stage y split-fp16 into sY (row stride 40 halves; lane = col d)
#pragma unroll
        for (int p = 0; p < 4; p++) {
            float x, z; up2(y[p], x, z);
            int R0 = warp * 8 + 2 * p, R1 = R0 + 1;
            __half hx = __float2half_rn(x), hz = __float2half_rn(z);
            sYh[R0 * 40 + lane] = hx;
            sYh[R1 * 40 + lane] = hz;
            sYl[R0 * 40 + lane] = __float2half_rn(x - __half2float(hx));
            sYl[R1 * 40 + lane] = __float2half_rn(z - __half2float(hz));
        }
        __syncthreads();               // S1

        // ---- h1pre mma: 64x128 = y(64x32) @ E1y(32x128), warp n-slice 16 cols ----
        {
            float D1[4][2][4];
#pragma unroll
            for (int mt = 0; mt < 4; mt++)
#pragma unroll
                for (int n = 0; n < 2; n++)
#pragma unroll
                    for (int q = 0; q < 4; q++) D1[mt][n][q] = 0.f;
#pragma unroll
            for (int kt = 0; kt < 2; kt++) {
                int dr = kt * 16 + (lane & 15);
                u32 broff = (u32)(dr * 256);
                int ds = dr & 7;
                u32 bw0[2], bw1[2], bl0[2], bl1[2];
#pragma unroll
                for (int n = 0; n < 2; n++) {
                    u32 off = broff + (u32)((((ntg0 + n) ^ ds) & 15) << 4);
                    ldsm2t(e1fU + off, bw0[n], bw1[n]);
                    ldsm2t(e1lU + off, bl0[n], bl1[n]);
                }
#pragma unroll
                for (int mt = 0; mt < 4; mt++) {
                    int row = mt * 16 + (lane & 15);
                    u32 ro = (u32)(row * 80 + ((kt * 2 + (lane >> 4)) << 4));
                    u32 a0, a1, a2, a3, e0, e1, e2, e3;
                    ldsm4(yhU + ro, a0, a1, a2, a3);
                    ldsm4(ylU + ro, e0, e1, e2, e3);
#pragma unroll
                    for (int n = 0; n < 2; n++) {
                        mma16816(D1[mt][n][0], D1[mt][n][1], D1[mt][n][2], D1[mt][n][3],
                                 a0, a1, a2, a3, bw0[n], bw1[n]);
                        mma16816(D1[mt][n][0], D1[mt][n][1], D1[mt][n][2], D1[mt][n][3],
                                 e0, e1, e2, e3, bw0[n], bw1[n]);
                        mma16816(D1[mt][n][0], D1[mt][n][1], D1[mt][n][2], D1[mt][n][3],
                                 a0, a1, a2, a3, bl0[n], bl1[n]);
                    }
                }
            }
            // scatter h1pre (rotated cols) into sscr[row][col]
#pragma unroll
            for (int mt = 0; mt < 4; mt++)
#pragma unroll
                for (int n = 0; n < 2; n++)
#pragma unroll
                    for (int q = 0; q < 4; q++) {
                        int row = mt * 16 + (lane >> 2) + ((q & 2) ? 8 : 0);
                        int col = 16 * warp + n * 8 + cb + (q & 1);
                        sscr[row * 128 + ((col + 4 * (row & 7)) & 127)] = D1[mt][n][q];
                    }
        }
        __syncthreads();               // S2

        // ---- owner: h1pre + hxe -> m1, relu, fp16 staging ----
        u64 A[4][4];
#pragma unroll
        for (int m = 0; m < 4; m++) {
            int jj = lane + 32 * m;
#pragma unroll
            for (int p = 0; p < 4; p++) {
                int R0 = warp * 8 + 2 * p, R1 = R0 + 1;
                float x = sscr[R0 * 128 + ((jj + 4 * (R0 & 7)) & 127)];
                float z = sscr[R1 * 128 + ((jj + 4 * (R1 & 7)) & 127)];
                A[m][p] = fadd2(pk2(x, z), hxe[m][p]);
            }
        }
        unsigned m1 = 0;
#pragma unroll
        for (int m = 0; m < 4; m++)
#pragma unroll
            for (int p = 0; p < 4; p++) {
                float x, z; up2(A[m][p], x, z);
                m1 |= (x > 0.f ? 1u : 0u) << (m * 8 + 2 * p);
                m1 |= (z > 0.f ? 1u : 0u) << (m * 8 + 2 * p + 1);
                A[m][p] = pk2(fmaxf(x, 0.f), fmaxf(z, 0.f));
            }
        {
            u32 mword = 0;
#pragma unroll
            for (int i = 0; i < 32; i++) {
                u32 b = __ballot_sync(0xffffffffu, (m1 >> (((i & 3) * 8) + (i >> 2))) & 1u);
                if (lane == i) mword = b;
            }
            sM1w[(warp * 8 + (lane >> 2)) * 4 + (lane & 3)] = mword;
        }
#pragma unroll
        for (int m = 0; m < 4; m++) {
            int jj = lane + 32 * m;
#pragma unroll
            for (int p = 0; p < 4; p++) {
                float x, z; up2(A[m][p], x, z);
                __half hx = __float2half_rn(x), hz = __float2half_rn(z);
                int R0 = warp * 8 + 2 * p, R1 = R0 + 1;
                int i0 = R0 * 128 + (((jj >> 3) ^ (R0 & 7)) << 3) + (jj & 7);
                int i1 = R1 * 128 + (((jj >> 3) ^ (R1 & 7)) << 3) + (jj & 7);
                sAh[i0] = hx; sAh[i1] = hz;
                sAl[i0] = __float2half_rn(x - __half2float(hx));
                sAl[i1] = __float2half_rn(z - __half2float(hz));
            }
        }
        __syncthreads();               // S3

        // ---- cooperative W2 fwd (mask-only) ----
        {
            float D[4][2][4];
#pragma unroll
            for (int mt = 0; mt < 4; mt++)
#pragma unroll
                for (int n = 0; n < 2; n++)
#pragma unroll
                    for (int q = 0; q < 4; q++) D[mt][n][q] = 0.f;
#pragma unroll 1
            for (int kt = 0; kt < 8; kt++) {
                int jr = kt * 16 + (lane & 15);
                u32 broff = (u32)(jr * 256);
                int js = jr & 7;
                u32 bw0[2], bw1[2], be0[2], be1[2];
#pragma unroll
                for (int n = 0; n < 2; n++) {
                    u32 off = broff + (u32)((((ntg0 + n) ^ js) & 15) << 4);
                    ldsm2t(waU + off, bw0[n], bw1[n]);
                    ldsm2t(weU + off, be0[n], be1[n]);
                }
#pragma unroll
                for (int mt = 0; mt < 4; mt++) {
                    int row = mt * 16 + (lane & 15);
                    u32 pch = (u32)((((kt * 2 + (lane >> 4)) ^ (lane & 7))) << 4);
                    u32 ro = (u32)(row * 256) + pch;
                    u32 a0, a1, a2, a3, e0, e1, e2, e3;
                    ldsm4(ahU + ro, a0, a1, a2, a3);
                    ldsm4(alU + ro, e0, e1, e2, e3);
#pragma unroll
                    for (int n = 0; n < 2; n++) {
                        mma16816(D[mt][n][0], D[mt][n][1], D[mt][n][2], D[mt][n][3],
                                 a0, a1, a2, a3, bw0[n], bw1[n]);
                        mma16816(D[mt][n][0], D[mt][n][1], D[mt][n][2], D[mt][n][3],
                                 e0, e1, e2, e3, bw0[n], bw1[n]);
                        mma16816(D[mt][n][0], D[mt][n][1], D[mt][n][2], D[mt][n][3],
                                 a0, a1, a2, a3, be0[n], be1[n]);
                    }
                }
            }
#pragma unroll
            for (int mt = 0; mt < 4; mt++) {
                u32 v = 0;
#pragma unroll
                for (int n = 0; n < 2; n++) {
                    int cg = (ntg0 + n) * 8 + cb, bp = n * 8 + cb;
                    if (D[mt][n][0] + sb2[cg]     > 0.f) v |= 1u << bp;
                    if (D[mt][n][1] + sb2[cg + 1] > 0.f) v |= 1u << (bp + 1);
                    if (D[mt][n][2] + sb2[cg]     > 0.f) v |= 1u << (16 + bp);
                    if (D[mt][n][3] + sb2[cg + 1] > 0.f) v |= 1u << (16 + bp + 1);
                }
                v |= __shfl_xor_sync(0xffffffffu, v, 1);
                v |= __shfl_xor_sync(0xffffffffu, v, 2);
                if ((lane & 3) == 0) {
                    int Ra = mt * 16 + (lane >> 2);
                    sM2v[Ra * 8 + warp]       = (u16)(v & 0xffff);
                    sM2v[(Ra + 8) * 8 + warp] = (u16)(v >> 16);
                }
            }
        }

        // ---- u mma: 64x128 = y(64x32) @ P(32x128); keep frags in regs ----
        float D2[4][2][4];
#pragma unroll
        for (int mt = 0; mt < 4; mt++)
#pragma unroll
            for (int n = 0; n < 2; n++)
#pragma unroll
                for (int q = 0; q < 4; q++) D2[mt][n][q] = 0.f;
#pragma unroll
        for (int kt = 0; kt < 2; kt++) {
            int dr = kt * 16 + (lane & 15);
            u32 broff = (u32)(dr * 256);
            int ds = dr & 7;
            u32 bw0[2], bw1[2], bl0[2], bl1[2];
#pragma unroll
            for (int n = 0; n < 2; n++) {
                u32 off = broff + (u32)((((ntg0 + n) ^ ds) & 15) << 4);
                ldsm2t(pfU + off, bw0[n], bw1[n]);
                ldsm2t(plU + off, bl0[n], bl1[n]);
            }
#pragma unroll
            for (int mt = 0; mt < 4; mt++) {
                int row = mt * 16 + (lane & 15);
                u32 ro = (u32)(row * 80 + ((kt * 2 + (lane >> 4)) << 4));
                u32 a0, a1, a2, a3, e0, e1, e2, e3;
                ldsm4(yhU + ro, a0, a1, a2, a3);
                ldsm4(ylU + ro, e0, e1, e2, e3);
#pragma unroll
                for (int n = 0; n < 2; n++) {
                    mma16816(D2[mt][n][0], D2[mt][n][1], D2[mt][n][2], D2[mt][n][3],
                             a0, a1, a2, a3, bw0[n], bw1[n]);
                    mma16816(D2[mt][n][0], D2[mt][n][1], D2[mt][n][2], D2[mt][n][3],
                             e0, e1, e2, e3, bw0[n], bw1[n]);
                    mma16816(D2[mt][n][0], D2[mt][n][1], D2[mt][n][2], D2[mt][n][3],
                             a0, a1, a2, a3, bl0[n], bl1[n]);
                }
            }
        }
        __syncthreads();               // S4: scr free, sM2v complete
        {
            int row = tid >> 2, wd = tid & 3;
            u32 lo = sM2v[row * 8 + wd * 2], hi = sM2v[row * 8 + wd * 2 + 1];
            sM2w[row * 4 + wd] = lo | (hi << 16);
        }
#pragma unroll
        for (int mt = 0; mt < 4; mt++)
#pragma unroll
            for (int n = 0; n < 2; n++)
#pragma unroll
                for (int q = 0; q < 4; q++) {
                    int row = mt * 16 + (lane >> 2) + ((q & 2) ? 8 : 0);
                    int col = 16 * warp + n * 8 + cb + (q & 1);
                    sscr[row * 128 + ((col + 4 * (row & 7)) & 127)] = D2[mt][n][q];
                }
        __syncthreads();               // S5

        // ---- owner: u = scatter + cc; logits; softmax; du ----
        u64 U[4][4];
#pragma unroll
        for (int m = 0; m < 4; m++) {
            int jj = lane + 32 * m;
#pragma unroll
            for (int p = 0; p < 4; p++) {
                int R0 = warp * 8 + 2 * p, R1 = R0 + 1;
                float x = sscr[R0 * 128 + ((jj + 4 * (R0 & 7)) & 127)];
                float z = sscr[R1 * 128 + ((jj + 4 * (R1 & 7)) & 127)];
                U[m][p] = fadd2(pk2(x, z), cc[m][p]);
            }
        }
        u64 lg[4][4];
#pragma unroll
        for (int k = 0; k < 4; k++)
#pragma unroll
            for (int p = 0; p < 4; p++) lg[k][p] = 0ull;
#pragma unroll
        for (int m = 0; m < 4; m++) {
            float4 t2 = *reinterpret_cast<const float4*>(&sT2[(lane + 32 * m) * 4]);
#pragma unroll
            for (int p = 0; p < 4; p++) {
                float ux, uz; up2(U[m][p], ux, uz);
                float ax = ux * __fdividef(1.f, 1.f + __expf(-ux));
                float az = uz * __fdividef(1.f, 1.f + __expf(-uz));
                u64 a2 = pk2(ax, az);
                lg[0][p] = ffma2(a2, pks(t2.x), lg[0][p]);
                lg[1][p] = ffma2(a2, pks(t2.y), lg[1][p]);
                lg[2][p] = ffma2(a2, pks(t2.z), lg[2][p]);
                lg[3][p] = ffma2(a2, pks(t2.w), lg[3][p]);
            }
        }
#pragma unroll
        for (int off = 16; off > 0; off >>= 1)
#pragma unroll
            for (int k = 0; k < 4; k++)
#pragma unroll
                for (int p = 0; p < 4; p++)
                    lg[k][p] = fadd2(lg[k][p], __shfl_xor_sync(0xffffffffu, lg[k][p], off));

        u64 dl[4][4];
#pragma unroll
        for (int p = 0; p < 4; p++) {
            float l0[4], l1[4];
#pragma unroll
            for (int k = 0; k < 4; k++) {
                float x, z; up2(lg[k][p], x, z);
                l0[k] = x + st2b[k]; l1[k] = z + st2b[k];
            }
            float dlo[4], dhi[4];
            {
                float mx = fmaxf(fmaxf(l0[0], l0[1]), fmaxf(l0[2], l0[3]));
                float e0 = __expf(l0[0] - mx), e1 = __expf(l0[1] - mx);
                float e2 = __expf(l0[2] - mx), e3 = __expf(l0[3] - mx);
                float sw = svf[2 * p]; int tc = tci[2 * p];
                float inv = sw * __fdividef(1.f, e0 + e1 + e2 + e3);
                dlo[0] = e0 * inv - (tc == 0 ? sw : 0.f);
                dlo[1] = e1 * inv - (tc == 1 ? sw : 0.f);
                dlo[2] = e2 * inv - (tc == 2 ? sw : 0.f);
                dlo[3] = e3 * inv - (tc == 3 ? sw : 0.f);
            }
            {
                float mx = fmaxf(fmaxf(l1[0], l1[1]), fmaxf(l1[2], l1[3]));
                float e0 = __expf(l1[0] - mx), e1 = __expf(l1[1] - mx);
                float e2 = __expf(l1[2] - mx), e3 = __expf(l1[3] - mx);
                float sw = svf[2 * p + 1]; int tc = tci[2 * p + 1];
                float inv = sw * __fdividef(1.f, e0 + e1 + e2 + e3);
                dhi[0] = e0 * inv - (tc == 0 ? sw : 0.f);
                dhi[1] = e1 * inv - (tc == 1 ? sw : 0.f);
                dhi[2] = e2 * inv - (tc == 2 ? sw : 0.f);
                dhi[3] = e3 * inv - (tc == 3 ? sw : 0.f);
            }
#pragma unroll
            for (int k = 0; k < 4; k++) dl[k][p] = pk2(dlo[k], dhi[k]);
        }

        // du -> own scr region (st8)
        __syncwarp();
#pragma unroll
        for (int m = 0; m < 4; m++) {
            int jj = lane + 32 * m;
            float4 t2 = *reinterpret_cast<const float4*>(&sT2[jj * 4]);
            u64 dv[4];
#pragma unroll
            for (int p = 0; p < 4; p++) {
                u64 da = fmul2(dl[0][p], pks(t2.x));
                da = ffma2(dl[1][p], pks(t2.y), da);
                da = ffma2(dl[2][p], pks(t2.z), da);
                da = ffma2(dl[3][p], pks(t2.w), da);
                float ux, uz; up2(U[m][p], ux, uz);
                float sgx = __fdividef(1.f, 1.f + __expf(-ux));
                float sgz = __fdividef(1.f, 1.f + __expf(-uz));
                dv[p] = fmul2(da, pk2(sgx * (1.f + ux * (1.f - sgx)),
                                      sgz * (1.f + uz * (1.f - sgz))));
            }
            st8(scr, jj, dv[0], dv[1], dv[2], dv[3]);
        }
        __syncwarp();

        // gy = 2*REG*y + P[lane,:] . du (own region)
        u64 gy[4];
#pragma unroll
        for (int p = 0; p < 4; p++) gy[p] = fmul2(pks(2.f * C_REG), y[p]);
#pragma unroll 4
        for (int k = 0; k < 128; k++) {
            u64 b0, b1, b2, b3; ld8(scr, k, b0, b1, b2, b3);
            u64 w = pks(sP[lane * 128 + (k & 96) + ((k & 31) ^ lane)]);
            gy[0] = ffma2(b0, w, gy[0]); gy[1] = ffma2(b1, w, gy[1]);
            gy[2] = ffma2(b2, w, gy[2]); gy[3] = ffma2(b3, w, gy[3]);
        }

        // dh2pre = (h2>0 via sM2w) * e_w3[:, tci] -> split-fp16 staging (own rows)
#pragma unroll
        for (int m = 0; m < 4; m++) {
            int jj = lane + 32 * m;
#pragma unroll
            for (int p = 0; p < 4; p++) {
                u32 w0 = sM2w[(warp * 8 + 2 * p) * 4 + m];
                u32 w1 = sM2w[(warp * 8 + 2 * p + 1) * 4 + m];
                float e0 = ((w0 >> lane) & 1u) ? sE3T[tci[2 * p] * 128 + jj]     : 0.f;
                float e1 = ((w1 >> lane) & 1u) ? sE3T[tci[2 * p + 1] * 128 + jj] : 0.f;
                __half h0 = __float2half_rn(e0), h1v = __float2half_rn(e1);
                int R0 = warp * 8 + 2 * p, R1 = R0 + 1;
                int i0 = R0 * 128 + (((jj >> 3) ^ (R0 & 7)) << 3) + (jj & 7);
                int i1 = R1 * 128 + (((jj >> 3) ^ (R1 & 7)) << 3) + (jj & 7);
                sAh[i0] = h0; sAh[i1] = h1v;
                sAl[i0] = __float2half_rn(e0 - __half2float(h0));
                sAl[i1] = __float2half_rn(e1 - __half2float(h1v));
            }
        }
        __syncthreads();               // S6

        // ---- cooperative W2 bwd: dh1 = dh2pre @ W2^T ----
        {
            float D[4][2][4];
#pragma unroll
            for (int mt = 0; mt < 4; mt++)
#pragma unroll
                for (int n = 0; n < 2; n++)
#pragma unroll
                    for (int q = 0; q < 4; q++) D[mt][n][q] = 0.f;
            int jB = 16 * warp + (lane & 7) + ((lane & 16) ? 8 : 0);
#pragma unroll 1
            for (int kt = 0; kt < 8; kt++) {
                int ch = kt * 2 + ((lane >> 3) & 1);
                u32 boff = (u32)(jB * 256 + ((ch ^ (jB & 7)) << 4));
                u32 bw0, bw1, bw2, bw3, be0, be1, be2, be3;
                ldsm4(waU + boff, bw0, bw1, bw2, bw3);
                ldsm4(weU + boff, be0, be1, be2, be3);
#pragma unroll
                for (int mt = 0; mt < 4; mt++) {
                    int row = mt * 16 + (lane & 15);
                    u32 pch = (u32)((((kt * 2 + (lane >> 4)) ^ (lane & 7))) << 4);
                    u32 ro = (u32)(row * 256) + pch;
                    u32 a0, a1, a2, a3, e0, e1, e2, e3;
                    ldsm4(ahU + ro, a0, a1, a2, a3);
                    ldsm4(alU + ro, e0, e1, e2, e3);
                    mma16816(D[mt][0][0], D[mt][0][1], D[mt][0][2], D[mt][0][3],
                             a0, a1, a2, a3, bw0, bw1);
                    mma16816(D[mt][0][0], D[mt][0][1], D[mt][0][2], D[mt][0][3],
                             e0, e1, e2, e3, bw0, bw1);
                    mma16816(D[mt][0][0], D[mt][0][1], D[mt][0][2], D[mt][0][3],
                             a0, a1, a2, a3, be0, be1);
                    mma16816(D[mt][1][0], D[mt][1][1], D[mt][1][2], D[mt][1][3],
                             a0, a1, a2, a3, bw2, bw3);
                    mma16816(D[mt][1][0], D[mt][1][1], D[mt][1][2], D[mt][1][3],
                             e0, e1, e2, e3, bw2, bw3);
                    mma16816(D[mt][1][0], D[mt][1][1], D[mt][1][2], D[mt][1][3],
                             a0, a1, a2, a3, be2, be3);
                }
            }
            __syncthreads();           // S7: P-bwd scr reads done CTA-wide
#pragma unroll
            for (int mt = 0; mt < 4; mt++)
#pragma unroll
                for (int q = 0; q < 4; q++) {
                    int row = mt * 16 + (lane >> 2) + ((q >= 2) ? 8 : 0);
                    u32 mw = sM1w[row * 4 + (warp >> 1)];
                    int owner = row >> 3;
                    int base = owner * 1024 + ((row & 4) ? 512 : 0) + (row & 3);
#pragma unroll
                    for (int n = 0; n < 2; n++) {
                        int j = 16 * warp + n * 8 + cb + (q & 1);
                        float v = ((mw >> (j & 31)) & 1u) ? D[mt][n][q] : 0.f;
                        sscr[base + j * 4] = v;
                    }
                }
        }
        __syncthreads();               // S8

        // gy += E1y[lane,:] . dh1pre (own region)
#pragma unroll 4
        for (int j = 0; j < 128; j++) {
            u64 b0, b1, b2, b3; ld8(scr, j, b0, b1, b2, b3);
            u64 w = pks(sE1y[lane * 128 + (j & 96) + ((j & 31) ^ lane)]);
            gy[0] = ffma2(b0, w, gy[0]); gy[1] = ffma2(b1, w, gy[1]);
            gy[2] = ffma2(b2, w, gy[2]); gy[3] = ffma2(b3, w, gy[3]);
        }

#pragma unroll
        for (int p = 0; p < 4; p++) y[p] = ffma2(gy[p], pks(-C_LR), y[p]);
    }

#pragma unroll
    for (int p = 0; p < 4; p++) {
        float a, b; up2(y[p], a, b);
        out[(r0 + 2 * p) * NDY + lane] = a;
        out[(r0 + 2 * p + 1) * NDY + lane] = b;
    }
}

extern "C" void kernel_launch(void* const* d_in, const int* in_sizes, int n_in,
                              void* d_out, int out_size) {
    const float* x      = (const float*)d_in[0];
    const int*   t      = (const int*)d_in[1];
    const float* e_w1   = (const float*)d_in[2];
    const float* e_b1   = (const float*)d_in[3];
    const float* e_w2   = (const float*)d_in[4];
    const float* e_b2   = (const float*)d_in[5];
    const float* e_w3   = (const float*)d_in[6];
    const float* s_xw   = (const float*)d_in[8];
    const float* s_xb   = (const float*)d_in[9];
    const float* s_yw   = (const float*)d_in[10];
    const float* s_yb   = (const float*)d_in[11];
    const float* s_temb = (const float*)d_in[12];
    const float* s_t1w  = (const float*)d_in[13];
    const float* s_t1b  = (const float*)d_in[14];
    const float* s_t2w  = (const float*)d_in[15];
    const float* s_t2b  = (const float*)d_in[16];
    const float* tr1w   = (const float*)d_in[17];
    const float* tr1b   = (const float*)d_in[18];
    const float* tr2w   = (const float*)d_in[19];
    const float* tr2b   = (const float*)d_in[20];
    const int*   steps  = (const int*)d_in[21];
    float* out = (float*)d_out;

    float *p_hxe, *p_hxs, *p_c, *p_cth;
    cudaGetSymbolAddress((void**)&p_hxe, g_hxe);
    cudaGetSymbolAddress((void**)&p_hxs, g_hxs);
    cudaGetSymbolAddress((void**)&p_c,   g_c);
    cudaGetSymbolAddress((void**)&p_cth, g_cth);

    cth_kernel<<<1, NH>>>(s_temb, s_t1w, s_t1b, s_t2w, s_t2b, tr1w, tr1b);
    p_kernel<<<NDY, NH>>>(s_yw, s_yb, tr1w);
    gemm128_dual_kernel<<<NB / 64, 256>>>(x, NDX, NDX, e_w1, e_b1, s_xw, s_xb, p_hxe, p_hxs);
    gemm128_kernel<<<NB / 64, 256>>>(p_hxs, NH, NH, tr1w, nullptr, p_cth, t, p_c);

    cudaFuncSetAttribute(edi_main_kernel, cudaFuncAttributeMaxDynamicSharedMemorySize, SMEM_BYTES);
    edi_main_kernel<<<NB / 64, 256, SMEM_BYTES>>>(t, e_w1, e_w2, e_b2, e_w3,
                                                  tr2w, tr2b, steps, out);
}